// round 9
// baseline (speedup 1.0000x reference)
#include <cuda_runtime.h>
#include <math.h>

// ---------------------------------------------------------------------------
// Problem constants
// ---------------------------------------------------------------------------
#define BATCH 4
#define SEQ   2048
#define DMODEL 1024
#define NHEADS 16
#define DK    64
#define DFF   4096
#define MROWS (BATCH * SEQ)   // 8192

// ---------------------------------------------------------------------------
// Scratch (no cudaMalloc allowed)
// ---------------------------------------------------------------------------
__device__ float g_q  [MROWS * DMODEL];
__device__ float g_k  [MROWS * DMODEL];
__device__ float g_v  [MROWS * DMODEL];
__device__ float g_ctx[MROWS * DMODEL];
__device__ float g_t1 [MROWS * DMODEL];
__device__ float g_h  [MROWS * DMODEL];
__device__ float g_hr [MROWS * DMODEL];
__device__ float g_ff [MROWS * DFF];
__device__ float g_xr [MROWS * DMODEL];
__device__ float g_wqr[DMODEL * DMODEL];
__device__ float g_wkr[DMODEL * DMODEL];
__device__ float g_wvr[DMODEL * DMODEL];
__device__ float g_wor[DMODEL * DMODEL];
__device__ float g_w1r[DMODEL * DFF];
__device__ float g_w2r[DFF * DMODEL];

// ---------------------------------------------------------------------------
// Helpers
// ---------------------------------------------------------------------------
__device__ __forceinline__ unsigned cvt_tf32(float x) {
    unsigned r;
    asm("cvt.rna.tf32.f32 %0, %1;" : "=r"(r) : "f"(x));
    return r;
}
__device__ __forceinline__ float rnd_tf32(float x) {
    return __uint_as_float(cvt_tf32(x));
}

__device__ __forceinline__ void mma_tf32(float* c, const unsigned* a, const unsigned* b) {
    asm volatile(
        "mma.sync.aligned.m16n8k8.row.col.f32.tf32.tf32.f32 "
        "{%0,%1,%2,%3}, {%4,%5,%6,%7}, {%8,%9}, {%0,%1,%2,%3};"
        : "+f"(c[0]), "+f"(c[1]), "+f"(c[2]), "+f"(c[3])
        : "r"(a[0]), "r"(a[1]), "r"(a[2]), "r"(a[3]), "r"(b[0]), "r"(b[1]));
}

__device__ __forceinline__ void cp_async16(void* smem_dst, const void* gmem_src) {
    unsigned saddr = (unsigned)__cvta_generic_to_shared(smem_dst);
    asm volatile("cp.async.cg.shared.global [%0], [%1], 16;"
                 :: "r"(saddr), "l"(gmem_src));
}
#define CP_COMMIT() asm volatile("cp.async.commit_group;")
#define CP_WAIT(n)  asm volatile("cp.async.wait_group %0;" :: "n"(n))

// ---------------------------------------------------------------------------
// Elementwise tf32 (rna) rounding: dst[i] = round_tf32(src[i])
// ---------------------------------------------------------------------------
__global__ __launch_bounds__(256) void round_tf32_kernel(
    const float* __restrict__ src, float* __restrict__ dst, int n4)
{
    int i = blockIdx.x * 256 + threadIdx.x;
    if (i < n4) {
        float4 v = ((const float4*)src)[i];
        v.x = rnd_tf32(v.x); v.y = rnd_tf32(v.y);
        v.z = rnd_tf32(v.z); v.w = rnd_tf32(v.w);
        ((float4*)dst)[i] = v;
    }
}

// ---------------------------------------------------------------------------
// TF32 tensor-core GEMM, 2-stage cp.async pipeline.
// C[M,N] = A[M,K] @ B[K,N] + bias[N] (optional ReLU, optional tf32-round out)
// BM=256, BN=128, BK=32. 256 threads = 8 warps (4x2), warp tile 64x64.
// Inputs are assumed pre-rounded to tf32 (raw bits fed to mma).
// ---------------------------------------------------------------------------
#define AS_STRIDE 36
#define BS_STRIDE 132
#define STAGE_FLOATS (256 * AS_STRIDE + 32 * BS_STRIDE)
#define GEMM_SMEM_BYTES (2 * STAGE_FLOATS * 4)

__global__ __launch_bounds__(256, 1) void gemm_tf32(
    int M, int N, int K,
    const float* __restrict__ A, const float* __restrict__ B,
    const float* __restrict__ bias, float* __restrict__ C, int relu, int rnd)
{
    extern __shared__ float sm[];

    const int tid  = threadIdx.x;
    const int lane = tid & 31;
    const int warp = tid >> 5;
    const int wm = (warp >> 1) * 64;   // 0,64,128,192
    const int wn = (warp & 1) * 64;    // 0,64
    const int g = lane >> 2;
    const int t = lane & 3;
    const int cRow = blockIdx.y, cCol = blockIdx.x;

    const int aRow = tid >> 3;         // 0..31
    const int aCol = (tid & 7) * 4;    // 0..28
    const int bRow = tid >> 5;         // 0..7
    const int bCol = (tid & 31) * 4;   // 0..124

    const float* Ag = A + (size_t)(cRow * 256) * K;
    const float* Bg = B + cCol * 128;

    float acc[4][8][4];
    #pragma unroll
    for (int i = 0; i < 4; i++)
        #pragma unroll
        for (int j = 0; j < 8; j++)
            #pragma unroll
            for (int e = 0; e < 4; e++) acc[i][j][e] = 0.f;

    const int NT = K >> 5;

    {
        float* As = sm;
        float* Bs = sm + 256 * AS_STRIDE;
        #pragma unroll
        for (int r = 0; r < 8; r++)
            cp_async16(&As[(aRow + r * 32) * AS_STRIDE + aCol],
                       Ag + (size_t)(aRow + r * 32) * K + aCol);
        #pragma unroll
        for (int r = 0; r < 4; r++)
            cp_async16(&Bs[(bRow + r * 8) * BS_STRIDE + bCol],
                       Bg + (size_t)(bRow + r * 8) * N + bCol);
        CP_COMMIT();
    }

    for (int it = 0; it < NT; it++) {
        if (it + 1 < NT) {
            const int k0 = (it + 1) << 5;
            float* As = sm + ((it + 1) & 1) * STAGE_FLOATS;
            float* Bs = As + 256 * AS_STRIDE;
            #pragma unroll
            for (int r = 0; r < 8; r++)
                cp_async16(&As[(aRow + r * 32) * AS_STRIDE + aCol],
                           Ag + (size_t)(aRow + r * 32) * K + k0 + aCol);
            #pragma unroll
            for (int r = 0; r < 4; r++)
                cp_async16(&Bs[(bRow + r * 8) * BS_STRIDE + bCol],
                           Bg + (size_t)(k0 + bRow + r * 8) * N + bCol);
            CP_COMMIT();
            CP_WAIT(1);
        } else {
            CP_WAIT(0);
        }
        __syncthreads();

        const unsigned* Asu = (const unsigned*)(sm + (it & 1) * STAGE_FLOATS);
        const unsigned* Bsu = Asu + 256 * AS_STRIDE;

        #pragma unroll
        for (int k8 = 0; k8 < 4; k8++) {
            const int kb = k8 * 8;
            unsigned af[4][4], bf[8][2];
            #pragma unroll
            for (int tm = 0; tm < 4; tm++) {
                int r0 = (wm + tm * 16 + g) * AS_STRIDE;
                af[tm][0] = Asu[r0 + kb + t];
                af[tm][1] = Asu[r0 + 8 * AS_STRIDE + kb + t];
                af[tm][2] = Asu[r0 + kb + 4 + t];
                af[tm][3] = Asu[r0 + 8 * AS_STRIDE + kb + 4 + t];
            }
            #pragma unroll
            for (int tn = 0; tn < 8; tn++) {
                bf[tn][0] = Bsu[(kb + t) * BS_STRIDE + wn + tn * 8 + g];
                bf[tn][1] = Bsu[(kb + 4 + t) * BS_STRIDE + wn + tn * 8 + g];
            }
            #pragma unroll
            for (int tm = 0; tm < 4; tm++)
                #pragma unroll
                for (int tn = 0; tn < 8; tn++)
                    mma_tf32(acc[tm][tn], af[tm], bf[tn]);
        }
        __syncthreads();
    }

    #pragma unroll
    for (int tm = 0; tm < 4; tm++) {
        #pragma unroll
        for (int tn = 0; tn < 8; tn++) {
            int row = cRow * 256 + wm + tm * 16 + g;
            int col = cCol * 128 + wn + tn * 8 + 2 * t;
            float2 bb = *(const float2*)(bias + col);
            float2 v0 = make_float2(acc[tm][tn][0] + bb.x, acc[tm][tn][1] + bb.y);
            float2 v1 = make_float2(acc[tm][tn][2] + bb.x, acc[tm][tn][3] + bb.y);
            if (relu) {
                v0.x = fmaxf(v0.x, 0.f); v0.y = fmaxf(v0.y, 0.f);
                v1.x = fmaxf(v1.x, 0.f); v1.y = fmaxf(v1.y, 0.f);
            }
            if (rnd) {
                v0.x = rnd_tf32(v0.x); v0.y = rnd_tf32(v0.y);
                v1.x = rnd_tf32(v1.x); v1.y = rnd_tf32(v1.y);
            }
            *(float2*)(C + (size_t)row * N + col) = v0;
            *(float2*)(C + (size_t)(row + 8) * N + col) = v1;
        }
    }
}

// ---------------------------------------------------------------------------
// Flash attention on tensor cores (tf32 mma.sync m16n8k8).
// Inputs Q/K/V are already exact tf32 (rounded by producing GEMM epilogue),
// so raw-bit feeding == rna semantics. Output ctx is rounded to tf32.
// ---------------------------------------------------------------------------
#define QS_STRIDE 68
#define KS_STRIDE 68
#define VS_STRIDE 72
#define ATTN_SMEM_BYTES (64 * KS_STRIDE * 4 + 64 * VS_STRIDE * 4 + 256)

__global__ __launch_bounds__(256, 2) void attn3(
    const float* __restrict__ Q, const float* __restrict__ K,
    const float* __restrict__ V, const int* __restrict__ mask,
    float* __restrict__ O)
{
    extern __shared__ char smc[];
    float*    Qstage = (float*)smc;
    unsigned* Ks     = (unsigned*)smc;
    unsigned* Vs     = (unsigned*)(smc + 64 * KS_STRIDE * 4);
    float*    maskf  = (float*)(smc + 64 * KS_STRIDE * 4 + 64 * VS_STRIDE * 4);

    const int qt = blockIdx.x, h = blockIdx.y, b = blockIdx.z;
    const int tid  = threadIdx.x;
    const int lane = tid & 31;
    const int warp = tid >> 5;
    const int g = lane >> 2;
    const int t = lane & 3;
    const size_t hoff = (size_t)h * DK;
    const size_t qrow0 = (size_t)b * SEQ + qt * 128;

    #pragma unroll
    for (int it = 0; it < 8; it++) {
        int idx = tid + it * 256;
        int r = idx >> 4;
        int c4 = (idx & 15) << 2;
        float4 v = *(const float4*)(Q + (qrow0 + r) * DMODEL + hoff + c4);
        v.x *= 0.125f; v.y *= 0.125f; v.z *= 0.125f; v.w *= 0.125f;
        *(float4*)&Qstage[r * QS_STRIDE + c4] = v;
    }
    __syncthreads();

    unsigned qf[8][4];
    {
        const int r0 = warp * 16;
        #pragma unroll
        for (int kk = 0; kk < 8; kk++) {
            qf[kk][0] = cvt_tf32(Qstage[(r0 + g)     * QS_STRIDE + kk * 8 + t]);
            qf[kk][1] = cvt_tf32(Qstage[(r0 + 8 + g) * QS_STRIDE + kk * 8 + t]);
            qf[kk][2] = cvt_tf32(Qstage[(r0 + g)     * QS_STRIDE + kk * 8 + 4 + t]);
            qf[kk][3] = cvt_tf32(Qstage[(r0 + 8 + g) * QS_STRIDE + kk * 8 + 4 + t]);
        }
    }
    __syncthreads();

    float m0 = -INFINITY, m1 = -INFINITY, l0 = 0.f, l1 = 0.f;
    float oacc[8][4];
    #pragma unroll
    for (int j = 0; j < 8; j++)
        #pragma unroll
        for (int e = 0; e < 4; e++) oacc[j][e] = 0.f;

    for (int kt = 0; kt < 32; kt++) {
        const size_t kvbase = ((size_t)b * SEQ + kt * 64) * DMODEL + hoff;

        #pragma unroll
        for (int it = 0; it < 4; it++) {
            int idx = tid + it * 256;
            int r = idx >> 4;
            int c4 = (idx & 15) << 2;
            *(uint4*)&Ks[r * KS_STRIDE + c4] =
                *(const uint4*)(K + kvbase + (size_t)r * DMODEL + c4);
            *(uint4*)&Vs[r * VS_STRIDE + c4] =
                *(const uint4*)(V + kvbase + (size_t)r * DMODEL + c4);
        }
        if (tid < 64)
            maskf[tid] = (mask[(size_t)b * SEQ + kt * 64 + tid] == 0) ? -INFINITY : 0.f;
        __syncthreads();

        float sacc[8][4];
        #pragma unroll
        for (int j = 0; j < 8; j++)
            #pragma unroll
            for (int e = 0; e < 4; e++) sacc[j][e] = 0.f;

        #pragma unroll
        for (int kk = 0; kk < 8; kk++) {
            #pragma unroll
            for (int nj = 0; nj < 8; nj++) {
                unsigned bf[2];
                bf[0] = Ks[(nj * 8 + g) * KS_STRIDE + kk * 8 + t];
                bf[1] = Ks[(nj * 8 + g) * KS_STRIDE + kk * 8 + 4 + t];
                mma_tf32(sacc[nj], qf[kk], bf);
            }
        }

        #pragma unroll
        for (int nj = 0; nj < 8; nj++) {
            float mk0 = maskf[nj * 8 + 2 * t];
            float mk1 = maskf[nj * 8 + 2 * t + 1];
            sacc[nj][0] += mk0; sacc[nj][1] += mk1;
            sacc[nj][2] += mk0; sacc[nj][3] += mk1;
        }

        {
            float mx0 = -INFINITY, mx1 = -INFINITY;
            #pragma unroll
            for (int nj = 0; nj < 8; nj++) {
                mx0 = fmaxf(mx0, fmaxf(sacc[nj][0], sacc[nj][1]));
                mx1 = fmaxf(mx1, fmaxf(sacc[nj][2], sacc[nj][3]));
            }
            mx0 = fmaxf(mx0, __shfl_xor_sync(0xffffffffu, mx0, 1));
            mx0 = fmaxf(mx0, __shfl_xor_sync(0xffffffffu, mx0, 2));
            mx1 = fmaxf(mx1, __shfl_xor_sync(0xffffffffu, mx1, 1));
            mx1 = fmaxf(mx1, __shfl_xor_sync(0xffffffffu, mx1, 2));
            float mn0 = fmaxf(m0, mx0), mn1 = fmaxf(m1, mx1);
            float corr0 = __expf(m0 - mn0), corr1 = __expf(m1 - mn1);

            float rs0 = 0.f, rs1 = 0.f;
            #pragma unroll
            for (int nj = 0; nj < 8; nj++) {
                sacc[nj][0] = __expf(sacc[nj][0] - mn0);
                sacc[nj][1] = __expf(sacc[nj][1] - mn0);
                sacc[nj][2] = __expf(sacc[nj][2] - mn1);
                sacc[nj][3] = __expf(sacc[nj][3] - mn1);
                rs0 += sacc[nj][0] + sacc[nj][1];
                rs1 += sacc[nj][2] + sacc[nj][3];
            }
            rs0 += __shfl_xor_sync(0xffffffffu, rs0, 1);
            rs0 += __shfl_xor_sync(0xffffffffu, rs0, 2);
            rs1 += __shfl_xor_sync(0xffffffffu, rs1, 1);
            rs1 += __shfl_xor_sync(0xffffffffu, rs1, 2);
            l0 = l0 * corr0 + rs0;  m0 = mn0;
            l1 = l1 * corr1 + rs1;  m1 = mn1;
            #pragma unroll
            for (int j = 0; j < 8; j++) {
                oacc[j][0] *= corr0; oacc[j][1] *= corr0;
                oacc[j][2] *= corr1; oacc[j][3] *= corr1;
            }
        }

        {
            const int src_lo = (lane & ~3) | (t >> 1);
            const int src_hi = src_lo + 2;
            const bool odd = (t & 1);
            #pragma unroll
            for (int j = 0; j < 8; j++) {
                float c0a = __shfl_sync(0xffffffffu, sacc[j][0], src_lo);
                float c1a = __shfl_sync(0xffffffffu, sacc[j][1], src_lo);
                float c0b = __shfl_sync(0xffffffffu, sacc[j][0], src_hi);
                float c1b = __shfl_sync(0xffffffffu, sacc[j][1], src_hi);
                float c2a = __shfl_sync(0xffffffffu, sacc[j][2], src_lo);
                float c3a = __shfl_sync(0xffffffffu, sacc[j][3], src_lo);
                float c2b = __shfl_sync(0xffffffffu, sacc[j][2], src_hi);
                float c3b = __shfl_sync(0xffffffffu, sacc[j][3], src_hi);
                unsigned af[4];
                af[0] = __float_as_uint(odd ? c1a : c0a);
                af[1] = __float_as_uint(odd ? c3a : c2a);
                af[2] = __float_as_uint(odd ? c1b : c0b);
                af[3] = __float_as_uint(odd ? c3b : c2b);
                #pragma unroll
                for (int jj = 0; jj < 8; jj++) {
                    unsigned bf[2];
                    bf[0] = Vs[(j * 8 + t)     * VS_STRIDE + jj * 8 + g];
                    bf[1] = Vs[(j * 8 + t + 4) * VS_STRIDE + jj * 8 + g];
                    mma_tf32(oacc[jj], af, bf);
                }
            }
        }
        __syncthreads();
    }

    {
        const float inv0 = 1.f / l0, inv1 = 1.f / l1;
        const size_t r0 = qrow0 + warp * 16 + g;
        #pragma unroll
        for (int jj = 0; jj < 8; jj++) {
            int col = jj * 8 + 2 * t;
            *(float2*)(O + r0 * DMODEL + hoff + col) =
                make_float2(rnd_tf32(oacc[jj][0] * inv0), rnd_tf32(oacc[jj][1] * inv0));
            *(float2*)(O + (r0 + 8) * DMODEL + hoff + col) =
                make_float2(rnd_tf32(oacc[jj][2] * inv1), rnd_tf32(oacc[jj][3] * inv1));
        }
    }
}

// ---------------------------------------------------------------------------
// out[row] = LayerNorm(a[row] + b[row]) * gamma + beta.
// Optionally also writes a tf32-rounded copy (out_r) for downstream GEMMs.
// ---------------------------------------------------------------------------
__global__ __launch_bounds__(256) void add_ln_kernel(
    const float* __restrict__ a, const float* __restrict__ bsrc,
    const float* __restrict__ g, const float* __restrict__ be,
    float* __restrict__ out, float* __restrict__ out_r)
{
    const int row = blockIdx.x;
    const int tid = threadIdx.x;
    const float* pa = a + (size_t)row * DMODEL;
    const float* pb = bsrc + (size_t)row * DMODEL;

    float v[4];
    float sum = 0.f, sq = 0.f;
    #pragma unroll
    for (int i = 0; i < 4; i++) {
        int c = tid + i * 256;
        float x = pa[c] + pb[c];
        v[i] = x;
        sum += x;
        sq += x * x;
    }
    #pragma unroll
    for (int o = 16; o > 0; o >>= 1) {
        sum += __shfl_xor_sync(0xffffffffu, sum, o);
        sq  += __shfl_xor_sync(0xffffffffu, sq,  o);
    }
    __shared__ float ssum[8], ssq[8];
    if ((tid & 31) == 0) { ssum[tid >> 5] = sum; ssq[tid >> 5] = sq; }
    __syncthreads();
    if (tid < 32) {
        float s2 = (tid < 8) ? ssum[tid] : 0.f;
        float q2 = (tid < 8) ? ssq[tid] : 0.f;
        #pragma unroll
        for (int o = 4; o > 0; o >>= 1) {
            s2 += __shfl_xor_sync(0xffffffffu, s2, o);
            q2 += __shfl_xor_sync(0xffffffffu, q2, o);
        }
        if (tid == 0) { ssum[0] = s2; ssq[0] = q2; }
    }
    __syncthreads();
    const float mu   = ssum[0] * (1.f / DMODEL);
    const float var  = ssq[0] * (1.f / DMODEL) - mu * mu;
    const float rstd = rsqrtf(var + 1e-5f);

    float* po = out + (size_t)row * DMODEL;
    float* pr = out_r ? out_r + (size_t)row * DMODEL : nullptr;
    #pragma unroll
    for (int i = 0; i < 4; i++) {
        int c = tid + i * 256;
        float y = (v[i] - mu) * rstd * g[c] + be[c];
        po[c] = y;
        if (pr) pr[c] = rnd_tf32(y);
    }
}

// ---------------------------------------------------------------------------
// Launch
// ---------------------------------------------------------------------------
extern "C" void kernel_launch(void* const* d_in, const int* in_sizes, int n_in,
                              void* d_out, int out_size)
{
    (void)in_sizes; (void)n_in; (void)out_size;
    const float* x    = (const float*)d_in[0];
    const int*   mask = (const int*)  d_in[1];
    const float* w_q  = (const float*)d_in[2];
    const float* b_q  = (const float*)d_in[3];
    const float* w_k  = (const float*)d_in[4];
    const float* b_k  = (const float*)d_in[5];
    const float* w_v  = (const float*)d_in[6];
    const float* b_v  = (const float*)d_in[7];
    const float* w_o  = (const float*)d_in[8];
    const float* b_o  = (const float*)d_in[9];
    const float* w1   = (const float*)d_in[10];
    const float* b1   = (const float*)d_in[11];
    const float* w2   = (const float*)d_in[12];
    const float* b2   = (const float*)d_in[13];
    const float* g1   = (const float*)d_in[14];
    const float* be1  = (const float*)d_in[15];
    const float* g2   = (const float*)d_in[16];
    const float* be2  = (const float*)d_in[17];

    float *q, *k, *v, *ctx, *t1, *h, *hr, *ff;
    float *xr, *wqr, *wkr, *wvr, *wor, *w1r, *w2r;
    cudaGetSymbolAddress((void**)&q,   g_q);
    cudaGetSymbolAddress((void**)&k,   g_k);
    cudaGetSymbolAddress((void**)&v,   g_v);
    cudaGetSymbolAddress((void**)&ctx, g_ctx);
    cudaGetSymbolAddress((void**)&t1,  g_t1);
    cudaGetSymbolAddress((void**)&h,   g_h);
    cudaGetSymbolAddress((void**)&hr,  g_hr);
    cudaGetSymbolAddress((void**)&ff,  g_ff);
    cudaGetSymbolAddress((void**)&xr,  g_xr);
    cudaGetSymbolAddress((void**)&wqr, g_wqr);
    cudaGetSymbolAddress((void**)&wkr, g_wkr);
    cudaGetSymbolAddress((void**)&wvr, g_wvr);
    cudaGetSymbolAddress((void**)&wor, g_wor);
    cudaGetSymbolAddress((void**)&w1r, g_w1r);
    cudaGetSymbolAddress((void**)&w2r, g_w2r);

    cudaFuncSetAttribute(gemm_tf32, cudaFuncAttributeMaxDynamicSharedMemorySize,
                         GEMM_SMEM_BYTES);
    cudaFuncSetAttribute(attn3, cudaFuncAttributeMaxDynamicSharedMemorySize,
                         ATTN_SMEM_BYTES);

    // ---- pre-round GEMM inputs to tf32 (rna) ----
    {
        const int TB = 256;
        int n;
        n = MROWS * DMODEL / 4;  round_tf32_kernel<<<(n + TB - 1) / TB, TB>>>(x,   xr,  n);
        n = DMODEL * DMODEL / 4; round_tf32_kernel<<<(n + TB - 1) / TB, TB>>>(w_q, wqr, n);
        n = DMODEL * DMODEL / 4; round_tf32_kernel<<<(n + TB - 1) / TB, TB>>>(w_k, wkr, n);
        n = DMODEL * DMODEL / 4; round_tf32_kernel<<<(n + TB - 1) / TB, TB>>>(w_v, wvr, n);
        n = DMODEL * DMODEL / 4; round_tf32_kernel<<<(n + TB - 1) / TB, TB>>>(w_o, wor, n);
        n = DMODEL * DFF / 4;    round_tf32_kernel<<<(n + TB - 1) / TB, TB>>>(w1,  w1r, n);
        n = DFF * DMODEL / 4;    round_tf32_kernel<<<(n + TB - 1) / TB, TB>>>(w2,  w2r, n);
    }

    dim3 blk(256);
    dim3 gProj(DMODEL / 128, MROWS / 256);   // (8, 32)
    dim3 gFF1(DFF / 128, MROWS / 256);       // (32, 32)
    dim3 gAtt(SEQ / 128, NHEADS, BATCH);     // (16, 16, 4)

    // QKV projections: outputs rounded to tf32 (consumed by attn mma)
    gemm_tf32<<<gProj, blk, GEMM_SMEM_BYTES>>>(MROWS, DMODEL, DMODEL, xr, wqr, b_q, q, 0, 1);
    gemm_tf32<<<gProj, blk, GEMM_SMEM_BYTES>>>(MROWS, DMODEL, DMODEL, xr, wkr, b_k, k, 0, 1);
    gemm_tf32<<<gProj, blk, GEMM_SMEM_BYTES>>>(MROWS, DMODEL, DMODEL, xr, wvr, b_v, v, 0, 1);

    attn3<<<gAtt, blk, ATTN_SMEM_BYTES>>>(q, k, v, mask, ctx);  // ctx rounded

    gemm_tf32<<<gProj, blk, GEMM_SMEM_BYTES>>>(MROWS, DMODEL, DMODEL, ctx, wor, b_o, t1, 0, 0);
    add_ln_kernel<<<MROWS, 256>>>(x, t1, g1, be1, h, hr);

    gemm_tf32<<<gFF1, blk, GEMM_SMEM_BYTES>>>(MROWS, DFF, DMODEL, hr, w1r, b1, ff, 1, 1);
    gemm_tf32<<<gProj, blk, GEMM_SMEM_BYTES>>>(MROWS, DMODEL, DFF, ff, w2r, b2, t1, 0, 0);
    add_ln_kernel<<<MROWS, 256>>>(h, t1, g2, be2, (float*)d_out, nullptr);
}

// round 10
// speedup vs baseline: 1.5190x; 1.5190x over previous
#include <cuda_runtime.h>
#include <math.h>

// ---------------------------------------------------------------------------
// Problem constants
// ---------------------------------------------------------------------------
#define BATCH 4
#define SEQ   2048
#define DMODEL 1024
#define NHEADS 16
#define DK    64
#define DFF   4096
#define MROWS (BATCH * SEQ)   // 8192

// ---------------------------------------------------------------------------
// Scratch (no cudaMalloc allowed)
// ---------------------------------------------------------------------------
__device__ float g_q  [MROWS * DMODEL];
__device__ float g_k  [MROWS * DMODEL];
__device__ float g_v  [MROWS * DMODEL];
__device__ float g_ctx[MROWS * DMODEL];
__device__ float g_t1 [MROWS * DMODEL];
__device__ float g_h  [MROWS * DMODEL];
__device__ float g_hr [MROWS * DMODEL];
__device__ float g_ff [MROWS * DFF];
__device__ float g_xr [MROWS * DMODEL];
__device__ float g_wqr[DMODEL * DMODEL];
__device__ float g_wkr[DMODEL * DMODEL];
__device__ float g_wvr[DMODEL * DMODEL];
__device__ float g_wor[DMODEL * DMODEL];
__device__ float g_w1r[DMODEL * DFF];
__device__ float g_w2r[DFF * DMODEL];

// ---------------------------------------------------------------------------
// Helpers
// ---------------------------------------------------------------------------
__device__ __forceinline__ unsigned cvt_tf32(float x) {
    unsigned r;
    asm("cvt.rna.tf32.f32 %0, %1;" : "=r"(r) : "f"(x));
    return r;
}
__device__ __forceinline__ float rnd_tf32(float x) {
    return __uint_as_float(cvt_tf32(x));
}

__device__ __forceinline__ void mma_tf32(float* c, const unsigned* a, const unsigned* b) {
    asm volatile(
        "mma.sync.aligned.m16n8k8.row.col.f32.tf32.tf32.f32 "
        "{%0,%1,%2,%3}, {%4,%5,%6,%7}, {%8,%9}, {%0,%1,%2,%3};"
        : "+f"(c[0]), "+f"(c[1]), "+f"(c[2]), "+f"(c[3])
        : "r"(a[0]), "r"(a[1]), "r"(a[2]), "r"(a[3]), "r"(b[0]), "r"(b[1]));
}

__device__ __forceinline__ void cp_async16(void* smem_dst, const void* gmem_src) {
    unsigned saddr = (unsigned)__cvta_generic_to_shared(smem_dst);
    asm volatile("cp.async.cg.shared.global [%0], [%1], 16;"
                 :: "r"(saddr), "l"(gmem_src));
}
#define CP_COMMIT() asm volatile("cp.async.commit_group;")
#define CP_WAIT(n)  asm volatile("cp.async.wait_group %0;" :: "n"(n))

// ---------------------------------------------------------------------------
// Elementwise tf32 (rna) rounding: dst[i] = round_tf32(src[i])
// ---------------------------------------------------------------------------
__global__ __launch_bounds__(256) void round_tf32_kernel(
    const float* __restrict__ src, float* __restrict__ dst, int n4)
{
    int i = blockIdx.x * 256 + threadIdx.x;
    if (i < n4) {
        float4 v = ((const float4*)src)[i];
        v.x = rnd_tf32(v.x); v.y = rnd_tf32(v.y);
        v.z = rnd_tf32(v.z); v.w = rnd_tf32(v.w);
        ((float4*)dst)[i] = v;
    }
}

// ---------------------------------------------------------------------------
// TF32 tensor-core GEMM, 2-stage cp.async pipeline.
// C[M,N] = A[M,K] @ B[K,N] + bias[N] (optional ReLU, optional tf32-round out)
// BM=256, BN=128, BK=32. 256 threads = 8 warps (4x2), warp tile 64x64.
// Inputs are assumed pre-rounded to tf32 (raw bits fed to mma).
// ---------------------------------------------------------------------------
#define AS_STRIDE 36
#define BS_STRIDE 132
#define STAGE_FLOATS (256 * AS_STRIDE + 32 * BS_STRIDE)
#define GEMM_SMEM_BYTES (2 * STAGE_FLOATS * 4)

__global__ __launch_bounds__(256, 1) void gemm_tf32(
    int M, int N, int K,
    const float* __restrict__ A, const float* __restrict__ B,
    const float* __restrict__ bias, float* __restrict__ C, int relu, int rnd)
{
    extern __shared__ float sm[];

    const int tid  = threadIdx.x;
    const int lane = tid & 31;
    const int warp = tid >> 5;
    const int wm = (warp >> 1) * 64;   // 0,64,128,192
    const int wn = (warp & 1) * 64;    // 0,64
    const int g = lane >> 2;
    const int t = lane & 3;
    const int cRow = blockIdx.y, cCol = blockIdx.x;

    const int aRow = tid >> 3;         // 0..31
    const int aCol = (tid & 7) * 4;    // 0..28
    const int bRow = tid >> 5;         // 0..7
    const int bCol = (tid & 31) * 4;   // 0..124

    const float* Ag = A + (size_t)(cRow * 256) * K;
    const float* Bg = B + cCol * 128;

    float acc[4][8][4];
    #pragma unroll
    for (int i = 0; i < 4; i++)
        #pragma unroll
        for (int j = 0; j < 8; j++)
            #pragma unroll
            for (int e = 0; e < 4; e++) acc[i][j][e] = 0.f;

    const int NT = K >> 5;

    {
        float* As = sm;
        float* Bs = sm + 256 * AS_STRIDE;
        #pragma unroll
        for (int r = 0; r < 8; r++)
            cp_async16(&As[(aRow + r * 32) * AS_STRIDE + aCol],
                       Ag + (size_t)(aRow + r * 32) * K + aCol);
        #pragma unroll
        for (int r = 0; r < 4; r++)
            cp_async16(&Bs[(bRow + r * 8) * BS_STRIDE + bCol],
                       Bg + (size_t)(bRow + r * 8) * N + bCol);
        CP_COMMIT();
    }

    for (int it = 0; it < NT; it++) {
        if (it + 1 < NT) {
            const int k0 = (it + 1) << 5;
            float* As = sm + ((it + 1) & 1) * STAGE_FLOATS;
            float* Bs = As + 256 * AS_STRIDE;
            #pragma unroll
            for (int r = 0; r < 8; r++)
                cp_async16(&As[(aRow + r * 32) * AS_STRIDE + aCol],
                           Ag + (size_t)(aRow + r * 32) * K + k0 + aCol);
            #pragma unroll
            for (int r = 0; r < 4; r++)
                cp_async16(&Bs[(bRow + r * 8) * BS_STRIDE + bCol],
                           Bg + (size_t)(k0 + bRow + r * 8) * N + bCol);
            CP_COMMIT();
            CP_WAIT(1);
        } else {
            CP_WAIT(0);
        }
        __syncthreads();

        const unsigned* Asu = (const unsigned*)(sm + (it & 1) * STAGE_FLOATS);
        const unsigned* Bsu = Asu + 256 * AS_STRIDE;

        #pragma unroll
        for (int k8 = 0; k8 < 4; k8++) {
            const int kb = k8 * 8;
            unsigned af[4][4], bf[8][2];
            #pragma unroll
            for (int tm = 0; tm < 4; tm++) {
                int r0 = (wm + tm * 16 + g) * AS_STRIDE;
                af[tm][0] = Asu[r0 + kb + t];
                af[tm][1] = Asu[r0 + 8 * AS_STRIDE + kb + t];
                af[tm][2] = Asu[r0 + kb + 4 + t];
                af[tm][3] = Asu[r0 + 8 * AS_STRIDE + kb + 4 + t];
            }
            #pragma unroll
            for (int tn = 0; tn < 8; tn++) {
                bf[tn][0] = Bsu[(kb + t) * BS_STRIDE + wn + tn * 8 + g];
                bf[tn][1] = Bsu[(kb + 4 + t) * BS_STRIDE + wn + tn * 8 + g];
            }
            #pragma unroll
            for (int tm = 0; tm < 4; tm++)
                #pragma unroll
                for (int tn = 0; tn < 8; tn++)
                    mma_tf32(acc[tm][tn], af[tm], bf[tn]);
        }
        __syncthreads();
    }

    #pragma unroll
    for (int tm = 0; tm < 4; tm++) {
        #pragma unroll
        for (int tn = 0; tn < 8; tn++) {
            int row = cRow * 256 + wm + tm * 16 + g;
            int col = cCol * 128 + wn + tn * 8 + 2 * t;
            float2 bb = *(const float2*)(bias + col);
            float2 v0 = make_float2(acc[tm][tn][0] + bb.x, acc[tm][tn][1] + bb.y);
            float2 v1 = make_float2(acc[tm][tn][2] + bb.x, acc[tm][tn][3] + bb.y);
            if (relu) {
                v0.x = fmaxf(v0.x, 0.f); v0.y = fmaxf(v0.y, 0.f);
                v1.x = fmaxf(v1.x, 0.f); v1.y = fmaxf(v1.y, 0.f);
            }
            if (rnd) {
                v0.x = rnd_tf32(v0.x); v0.y = rnd_tf32(v0.y);
                v1.x = rnd_tf32(v1.x); v1.y = rnd_tf32(v1.y);
            }
            *(float2*)(C + (size_t)row * N + col) = v0;
            *(float2*)(C + (size_t)(row + 8) * N + col) = v1;
        }
    }
}

// ---------------------------------------------------------------------------
// Flash attention on tensor cores (tf32 mma.sync m16n8k8).
// Inputs Q/K/V are already exact tf32 (rounded by producing GEMM epilogue),
// so raw-bit feeding == rna semantics. Output ctx is rounded to tf32.
// ---------------------------------------------------------------------------
#define QS_STRIDE 68
#define KS_STRIDE 68
#define VS_STRIDE 72
#define ATTN_SMEM_BYTES (64 * KS_STRIDE * 4 + 64 * VS_STRIDE * 4 + 256)

__global__ __launch_bounds__(256, 2) void attn3(
    const float* __restrict__ Q, const float* __restrict__ K,
    const float* __restrict__ V, const int* __restrict__ mask,
    float* __restrict__ O)
{
    extern __shared__ char smc[];
    float*    Qstage = (float*)smc;
    unsigned* Ks     = (unsigned*)smc;
    unsigned* Vs     = (unsigned*)(smc + 64 * KS_STRIDE * 4);
    float*    maskf  = (float*)(smc + 64 * KS_STRIDE * 4 + 64 * VS_STRIDE * 4);

    const int qt = blockIdx.x, h = blockIdx.y, b = blockIdx.z;
    const int tid  = threadIdx.x;
    const int lane = tid & 31;
    const int warp = tid >> 5;
    const int g = lane >> 2;
    const int t = lane & 3;
    const size_t hoff = (size_t)h * DK;
    const size_t qrow0 = (size_t)b * SEQ + qt * 128;

    #pragma unroll
    for (int it = 0; it < 8; it++) {
        int idx = tid + it * 256;
        int r = idx >> 4;
        int c4 = (idx & 15) << 2;
        float4 v = *(const float4*)(Q + (qrow0 + r) * DMODEL + hoff + c4);
        v.x *= 0.125f; v.y *= 0.125f; v.z *= 0.125f; v.w *= 0.125f;
        *(float4*)&Qstage[r * QS_STRIDE + c4] = v;
    }
    __syncthreads();

    unsigned qf[8][4];
    {
        const int r0 = warp * 16;
        #pragma unroll
        for (int kk = 0; kk < 8; kk++) {
            qf[kk][0] = cvt_tf32(Qstage[(r0 + g)     * QS_STRIDE + kk * 8 + t]);
            qf[kk][1] = cvt_tf32(Qstage[(r0 + 8 + g) * QS_STRIDE + kk * 8 + t]);
            qf[kk][2] = cvt_tf32(Qstage[(r0 + g)     * QS_STRIDE + kk * 8 + 4 + t]);
            qf[kk][3] = cvt_tf32(Qstage[(r0 + 8 + g) * QS_STRIDE + kk * 8 + 4 + t]);
        }
    }
    __syncthreads();

    float m0 = -INFINITY, m1 = -INFINITY, l0 = 0.f, l1 = 0.f;
    float oacc[8][4];
    #pragma unroll
    for (int j = 0; j < 8; j++)
        #pragma unroll
        for (int e = 0; e < 4; e++) oacc[j][e] = 0.f;

    for (int kt = 0; kt < 32; kt++) {
        const size_t kvbase = ((size_t)b * SEQ + kt * 64) * DMODEL + hoff;

        #pragma unroll
        for (int it = 0; it < 4; it++) {
            int idx = tid + it * 256;
            int r = idx >> 4;
            int c4 = (idx & 15) << 2;
            *(uint4*)&Ks[r * KS_STRIDE + c4] =
                *(const uint4*)(K + kvbase + (size_t)r * DMODEL + c4);
            *(uint4*)&Vs[r * VS_STRIDE + c4] =
                *(const uint4*)(V + kvbase + (size_t)r * DMODEL + c4);
        }
        if (tid < 64)
            maskf[tid] = (mask[(size_t)b * SEQ + kt * 64 + tid] == 0) ? -INFINITY : 0.f;
        __syncthreads();

        float sacc[8][4];
        #pragma unroll
        for (int j = 0; j < 8; j++)
            #pragma unroll
            for (int e = 0; e < 4; e++) sacc[j][e] = 0.f;

        #pragma unroll
        for (int kk = 0; kk < 8; kk++) {
            #pragma unroll
            for (int nj = 0; nj < 8; nj++) {
                unsigned bf[2];
                bf[0] = Ks[(nj * 8 + g) * KS_STRIDE + kk * 8 + t];
                bf[1] = Ks[(nj * 8 + g) * KS_STRIDE + kk * 8 + 4 + t];
                mma_tf32(sacc[nj], qf[kk], bf);
            }
        }

        #pragma unroll
        for (int nj = 0; nj < 8; nj++) {
            float mk0 = maskf[nj * 8 + 2 * t];
            float mk1 = maskf[nj * 8 + 2 * t + 1];
            sacc[nj][0] += mk0; sacc[nj][1] += mk1;
            sacc[nj][2] += mk0; sacc[nj][3] += mk1;
        }

        {
            float mx0 = -INFINITY, mx1 = -INFINITY;
            #pragma unroll
            for (int nj = 0; nj < 8; nj++) {
                mx0 = fmaxf(mx0, fmaxf(sacc[nj][0], sacc[nj][1]));
                mx1 = fmaxf(mx1, fmaxf(sacc[nj][2], sacc[nj][3]));
            }
            mx0 = fmaxf(mx0, __shfl_xor_sync(0xffffffffu, mx0, 1));
            mx0 = fmaxf(mx0, __shfl_xor_sync(0xffffffffu, mx0, 2));
            mx1 = fmaxf(mx1, __shfl_xor_sync(0xffffffffu, mx1, 1));
            mx1 = fmaxf(mx1, __shfl_xor_sync(0xffffffffu, mx1, 2));
            float mn0 = fmaxf(m0, mx0), mn1 = fmaxf(m1, mx1);
            float corr0 = __expf(m0 - mn0), corr1 = __expf(m1 - mn1);

            float rs0 = 0.f, rs1 = 0.f;
            #pragma unroll
            for (int nj = 0; nj < 8; nj++) {
                sacc[nj][0] = __expf(sacc[nj][0] - mn0);
                sacc[nj][1] = __expf(sacc[nj][1] - mn0);
                sacc[nj][2] = __expf(sacc[nj][2] - mn1);
                sacc[nj][3] = __expf(sacc[nj][3] - mn1);
                rs0 += sacc[nj][0] + sacc[nj][1];
                rs1 += sacc[nj][2] + sacc[nj][3];
            }
            rs0 += __shfl_xor_sync(0xffffffffu, rs0, 1);
            rs0 += __shfl_xor_sync(0xffffffffu, rs0, 2);
            rs1 += __shfl_xor_sync(0xffffffffu, rs1, 1);
            rs1 += __shfl_xor_sync(0xffffffffu, rs1, 2);
            l0 = l0 * corr0 + rs0;  m0 = mn0;
            l1 = l1 * corr1 + rs1;  m1 = mn1;
            #pragma unroll
            for (int j = 0; j < 8; j++) {
                oacc[j][0] *= corr0; oacc[j][1] *= corr0;
                oacc[j][2] *= corr1; oacc[j][3] *= corr1;
            }
        }

        {
            const int src_lo = (lane & ~3) | (t >> 1);
            const int src_hi = src_lo + 2;
            const bool odd = (t & 1);
            #pragma unroll
            for (int j = 0; j < 8; j++) {
                float c0a = __shfl_sync(0xffffffffu, sacc[j][0], src_lo);
                float c1a = __shfl_sync(0xffffffffu, sacc[j][1], src_lo);
                float c0b = __shfl_sync(0xffffffffu, sacc[j][0], src_hi);
                float c1b = __shfl_sync(0xffffffffu, sacc[j][1], src_hi);
                float c2a = __shfl_sync(0xffffffffu, sacc[j][2], src_lo);
                float c3a = __shfl_sync(0xffffffffu, sacc[j][3], src_lo);
                float c2b = __shfl_sync(0xffffffffu, sacc[j][2], src_hi);
                float c3b = __shfl_sync(0xffffffffu, sacc[j][3], src_hi);
                unsigned af[4];
                af[0] = __float_as_uint(odd ? c1a : c0a);
                af[1] = __float_as_uint(odd ? c3a : c2a);
                af[2] = __float_as_uint(odd ? c1b : c0b);
                af[3] = __float_as_uint(odd ? c3b : c2b);
                #pragma unroll
                for (int jj = 0; jj < 8; jj++) {
                    unsigned bf[2];
                    bf[0] = Vs[(j * 8 + t)     * VS_STRIDE + jj * 8 + g];
                    bf[1] = Vs[(j * 8 + t + 4) * VS_STRIDE + jj * 8 + g];
                    mma_tf32(oacc[jj], af, bf);
                }
            }
        }
        __syncthreads();
    }

    {
        const float inv0 = 1.f / l0, inv1 = 1.f / l1;
        const size_t r0 = qrow0 + warp * 16 + g;
        #pragma unroll
        for (int jj = 0; jj < 8; jj++) {
            int col = jj * 8 + 2 * t;
            *(float2*)(O + r0 * DMODEL + hoff + col) =
                make_float2(rnd_tf32(oacc[jj][0] * inv0), rnd_tf32(oacc[jj][1] * inv0));
            *(float2*)(O + (r0 + 8) * DMODEL + hoff + col) =
                make_float2(rnd_tf32(oacc[jj][2] * inv1), rnd_tf32(oacc[jj][3] * inv1));
        }
    }
}

// ---------------------------------------------------------------------------
// out[row] = LayerNorm(a[row] + b[row]) * gamma + beta.
// Optionally also writes a tf32-rounded copy (out_r) for downstream GEMMs.
// ---------------------------------------------------------------------------
__global__ __launch_bounds__(256) void add_ln_kernel(
    const float* __restrict__ a, const float* __restrict__ bsrc,
    const float* __restrict__ g, const float* __restrict__ be,
    float* __restrict__ out, float* __restrict__ out_r)
{
    const int row = blockIdx.x;
    const int tid = threadIdx.x;
    const float* pa = a + (size_t)row * DMODEL;
    const float* pb = bsrc + (size_t)row * DMODEL;

    float v[4];
    float sum = 0.f, sq = 0.f;
    #pragma unroll
    for (int i = 0; i < 4; i++) {
        int c = tid + i * 256;
        float x = pa[c] + pb[c];
        v[i] = x;
        sum += x;
        sq += x * x;
    }
    #pragma unroll
    for (int o = 16; o > 0; o >>= 1) {
        sum += __shfl_xor_sync(0xffffffffu, sum, o);
        sq  += __shfl_xor_sync(0xffffffffu, sq,  o);
    }
    __shared__ float ssum[8], ssq[8];
    if ((tid & 31) == 0) { ssum[tid >> 5] = sum; ssq[tid >> 5] = sq; }
    __syncthreads();
    if (tid < 32) {
        float s2 = (tid < 8) ? ssum[tid] : 0.f;
        float q2 = (tid < 8) ? ssq[tid] : 0.f;
        #pragma unroll
        for (int o = 4; o > 0; o >>= 1) {
            s2 += __shfl_xor_sync(0xffffffffu, s2, o);
            q2 += __shfl_xor_sync(0xffffffffu, q2, o);
        }
        if (tid == 0) { ssum[0] = s2; ssq[0] = q2; }
    }
    __syncthreads();
    const float mu   = ssum[0] * (1.f / DMODEL);
    const float var  = ssq[0] * (1.f / DMODEL) - mu * mu;
    const float rstd = rsqrtf(var + 1e-5f);

    float* po = out + (size_t)row * DMODEL;
    float* pr = out_r ? out_r + (size_t)row * DMODEL : nullptr;
    #pragma unroll
    for (int i = 0; i < 4; i++) {
        int c = tid + i * 256;
        float y = (v[i] - mu) * rstd * g[c] + be[c];
        po[c] = y;
        if (pr) pr[c] = rnd_tf32(y);
    }
}

// ---------------------------------------------------------------------------
// Launch
// ---------------------------------------------------------------------------
extern "C" void kernel_launch(void* const* d_in, const int* in_sizes, int n_in,
                              void* d_out, int out_size)
{
    (void)in_sizes; (void)n_in; (void)out_size;
    const float* x    = (const float*)d_in[0];
    const int*   mask = (const int*)  d_in[1];
    const float* w_q  = (const float*)d_in[2];
    const float* b_q  = (const float*)d_in[3];
    const float* w_k  = (const float*)d_in[4];
    const float* b_k  = (const float*)d_in[5];
    const float* w_v  = (const float*)d_in[6];
    const float* b_v  = (const float*)d_in[7];
    const float* w_o  = (const float*)d_in[8];
    const float* b_o  = (const float*)d_in[9];
    const float* w1   = (const float*)d_in[10];
    const float* b1   = (const float*)d_in[11];
    const float* w2   = (const float*)d_in[12];
    const float* b2   = (const float*)d_in[13];
    const float* g1   = (const float*)d_in[14];
    const float* be1  = (const float*)d_in[15];
    const float* g2   = (const float*)d_in[16];
    const float* be2  = (const float*)d_in[17];

    float *q, *k, *v, *ctx, *t1, *h, *hr, *ff;
    float *xr, *wqr, *wkr, *wvr, *wor, *w1r, *w2r;
    cudaGetSymbolAddress((void**)&q,   g_q);
    cudaGetSymbolAddress((void**)&k,   g_k);
    cudaGetSymbolAddress((void**)&v,   g_v);
    cudaGetSymbolAddress((void**)&ctx, g_ctx);
    cudaGetSymbolAddress((void**)&t1,  g_t1);
    cudaGetSymbolAddress((void**)&h,   g_h);
    cudaGetSymbolAddress((void**)&hr,  g_hr);
    cudaGetSymbolAddress((void**)&ff,  g_ff);
    cudaGetSymbolAddress((void**)&xr,  g_xr);
    cudaGetSymbolAddress((void**)&wqr, g_wqr);
    cudaGetSymbolAddress((void**)&wkr, g_wkr);
    cudaGetSymbolAddress((void**)&wvr, g_wvr);
    cudaGetSymbolAddress((void**)&wor, g_wor);
    cudaGetSymbolAddress((void**)&w1r, g_w1r);
    cudaGetSymbolAddress((void**)&w2r, g_w2r);

    cudaFuncSetAttribute(gemm_tf32, cudaFuncAttributeMaxDynamicSharedMemorySize,
                         GEMM_SMEM_BYTES);
    cudaFuncSetAttribute(attn3, cudaFuncAttributeMaxDynamicSharedMemorySize,
                         ATTN_SMEM_BYTES);

    // ---- pre-round GEMM inputs to tf32 (rna) ----
    {
        const int TB = 256;
        int n;
        n = MROWS * DMODEL / 4;  round_tf32_kernel<<<(n + TB - 1) / TB, TB>>>(x,   xr,  n);
        n = DMODEL * DMODEL / 4; round_tf32_kernel<<<(n + TB - 1) / TB, TB>>>(w_q, wqr, n);
        n = DMODEL * DMODEL / 4; round_tf32_kernel<<<(n + TB - 1) / TB, TB>>>(w_k, wkr, n);
        n = DMODEL * DMODEL / 4; round_tf32_kernel<<<(n + TB - 1) / TB, TB>>>(w_v, wvr, n);
        n = DMODEL * DMODEL / 4; round_tf32_kernel<<<(n + TB - 1) / TB, TB>>>(w_o, wor, n);
        n = DMODEL * DFF / 4;    round_tf32_kernel<<<(n + TB - 1) / TB, TB>>>(w1,  w1r, n);
        n = DFF * DMODEL / 4;    round_tf32_kernel<<<(n + TB - 1) / TB, TB>>>(w2,  w2r, n);
    }

    dim3 blk(256);
    dim3 gProj(DMODEL / 128, MROWS / 256);   // (8, 32)
    dim3 gFF1(DFF / 128, MROWS / 256);       // (32, 32)
    dim3 gAtt(SEQ / 128, NHEADS, BATCH);     // (16, 16, 4)

    // QKV projections: outputs rounded to tf32 (consumed by attn mma)
    gemm_tf32<<<gProj, blk, GEMM_SMEM_BYTES>>>(MROWS, DMODEL, DMODEL, xr, wqr, b_q, q, 0, 1);
    gemm_tf32<<<gProj, blk, GEMM_SMEM_BYTES>>>(MROWS, DMODEL, DMODEL, xr, wkr, b_k, k, 0, 1);
    gemm_tf32<<<gProj, blk, GEMM_SMEM_BYTES>>>(MROWS, DMODEL, DMODEL, xr, wvr, b_v, v, 0, 1);

    attn3<<<gAtt, blk, ATTN_SMEM_BYTES>>>(q, k, v, mask, ctx);  // ctx rounded

    gemm_tf32<<<gProj, blk, GEMM_SMEM_BYTES>>>(MROWS, DMODEL, DMODEL, ctx, wor, b_o, t1, 0, 0);
    add_ln_kernel<<<MROWS, 256>>>(x, t1, g1, be1, h, hr);

    gemm_tf32<<<gFF1, blk, GEMM_SMEM_BYTES>>>(MROWS, DFF, DMODEL, hr, w1r, b1, ff, 1, 1);
    gemm_tf32<<<gProj, blk, GEMM_SMEM_BYTES>>>(MROWS, DMODEL, DFF, ff, w2r, b2, t1, 0, 0);
    add_ln_kernel<<<MROWS, 256>>>(h, t1, g2, be2, (float*)d_out, nullptr);
}

// round 11
// speedup vs baseline: 1.5195x; 1.0003x over previous
#include <cuda_runtime.h>
#include <math.h>

// ---------------------------------------------------------------------------
// Problem constants
// ---------------------------------------------------------------------------
#define BATCH 4
#define SEQ   2048
#define DMODEL 1024
#define NHEADS 16
#define DK    64
#define DFF   4096
#define MROWS (BATCH * SEQ)   // 8192

// ---------------------------------------------------------------------------
// Scratch (no cudaMalloc allowed)
// ---------------------------------------------------------------------------
__device__ float g_q  [MROWS * DMODEL];
__device__ float g_k  [MROWS * DMODEL];
__device__ float g_v  [MROWS * DMODEL];
__device__ float g_ctx[MROWS * DMODEL];
__device__ float g_t1 [MROWS * DMODEL];
__device__ float g_h  [MROWS * DMODEL];
__device__ float g_hr [MROWS * DMODEL];
__device__ float g_ff [MROWS * DFF];
__device__ float g_xr [MROWS * DMODEL];
__device__ float g_wqr[DMODEL * DMODEL];
__device__ float g_wkr[DMODEL * DMODEL];
__device__ float g_wvr[DMODEL * DMODEL];
__device__ float g_wor[DMODEL * DMODEL];
__device__ float g_w1r[DMODEL * DFF];
__device__ float g_w2r[DFF * DMODEL];

// ---------------------------------------------------------------------------
// Helpers
// ---------------------------------------------------------------------------
__device__ __forceinline__ unsigned cvt_tf32(float x) {
    unsigned r;
    asm("cvt.rna.tf32.f32 %0, %1;" : "=r"(r) : "f"(x));
    return r;
}
__device__ __forceinline__ float rnd_tf32(float x) {
    return __uint_as_float(cvt_tf32(x));
}

__device__ __forceinline__ void mma_tf32(float* c, const unsigned* a, const unsigned* b) {
    asm volatile(
        "mma.sync.aligned.m16n8k8.row.col.f32.tf32.tf32.f32 "
        "{%0,%1,%2,%3}, {%4,%5,%6,%7}, {%8,%9}, {%0,%1,%2,%3};"
        : "+f"(c[0]), "+f"(c[1]), "+f"(c[2]), "+f"(c[3])
        : "r"(a[0]), "r"(a[1]), "r"(a[2]), "r"(a[3]), "r"(b[0]), "r"(b[1]));
}

__device__ __forceinline__ void cp_async16(void* smem_dst, const void* gmem_src) {
    unsigned saddr = (unsigned)__cvta_generic_to_shared(smem_dst);
    asm volatile("cp.async.cg.shared.global [%0], [%1], 16;"
                 :: "r"(saddr), "l"(gmem_src));
}
#define CP_COMMIT() asm volatile("cp.async.commit_group;")
#define CP_WAIT(n)  asm volatile("cp.async.wait_group %0;" :: "n"(n))

// ---------------------------------------------------------------------------
// Elementwise tf32 (rna) rounding: dst[i] = round_tf32(src[i])
// ---------------------------------------------------------------------------
__global__ __launch_bounds__(256) void round_tf32_kernel(
    const float* __restrict__ src, float* __restrict__ dst, int n4)
{
    int i = blockIdx.x * 256 + threadIdx.x;
    if (i < n4) {
        float4 v = ((const float4*)src)[i];
        v.x = rnd_tf32(v.x); v.y = rnd_tf32(v.y);
        v.z = rnd_tf32(v.z); v.w = rnd_tf32(v.w);
        ((float4*)dst)[i] = v;
    }
}

// ---------------------------------------------------------------------------
// TF32 tensor-core GEMM, 2-stage cp.async pipeline.
// C[M,N] = A[M,K] @ B[K,N] + bias[N] (optional ReLU, optional tf32-round out)
// BM=256, BN=128, BK=32. 256 threads = 8 warps (4x2), warp tile 64x64.
// Inputs are assumed pre-rounded to tf32 (raw bits fed to mma).
// ---------------------------------------------------------------------------
#define AS_STRIDE 36
#define BS_STRIDE 132
#define STAGE_FLOATS (256 * AS_STRIDE + 32 * BS_STRIDE)
#define GEMM_SMEM_BYTES (2 * STAGE_FLOATS * 4)

__global__ __launch_bounds__(256, 1) void gemm_tf32(
    int M, int N, int K,
    const float* __restrict__ A, const float* __restrict__ B,
    const float* __restrict__ bias, float* __restrict__ C, int relu, int rnd)
{
    extern __shared__ float sm[];

    const int tid  = threadIdx.x;
    const int lane = tid & 31;
    const int warp = tid >> 5;
    const int wm = (warp >> 1) * 64;   // 0,64,128,192
    const int wn = (warp & 1) * 64;    // 0,64
    const int g = lane >> 2;
    const int t = lane & 3;
    const int cRow = blockIdx.y, cCol = blockIdx.x;

    const int aRow = tid >> 3;         // 0..31
    const int aCol = (tid & 7) * 4;    // 0..28
    const int bRow = tid >> 5;         // 0..7
    const int bCol = (tid & 31) * 4;   // 0..124

    const float* Ag = A + (size_t)(cRow * 256) * K;
    const float* Bg = B + cCol * 128;

    float acc[4][8][4];
    #pragma unroll
    for (int i = 0; i < 4; i++)
        #pragma unroll
        for (int j = 0; j < 8; j++)
            #pragma unroll
            for (int e = 0; e < 4; e++) acc[i][j][e] = 0.f;

    const int NT = K >> 5;

    {
        float* As = sm;
        float* Bs = sm + 256 * AS_STRIDE;
        #pragma unroll
        for (int r = 0; r < 8; r++)
            cp_async16(&As[(aRow + r * 32) * AS_STRIDE + aCol],
                       Ag + (size_t)(aRow + r * 32) * K + aCol);
        #pragma unroll
        for (int r = 0; r < 4; r++)
            cp_async16(&Bs[(bRow + r * 8) * BS_STRIDE + bCol],
                       Bg + (size_t)(bRow + r * 8) * N + bCol);
        CP_COMMIT();
    }

    for (int it = 0; it < NT; it++) {
        if (it + 1 < NT) {
            const int k0 = (it + 1) << 5;
            float* As = sm + ((it + 1) & 1) * STAGE_FLOATS;
            float* Bs = As + 256 * AS_STRIDE;
            #pragma unroll
            for (int r = 0; r < 8; r++)
                cp_async16(&As[(aRow + r * 32) * AS_STRIDE + aCol],
                           Ag + (size_t)(aRow + r * 32) * K + k0 + aCol);
            #pragma unroll
            for (int r = 0; r < 4; r++)
                cp_async16(&Bs[(bRow + r * 8) * BS_STRIDE + bCol],
                           Bg + (size_t)(k0 + bRow + r * 8) * N + bCol);
            CP_COMMIT();
            CP_WAIT(1);
        } else {
            CP_WAIT(0);
        }
        __syncthreads();

        const unsigned* Asu = (const unsigned*)(sm + (it & 1) * STAGE_FLOATS);
        const unsigned* Bsu = Asu + 256 * AS_STRIDE;

        #pragma unroll
        for (int k8 = 0; k8 < 4; k8++) {
            const int kb = k8 * 8;
            unsigned af[4][4], bf[8][2];
            #pragma unroll
            for (int tm = 0; tm < 4; tm++) {
                int r0 = (wm + tm * 16 + g) * AS_STRIDE;
                af[tm][0] = Asu[r0 + kb + t];
                af[tm][1] = Asu[r0 + 8 * AS_STRIDE + kb + t];
                af[tm][2] = Asu[r0 + kb + 4 + t];
                af[tm][3] = Asu[r0 + 8 * AS_STRIDE + kb + 4 + t];
            }
            #pragma unroll
            for (int tn = 0; tn < 8; tn++) {
                bf[tn][0] = Bsu[(kb + t) * BS_STRIDE + wn + tn * 8 + g];
                bf[tn][1] = Bsu[(kb + 4 + t) * BS_STRIDE + wn + tn * 8 + g];
            }
            #pragma unroll
            for (int tm = 0; tm < 4; tm++)
                #pragma unroll
                for (int tn = 0; tn < 8; tn++)
                    mma_tf32(acc[tm][tn], af[tm], bf[tn]);
        }
        __syncthreads();
    }

    #pragma unroll
    for (int tm = 0; tm < 4; tm++) {
        #pragma unroll
        for (int tn = 0; tn < 8; tn++) {
            int row = cRow * 256 + wm + tm * 16 + g;
            int col = cCol * 128 + wn + tn * 8 + 2 * t;
            float2 bb = *(const float2*)(bias + col);
            float2 v0 = make_float2(acc[tm][tn][0] + bb.x, acc[tm][tn][1] + bb.y);
            float2 v1 = make_float2(acc[tm][tn][2] + bb.x, acc[tm][tn][3] + bb.y);
            if (relu) {
                v0.x = fmaxf(v0.x, 0.f); v0.y = fmaxf(v0.y, 0.f);
                v1.x = fmaxf(v1.x, 0.f); v1.y = fmaxf(v1.y, 0.f);
            }
            if (rnd) {
                v0.x = rnd_tf32(v0.x); v0.y = rnd_tf32(v0.y);
                v1.x = rnd_tf32(v1.x); v1.y = rnd_tf32(v1.y);
            }
            *(float2*)(C + (size_t)row * N + col) = v0;
            *(float2*)(C + (size_t)(row + 8) * N + col) = v1;
        }
    }
}

// ---------------------------------------------------------------------------
// Flash attention on tensor cores (tf32 mma.sync m16n8k8).
// Inputs Q/K/V are already exact tf32 (rounded by producing GEMM epilogue),
// so raw-bit feeding == rna semantics. Output ctx is rounded to tf32.
// ---------------------------------------------------------------------------
#define QS_STRIDE 68
#define KS_STRIDE 68
#define VS_STRIDE 72
#define ATTN_SMEM_BYTES (64 * KS_STRIDE * 4 + 64 * VS_STRIDE * 4 + 256)

__global__ __launch_bounds__(256, 2) void attn3(
    const float* __restrict__ Q, const float* __restrict__ K,
    const float* __restrict__ V, const int* __restrict__ mask,
    float* __restrict__ O)
{
    extern __shared__ char smc[];
    float*    Qstage = (float*)smc;
    unsigned* Ks     = (unsigned*)smc;
    unsigned* Vs     = (unsigned*)(smc + 64 * KS_STRIDE * 4);
    float*    maskf  = (float*)(smc + 64 * KS_STRIDE * 4 + 64 * VS_STRIDE * 4);

    const int qt = blockIdx.x, h = blockIdx.y, b = blockIdx.z;
    const int tid  = threadIdx.x;
    const int lane = tid & 31;
    const int warp = tid >> 5;
    const int g = lane >> 2;
    const int t = lane & 3;
    const size_t hoff = (size_t)h * DK;
    const size_t qrow0 = (size_t)b * SEQ + qt * 128;

    #pragma unroll
    for (int it = 0; it < 8; it++) {
        int idx = tid + it * 256;
        int r = idx >> 4;
        int c4 = (idx & 15) << 2;
        float4 v = *(const float4*)(Q + (qrow0 + r) * DMODEL + hoff + c4);
        v.x *= 0.125f; v.y *= 0.125f; v.z *= 0.125f; v.w *= 0.125f;
        *(float4*)&Qstage[r * QS_STRIDE + c4] = v;
    }
    __syncthreads();

    unsigned qf[8][4];
    {
        const int r0 = warp * 16;
        #pragma unroll
        for (int kk = 0; kk < 8; kk++) {
            qf[kk][0] = cvt_tf32(Qstage[(r0 + g)     * QS_STRIDE + kk * 8 + t]);
            qf[kk][1] = cvt_tf32(Qstage[(r0 + 8 + g) * QS_STRIDE + kk * 8 + t]);
            qf[kk][2] = cvt_tf32(Qstage[(r0 + g)     * QS_STRIDE + kk * 8 + 4 + t]);
            qf[kk][3] = cvt_tf32(Qstage[(r0 + 8 + g) * QS_STRIDE + kk * 8 + 4 + t]);
        }
    }
    __syncthreads();

    float m0 = -INFINITY, m1 = -INFINITY, l0 = 0.f, l1 = 0.f;
    float oacc[8][4];
    #pragma unroll
    for (int j = 0; j < 8; j++)
        #pragma unroll
        for (int e = 0; e < 4; e++) oacc[j][e] = 0.f;

    for (int kt = 0; kt < 32; kt++) {
        const size_t kvbase = ((size_t)b * SEQ + kt * 64) * DMODEL + hoff;

        #pragma unroll
        for (int it = 0; it < 4; it++) {
            int idx = tid + it * 256;
            int r = idx >> 4;
            int c4 = (idx & 15) << 2;
            *(uint4*)&Ks[r * KS_STRIDE + c4] =
                *(const uint4*)(K + kvbase + (size_t)r * DMODEL + c4);
            *(uint4*)&Vs[r * VS_STRIDE + c4] =
                *(const uint4*)(V + kvbase + (size_t)r * DMODEL + c4);
        }
        if (tid < 64)
            maskf[tid] = (mask[(size_t)b * SEQ + kt * 64 + tid] == 0) ? -INFINITY : 0.f;
        __syncthreads();

        float sacc[8][4];
        #pragma unroll
        for (int j = 0; j < 8; j++)
            #pragma unroll
            for (int e = 0; e < 4; e++) sacc[j][e] = 0.f;

        #pragma unroll
        for (int kk = 0; kk < 8; kk++) {
            #pragma unroll
            for (int nj = 0; nj < 8; nj++) {
                unsigned bf[2];
                bf[0] = Ks[(nj * 8 + g) * KS_STRIDE + kk * 8 + t];
                bf[1] = Ks[(nj * 8 + g) * KS_STRIDE + kk * 8 + 4 + t];
                mma_tf32(sacc[nj], qf[kk], bf);
            }
        }

        #pragma unroll
        for (int nj = 0; nj < 8; nj++) {
            float mk0 = maskf[nj * 8 + 2 * t];
            float mk1 = maskf[nj * 8 + 2 * t + 1];
            sacc[nj][0] += mk0; sacc[nj][1] += mk1;
            sacc[nj][2] += mk0; sacc[nj][3] += mk1;
        }

        {
            float mx0 = -INFINITY, mx1 = -INFINITY;
            #pragma unroll
            for (int nj = 0; nj < 8; nj++) {
                mx0 = fmaxf(mx0, fmaxf(sacc[nj][0], sacc[nj][1]));
                mx1 = fmaxf(mx1, fmaxf(sacc[nj][2], sacc[nj][3]));
            }
            mx0 = fmaxf(mx0, __shfl_xor_sync(0xffffffffu, mx0, 1));
            mx0 = fmaxf(mx0, __shfl_xor_sync(0xffffffffu, mx0, 2));
            mx1 = fmaxf(mx1, __shfl_xor_sync(0xffffffffu, mx1, 1));
            mx1 = fmaxf(mx1, __shfl_xor_sync(0xffffffffu, mx1, 2));
            float mn0 = fmaxf(m0, mx0), mn1 = fmaxf(m1, mx1);
            float corr0 = __expf(m0 - mn0), corr1 = __expf(m1 - mn1);

            float rs0 = 0.f, rs1 = 0.f;
            #pragma unroll
            for (int nj = 0; nj < 8; nj++) {
                sacc[nj][0] = __expf(sacc[nj][0] - mn0);
                sacc[nj][1] = __expf(sacc[nj][1] - mn0);
                sacc[nj][2] = __expf(sacc[nj][2] - mn1);
                sacc[nj][3] = __expf(sacc[nj][3] - mn1);
                rs0 += sacc[nj][0] + sacc[nj][1];
                rs1 += sacc[nj][2] + sacc[nj][3];
            }
            rs0 += __shfl_xor_sync(0xffffffffu, rs0, 1);
            rs0 += __shfl_xor_sync(0xffffffffu, rs0, 2);
            rs1 += __shfl_xor_sync(0xffffffffu, rs1, 1);
            rs1 += __shfl_xor_sync(0xffffffffu, rs1, 2);
            l0 = l0 * corr0 + rs0;  m0 = mn0;
            l1 = l1 * corr1 + rs1;  m1 = mn1;
            #pragma unroll
            for (int j = 0; j < 8; j++) {
                oacc[j][0] *= corr0; oacc[j][1] *= corr0;
                oacc[j][2] *= corr1; oacc[j][3] *= corr1;
            }
        }

        {
            const int src_lo = (lane & ~3) | (t >> 1);
            const int src_hi = src_lo + 2;
            const bool odd = (t & 1);
            #pragma unroll
            for (int j = 0; j < 8; j++) {
                float c0a = __shfl_sync(0xffffffffu, sacc[j][0], src_lo);
                float c1a = __shfl_sync(0xffffffffu, sacc[j][1], src_lo);
                float c0b = __shfl_sync(0xffffffffu, sacc[j][0], src_hi);
                float c1b = __shfl_sync(0xffffffffu, sacc[j][1], src_hi);
                float c2a = __shfl_sync(0xffffffffu, sacc[j][2], src_lo);
                float c3a = __shfl_sync(0xffffffffu, sacc[j][3], src_lo);
                float c2b = __shfl_sync(0xffffffffu, sacc[j][2], src_hi);
                float c3b = __shfl_sync(0xffffffffu, sacc[j][3], src_hi);
                unsigned af[4];
                af[0] = __float_as_uint(odd ? c1a : c0a);
                af[1] = __float_as_uint(odd ? c3a : c2a);
                af[2] = __float_as_uint(odd ? c1b : c0b);
                af[3] = __float_as_uint(odd ? c3b : c2b);
                #pragma unroll
                for (int jj = 0; jj < 8; jj++) {
                    unsigned bf[2];
                    bf[0] = Vs[(j * 8 + t)     * VS_STRIDE + jj * 8 + g];
                    bf[1] = Vs[(j * 8 + t + 4) * VS_STRIDE + jj * 8 + g];
                    mma_tf32(oacc[jj], af, bf);
                }
            }
        }
        __syncthreads();
    }

    {
        const float inv0 = 1.f / l0, inv1 = 1.f / l1;
        const size_t r0 = qrow0 + warp * 16 + g;
        #pragma unroll
        for (int jj = 0; jj < 8; jj++) {
            int col = jj * 8 + 2 * t;
            *(float2*)(O + r0 * DMODEL + hoff + col) =
                make_float2(rnd_tf32(oacc[jj][0] * inv0), rnd_tf32(oacc[jj][1] * inv0));
            *(float2*)(O + (r0 + 8) * DMODEL + hoff + col) =
                make_float2(rnd_tf32(oacc[jj][2] * inv1), rnd_tf32(oacc[jj][3] * inv1));
        }
    }
}

// ---------------------------------------------------------------------------
// out[row] = LayerNorm(a[row] + b[row]) * gamma + beta.
// Optionally also writes a tf32-rounded copy (out_r) for downstream GEMMs.
// ---------------------------------------------------------------------------
__global__ __launch_bounds__(256) void add_ln_kernel(
    const float* __restrict__ a, const float* __restrict__ bsrc,
    const float* __restrict__ g, const float* __restrict__ be,
    float* __restrict__ out, float* __restrict__ out_r)
{
    const int row = blockIdx.x;
    const int tid = threadIdx.x;
    const float* pa = a + (size_t)row * DMODEL;
    const float* pb = bsrc + (size_t)row * DMODEL;

    float v[4];
    float sum = 0.f, sq = 0.f;
    #pragma unroll
    for (int i = 0; i < 4; i++) {
        int c = tid + i * 256;
        float x = pa[c] + pb[c];
        v[i] = x;
        sum += x;
        sq += x * x;
    }
    #pragma unroll
    for (int o = 16; o > 0; o >>= 1) {
        sum += __shfl_xor_sync(0xffffffffu, sum, o);
        sq  += __shfl_xor_sync(0xffffffffu, sq,  o);
    }
    __shared__ float ssum[8], ssq[8];
    if ((tid & 31) == 0) { ssum[tid >> 5] = sum; ssq[tid >> 5] = sq; }
    __syncthreads();
    if (tid < 32) {
        float s2 = (tid < 8) ? ssum[tid] : 0.f;
        float q2 = (tid < 8) ? ssq[tid] : 0.f;
        #pragma unroll
        for (int o = 4; o > 0; o >>= 1) {
            s2 += __shfl_xor_sync(0xffffffffu, s2, o);
            q2 += __shfl_xor_sync(0xffffffffu, q2, o);
        }
        if (tid == 0) { ssum[0] = s2; ssq[0] = q2; }
    }
    __syncthreads();
    const float mu   = ssum[0] * (1.f / DMODEL);
    const float var  = ssq[0] * (1.f / DMODEL) - mu * mu;
    const float rstd = rsqrtf(var + 1e-5f);

    float* po = out + (size_t)row * DMODEL;
    float* pr = out_r ? out_r + (size_t)row * DMODEL : nullptr;
    #pragma unroll
    for (int i = 0; i < 4; i++) {
        int c = tid + i * 256;
        float y = (v[i] - mu) * rstd * g[c] + be[c];
        po[c] = y;
        if (pr) pr[c] = rnd_tf32(y);
    }
}

// ---------------------------------------------------------------------------
// Launch
// ---------------------------------------------------------------------------
extern "C" void kernel_launch(void* const* d_in, const int* in_sizes, int n_in,
                              void* d_out, int out_size)
{
    (void)in_sizes; (void)n_in; (void)out_size;
    const float* x    = (const float*)d_in[0];
    const int*   mask = (const int*)  d_in[1];
    const float* w_q  = (const float*)d_in[2];
    const float* b_q  = (const float*)d_in[3];
    const float* w_k  = (const float*)d_in[4];
    const float* b_k  = (const float*)d_in[5];
    const float* w_v  = (const float*)d_in[6];
    const float* b_v  = (const float*)d_in[7];
    const float* w_o  = (const float*)d_in[8];
    const float* b_o  = (const float*)d_in[9];
    const float* w1   = (const float*)d_in[10];
    const float* b1   = (const float*)d_in[11];
    const float* w2   = (const float*)d_in[12];
    const float* b2   = (const float*)d_in[13];
    const float* g1   = (const float*)d_in[14];
    const float* be1  = (const float*)d_in[15];
    const float* g2   = (const float*)d_in[16];
    const float* be2  = (const float*)d_in[17];

    float *q, *k, *v, *ctx, *t1, *h, *hr, *ff;
    float *xr, *wqr, *wkr, *wvr, *wor, *w1r, *w2r;
    cudaGetSymbolAddress((void**)&q,   g_q);
    cudaGetSymbolAddress((void**)&k,   g_k);
    cudaGetSymbolAddress((void**)&v,   g_v);
    cudaGetSymbolAddress((void**)&ctx, g_ctx);
    cudaGetSymbolAddress((void**)&t1,  g_t1);
    cudaGetSymbolAddress((void**)&h,   g_h);
    cudaGetSymbolAddress((void**)&hr,  g_hr);
    cudaGetSymbolAddress((void**)&ff,  g_ff);
    cudaGetSymbolAddress((void**)&xr,  g_xr);
    cudaGetSymbolAddress((void**)&wqr, g_wqr);
    cudaGetSymbolAddress((void**)&wkr, g_wkr);
    cudaGetSymbolAddress((void**)&wvr, g_wvr);
    cudaGetSymbolAddress((void**)&wor, g_wor);
    cudaGetSymbolAddress((void**)&w1r, g_w1r);
    cudaGetSymbolAddress((void**)&w2r, g_w2r);

    cudaFuncSetAttribute(gemm_tf32, cudaFuncAttributeMaxDynamicSharedMemorySize,
                         GEMM_SMEM_BYTES);
    cudaFuncSetAttribute(attn3, cudaFuncAttributeMaxDynamicSharedMemorySize,
                         ATTN_SMEM_BYTES);

    // ---- pre-round GEMM inputs to tf32 (rna) ----
    {
        const int TB = 256;
        int n;
        n = MROWS * DMODEL / 4;  round_tf32_kernel<<<(n + TB - 1) / TB, TB>>>(x,   xr,  n);
        n = DMODEL * DMODEL / 4; round_tf32_kernel<<<(n + TB - 1) / TB, TB>>>(w_q, wqr, n);
        n = DMODEL * DMODEL / 4; round_tf32_kernel<<<(n + TB - 1) / TB, TB>>>(w_k, wkr, n);
        n = DMODEL * DMODEL / 4; round_tf32_kernel<<<(n + TB - 1) / TB, TB>>>(w_v, wvr, n);
        n = DMODEL * DMODEL / 4; round_tf32_kernel<<<(n + TB - 1) / TB, TB>>>(w_o, wor, n);
        n = DMODEL * DFF / 4;    round_tf32_kernel<<<(n + TB - 1) / TB, TB>>>(w1,  w1r, n);
        n = DFF * DMODEL / 4;    round_tf32_kernel<<<(n + TB - 1) / TB, TB>>>(w2,  w2r, n);
    }

    dim3 blk(256);
    dim3 gProj(DMODEL / 128, MROWS / 256);   // (8, 32)
    dim3 gFF1(DFF / 128, MROWS / 256);       // (32, 32)
    dim3 gAtt(SEQ / 128, NHEADS, BATCH);     // (16, 16, 4)

    // QKV projections: outputs rounded to tf32 (consumed by attn mma)
    gemm_tf32<<<gProj, blk, GEMM_SMEM_BYTES>>>(MROWS, DMODEL, DMODEL, xr, wqr, b_q, q, 0, 1);
    gemm_tf32<<<gProj, blk, GEMM_SMEM_BYTES>>>(MROWS, DMODEL, DMODEL, xr, wkr, b_k, k, 0, 1);
    gemm_tf32<<<gProj, blk, GEMM_SMEM_BYTES>>>(MROWS, DMODEL, DMODEL, xr, wvr, b_v, v, 0, 1);

    attn3<<<gAtt, blk, ATTN_SMEM_BYTES>>>(q, k, v, mask, ctx);  // ctx rounded

    gemm_tf32<<<gProj, blk, GEMM_SMEM_BYTES>>>(MROWS, DMODEL, DMODEL, ctx, wor, b_o, t1, 0, 0);
    add_ln_kernel<<<MROWS, 256>>>(x, t1, g1, be1, h, hr);

    gemm_tf32<<<gFF1, blk, GEMM_SMEM_BYTES>>>(MROWS, DFF, DMODEL, hr, w1r, b1, ff, 1, 1);
    gemm_tf32<<<gProj, blk, GEMM_SMEM_BYTES>>>(MROWS, DMODEL, DFF, ff, w2r, b2, t1, 0, 0);
    add_ln_kernel<<<MROWS, 256>>>(h, t1, g2, be2, (float*)d_out, nullptr);
}

// round 12
// speedup vs baseline: 1.5641x; 1.0294x over previous
#include <cuda_runtime.h>
#include <math.h>

// ---------------------------------------------------------------------------
// Problem constants
// ---------------------------------------------------------------------------
#define BATCH 4
#define SEQ   2048
#define DMODEL 1024
#define NHEADS 16
#define DK    64
#define DFF   4096
#define MROWS (BATCH * SEQ)   // 8192

// ---------------------------------------------------------------------------
// Scratch (no cudaMalloc allowed)
// ---------------------------------------------------------------------------
__device__ float g_q  [MROWS * DMODEL];
__device__ float g_k  [MROWS * DMODEL];
__device__ float g_v  [MROWS * DMODEL];
__device__ float g_ctx[MROWS * DMODEL];
__device__ float g_t1 [MROWS * DMODEL];
__device__ float g_h  [MROWS * DMODEL];
__device__ float g_hr [MROWS * DMODEL];
__device__ float g_ff [MROWS * DFF];
__device__ float g_xr [MROWS * DMODEL];
__device__ float g_wqr[DMODEL * DMODEL];
__device__ float g_wkr[DMODEL * DMODEL];
__device__ float g_wvr[DMODEL * DMODEL];
__device__ float g_wor[DMODEL * DMODEL];
__device__ float g_w1r[DMODEL * DFF];
__device__ float g_w2r[DFF * DMODEL];

// ---------------------------------------------------------------------------
// Helpers
// ---------------------------------------------------------------------------
__device__ __forceinline__ unsigned cvt_tf32(float x) {
    unsigned r;
    asm("cvt.rna.tf32.f32 %0, %1;" : "=r"(r) : "f"(x));
    return r;
}
__device__ __forceinline__ float rnd_tf32(float x) {
    return __uint_as_float(cvt_tf32(x));
}

__device__ __forceinline__ void mma_tf32(float* c, const unsigned* a, const unsigned* b) {
    asm volatile(
        "mma.sync.aligned.m16n8k8.row.col.f32.tf32.tf32.f32 "
        "{%0,%1,%2,%3}, {%4,%5,%6,%7}, {%8,%9}, {%0,%1,%2,%3};"
        : "+f"(c[0]), "+f"(c[1]), "+f"(c[2]), "+f"(c[3])
        : "r"(a[0]), "r"(a[1]), "r"(a[2]), "r"(a[3]), "r"(b[0]), "r"(b[1]));
}

__device__ __forceinline__ void cp_async16(void* smem_dst, const void* gmem_src) {
    unsigned saddr = (unsigned)__cvta_generic_to_shared(smem_dst);
    asm volatile("cp.async.cg.shared.global [%0], [%1], 16;"
                 :: "r"(saddr), "l"(gmem_src));
}
#define CP_COMMIT() asm volatile("cp.async.commit_group;")
#define CP_WAIT(n)  asm volatile("cp.async.wait_group %0;" :: "n"(n))

// ---------------------------------------------------------------------------
// Elementwise tf32 (rna) rounding: dst[i] = round_tf32(src[i])
// ---------------------------------------------------------------------------
__global__ __launch_bounds__(256) void round_tf32_kernel(
    const float* __restrict__ src, float* __restrict__ dst, int n4)
{
    int i = blockIdx.x * 256 + threadIdx.x;
    if (i < n4) {
        float4 v = ((const float4*)src)[i];
        v.x = rnd_tf32(v.x); v.y = rnd_tf32(v.y);
        v.z = rnd_tf32(v.z); v.w = rnd_tf32(v.w);
        ((float4*)dst)[i] = v;
    }
}

// ---------------------------------------------------------------------------
// TF32 tensor-core GEMM, 3-stage cp.async pipeline, one barrier per K-step.
// C[M,N] = A[M,K] @ B[K,N] + bias[N] (optional ReLU, optional tf32-round out)
// BM=128, BN=128, BK=32. 128 threads = 4 warps (2x2), warp tile 64x64.
// Two CTAs co-resident per SM so barrier/wait bubbles overlap.
// Inputs are assumed pre-rounded to tf32 (raw bits fed to mma).
// ---------------------------------------------------------------------------
#define AS_STRIDE 36
#define BS_STRIDE 132
#define STAGE_FLOATS (128 * AS_STRIDE + 32 * BS_STRIDE)   // 8832
#define GEMM_SMEM_BYTES (3 * STAGE_FLOATS * 4)            // 105984

__global__ __launch_bounds__(128, 2) void gemm_tf32(
    int M, int N, int K,
    const float* __restrict__ A, const float* __restrict__ B,
    const float* __restrict__ bias, float* __restrict__ C, int relu, int rnd)
{
    extern __shared__ float sm[];

    const int tid  = threadIdx.x;
    const int lane = tid & 31;
    const int warp = tid >> 5;
    const int wm = (warp >> 1) * 64;   // 0,64
    const int wn = (warp & 1) * 64;    // 0,64
    const int g = lane >> 2;
    const int t = lane & 3;
    const int cRow = blockIdx.y, cCol = blockIdx.x;

    const int aRow = tid >> 3;         // 0..15
    const int aCol = (tid & 7) * 4;    // 0..28
    const int bRow = tid >> 5;         // 0..3
    const int bCol = (tid & 31) * 4;   // 0..124

    const float* Ag = A + (size_t)(cRow * 128) * K;
    const float* Bg = B + cCol * 128;

    float acc[4][8][4];
    #pragma unroll
    for (int i = 0; i < 4; i++)
        #pragma unroll
        for (int j = 0; j < 8; j++)
            #pragma unroll
            for (int e = 0; e < 4; e++) acc[i][j][e] = 0.f;

    const int NT = K >> 5;

    // ---- prologue: issue stages 0 and 1 ----
    #pragma unroll
    for (int s = 0; s < 2; s++) {
        float* As = sm + s * STAGE_FLOATS;
        float* Bs = As + 128 * AS_STRIDE;
        const int k0 = s << 5;
        #pragma unroll
        for (int r = 0; r < 8; r++)
            cp_async16(&As[(aRow + r * 16) * AS_STRIDE + aCol],
                       Ag + (size_t)(aRow + r * 16) * K + k0 + aCol);
        #pragma unroll
        for (int r = 0; r < 8; r++)
            cp_async16(&Bs[(bRow + r * 4) * BS_STRIDE + bCol],
                       Bg + (size_t)(k0 + bRow + r * 4) * N + bCol);
        CP_COMMIT();
    }

    int buf = 0;
    for (int it = 0; it < NT; it++) {
        if (it < NT - 1) { CP_WAIT(1); } else { CP_WAIT(0); }
        __syncthreads();   // stage `it` visible to all; stage it-1 fully consumed

        // prefetch stage it+2 into buffer (it+2)%3 (== buffer of stage it-1)
        if (it + 2 < NT) {
            const int k0 = (it + 2) << 5;
            int wbuf = buf + 2; if (wbuf >= 3) wbuf -= 3;
            float* As = sm + wbuf * STAGE_FLOATS;
            float* Bs = As + 128 * AS_STRIDE;
            #pragma unroll
            for (int r = 0; r < 8; r++)
                cp_async16(&As[(aRow + r * 16) * AS_STRIDE + aCol],
                           Ag + (size_t)(aRow + r * 16) * K + k0 + aCol);
            #pragma unroll
            for (int r = 0; r < 8; r++)
                cp_async16(&Bs[(bRow + r * 4) * BS_STRIDE + bCol],
                           Bg + (size_t)(k0 + bRow + r * 4) * N + bCol);
            CP_COMMIT();
        }

        const unsigned* Asu = (const unsigned*)(sm + buf * STAGE_FLOATS);
        const unsigned* Bsu = Asu + 128 * AS_STRIDE;

        #pragma unroll
        for (int k8 = 0; k8 < 4; k8++) {
            const int kb = k8 * 8;
            unsigned af[4][4], bf[8][2];
            #pragma unroll
            for (int tm = 0; tm < 4; tm++) {
                int r0 = (wm + tm * 16 + g) * AS_STRIDE;
                af[tm][0] = Asu[r0 + kb + t];
                af[tm][1] = Asu[r0 + 8 * AS_STRIDE + kb + t];
                af[tm][2] = Asu[r0 + kb + 4 + t];
                af[tm][3] = Asu[r0 + 8 * AS_STRIDE + kb + 4 + t];
            }
            #pragma unroll
            for (int tn = 0; tn < 8; tn++) {
                bf[tn][0] = Bsu[(kb + t) * BS_STRIDE + wn + tn * 8 + g];
                bf[tn][1] = Bsu[(kb + 4 + t) * BS_STRIDE + wn + tn * 8 + g];
            }
            #pragma unroll
            for (int tm = 0; tm < 4; tm++)
                #pragma unroll
                for (int tn = 0; tn < 8; tn++)
                    mma_tf32(acc[tm][tn], af[tm], bf[tn]);
        }

        if (++buf == 3) buf = 0;
    }

    #pragma unroll
    for (int tm = 0; tm < 4; tm++) {
        #pragma unroll
        for (int tn = 0; tn < 8; tn++) {
            int row = cRow * 128 + wm + tm * 16 + g;
            int col = cCol * 128 + wn + tn * 8 + 2 * t;
            float2 bb = *(const float2*)(bias + col);
            float2 v0 = make_float2(acc[tm][tn][0] + bb.x, acc[tm][tn][1] + bb.y);
            float2 v1 = make_float2(acc[tm][tn][2] + bb.x, acc[tm][tn][3] + bb.y);
            if (relu) {
                v0.x = fmaxf(v0.x, 0.f); v0.y = fmaxf(v0.y, 0.f);
                v1.x = fmaxf(v1.x, 0.f); v1.y = fmaxf(v1.y, 0.f);
            }
            if (rnd) {
                v0.x = rnd_tf32(v0.x); v0.y = rnd_tf32(v0.y);
                v1.x = rnd_tf32(v1.x); v1.y = rnd_tf32(v1.y);
            }
            *(float2*)(C + (size_t)row * N + col) = v0;
            *(float2*)(C + (size_t)(row + 8) * N + col) = v1;
        }
    }
}

// ---------------------------------------------------------------------------
// Flash attention on tensor cores (tf32 mma.sync m16n8k8).
// Inputs Q/K/V are already exact tf32 (rounded by producing GEMM epilogue),
// so raw-bit feeding == rna semantics. Output ctx is rounded to tf32.
// ---------------------------------------------------------------------------
#define QS_STRIDE 68
#define KS_STRIDE 68
#define VS_STRIDE 72
#define ATTN_SMEM_BYTES (64 * KS_STRIDE * 4 + 64 * VS_STRIDE * 4 + 256)

__global__ __launch_bounds__(256, 2) void attn3(
    const float* __restrict__ Q, const float* __restrict__ K,
    const float* __restrict__ V, const int* __restrict__ mask,
    float* __restrict__ O)
{
    extern __shared__ char smc[];
    float*    Qstage = (float*)smc;
    unsigned* Ks     = (unsigned*)smc;
    unsigned* Vs     = (unsigned*)(smc + 64 * KS_STRIDE * 4);
    float*    maskf  = (float*)(smc + 64 * KS_STRIDE * 4 + 64 * VS_STRIDE * 4);

    const int qt = blockIdx.x, h = blockIdx.y, b = blockIdx.z;
    const int tid  = threadIdx.x;
    const int lane = tid & 31;
    const int warp = tid >> 5;
    const int g = lane >> 2;
    const int t = lane & 3;
    const size_t hoff = (size_t)h * DK;
    const size_t qrow0 = (size_t)b * SEQ + qt * 128;

    #pragma unroll
    for (int it = 0; it < 8; it++) {
        int idx = tid + it * 256;
        int r = idx >> 4;
        int c4 = (idx & 15) << 2;
        float4 v = *(const float4*)(Q + (qrow0 + r) * DMODEL + hoff + c4);
        v.x *= 0.125f; v.y *= 0.125f; v.z *= 0.125f; v.w *= 0.125f;
        *(float4*)&Qstage[r * QS_STRIDE + c4] = v;
    }
    __syncthreads();

    unsigned qf[8][4];
    {
        const int r0 = warp * 16;
        #pragma unroll
        for (int kk = 0; kk < 8; kk++) {
            qf[kk][0] = cvt_tf32(Qstage[(r0 + g)     * QS_STRIDE + kk * 8 + t]);
            qf[kk][1] = cvt_tf32(Qstage[(r0 + 8 + g) * QS_STRIDE + kk * 8 + t]);
            qf[kk][2] = cvt_tf32(Qstage[(r0 + g)     * QS_STRIDE + kk * 8 + 4 + t]);
            qf[kk][3] = cvt_tf32(Qstage[(r0 + 8 + g) * QS_STRIDE + kk * 8 + 4 + t]);
        }
    }
    __syncthreads();

    float m0 = -INFINITY, m1 = -INFINITY, l0 = 0.f, l1 = 0.f;
    float oacc[8][4];
    #pragma unroll
    for (int j = 0; j < 8; j++)
        #pragma unroll
        for (int e = 0; e < 4; e++) oacc[j][e] = 0.f;

    for (int kt = 0; kt < 32; kt++) {
        const size_t kvbase = ((size_t)b * SEQ + kt * 64) * DMODEL + hoff;

        #pragma unroll
        for (int it = 0; it < 4; it++) {
            int idx = tid + it * 256;
            int r = idx >> 4;
            int c4 = (idx & 15) << 2;
            *(uint4*)&Ks[r * KS_STRIDE + c4] =
                *(const uint4*)(K + kvbase + (size_t)r * DMODEL + c4);
            *(uint4*)&Vs[r * VS_STRIDE + c4] =
                *(const uint4*)(V + kvbase + (size_t)r * DMODEL + c4);
        }
        if (tid < 64)
            maskf[tid] = (mask[(size_t)b * SEQ + kt * 64 + tid] == 0) ? -INFINITY : 0.f;
        __syncthreads();

        float sacc[8][4];
        #pragma unroll
        for (int j = 0; j < 8; j++)
            #pragma unroll
            for (int e = 0; e < 4; e++) sacc[j][e] = 0.f;

        #pragma unroll
        for (int kk = 0; kk < 8; kk++) {
            #pragma unroll
            for (int nj = 0; nj < 8; nj++) {
                unsigned bf[2];
                bf[0] = Ks[(nj * 8 + g) * KS_STRIDE + kk * 8 + t];
                bf[1] = Ks[(nj * 8 + g) * KS_STRIDE + kk * 8 + 4 + t];
                mma_tf32(sacc[nj], qf[kk], bf);
            }
        }

        #pragma unroll
        for (int nj = 0; nj < 8; nj++) {
            float mk0 = maskf[nj * 8 + 2 * t];
            float mk1 = maskf[nj * 8 + 2 * t + 1];
            sacc[nj][0] += mk0; sacc[nj][1] += mk1;
            sacc[nj][2] += mk0; sacc[nj][3] += mk1;
        }

        {
            float mx0 = -INFINITY, mx1 = -INFINITY;
            #pragma unroll
            for (int nj = 0; nj < 8; nj++) {
                mx0 = fmaxf(mx0, fmaxf(sacc[nj][0], sacc[nj][1]));
                mx1 = fmaxf(mx1, fmaxf(sacc[nj][2], sacc[nj][3]));
            }
            mx0 = fmaxf(mx0, __shfl_xor_sync(0xffffffffu, mx0, 1));
            mx0 = fmaxf(mx0, __shfl_xor_sync(0xffffffffu, mx0, 2));
            mx1 = fmaxf(mx1, __shfl_xor_sync(0xffffffffu, mx1, 1));
            mx1 = fmaxf(mx1, __shfl_xor_sync(0xffffffffu, mx1, 2));
            float mn0 = fmaxf(m0, mx0), mn1 = fmaxf(m1, mx1);
            float corr0 = __expf(m0 - mn0), corr1 = __expf(m1 - mn1);

            float rs0 = 0.f, rs1 = 0.f;
            #pragma unroll
            for (int nj = 0; nj < 8; nj++) {
                sacc[nj][0] = __expf(sacc[nj][0] - mn0);
                sacc[nj][1] = __expf(sacc[nj][1] - mn0);
                sacc[nj][2] = __expf(sacc[nj][2] - mn1);
                sacc[nj][3] = __expf(sacc[nj][3] - mn1);
                rs0 += sacc[nj][0] + sacc[nj][1];
                rs1 += sacc[nj][2] + sacc[nj][3];
            }
            rs0 += __shfl_xor_sync(0xffffffffu, rs0, 1);
            rs0 += __shfl_xor_sync(0xffffffffu, rs0, 2);
            rs1 += __shfl_xor_sync(0xffffffffu, rs1, 1);
            rs1 += __shfl_xor_sync(0xffffffffu, rs1, 2);
            l0 = l0 * corr0 + rs0;  m0 = mn0;
            l1 = l1 * corr1 + rs1;  m1 = mn1;
            #pragma unroll
            for (int j = 0; j < 8; j++) {
                oacc[j][0] *= corr0; oacc[j][1] *= corr0;
                oacc[j][2] *= corr1; oacc[j][3] *= corr1;
            }
        }

        {
            const int src_lo = (lane & ~3) | (t >> 1);
            const int src_hi = src_lo + 2;
            const bool odd = (t & 1);
            #pragma unroll
            for (int j = 0; j < 8; j++) {
                float c0a = __shfl_sync(0xffffffffu, sacc[j][0], src_lo);
                float c1a = __shfl_sync(0xffffffffu, sacc[j][1], src_lo);
                float c0b = __shfl_sync(0xffffffffu, sacc[j][0], src_hi);
                float c1b = __shfl_sync(0xffffffffu, sacc[j][1], src_hi);
                float c2a = __shfl_sync(0xffffffffu, sacc[j][2], src_lo);
                float c3a = __shfl_sync(0xffffffffu, sacc[j][3], src_lo);
                float c2b = __shfl_sync(0xffffffffu, sacc[j][2], src_hi);
                float c3b = __shfl_sync(0xffffffffu, sacc[j][3], src_hi);
                unsigned af[4];
                af[0] = __float_as_uint(odd ? c1a : c0a);
                af[1] = __float_as_uint(odd ? c3a : c2a);
                af[2] = __float_as_uint(odd ? c1b : c0b);
                af[3] = __float_as_uint(odd ? c3b : c2b);
                #pragma unroll
                for (int jj = 0; jj < 8; jj++) {
                    unsigned bf[2];
                    bf[0] = Vs[(j * 8 + t)     * VS_STRIDE + jj * 8 + g];
                    bf[1] = Vs[(j * 8 + t + 4) * VS_STRIDE + jj * 8 + g];
                    mma_tf32(oacc[jj], af, bf);
                }
            }
        }
        __syncthreads();
    }

    {
        const float inv0 = 1.f / l0, inv1 = 1.f / l1;
        const size_t r0 = qrow0 + warp * 16 + g;
        #pragma unroll
        for (int jj = 0; jj < 8; jj++) {
            int col = jj * 8 + 2 * t;
            *(float2*)(O + r0 * DMODEL + hoff + col) =
                make_float2(rnd_tf32(oacc[jj][0] * inv0), rnd_tf32(oacc[jj][1] * inv0));
            *(float2*)(O + (r0 + 8) * DMODEL + hoff + col) =
                make_float2(rnd_tf32(oacc[jj][2] * inv1), rnd_tf32(oacc[jj][3] * inv1));
        }
    }
}

// ---------------------------------------------------------------------------
// out[row] = LayerNorm(a[row] + b[row]) * gamma + beta.
// Optionally also writes a tf32-rounded copy (out_r) for downstream GEMMs.
// ---------------------------------------------------------------------------
__global__ __launch_bounds__(256) void add_ln_kernel(
    const float* __restrict__ a, const float* __restrict__ bsrc,
    const float* __restrict__ g, const float* __restrict__ be,
    float* __restrict__ out, float* __restrict__ out_r)
{
    const int row = blockIdx.x;
    const int tid = threadIdx.x;
    const float* pa = a + (size_t)row * DMODEL;
    const float* pb = bsrc + (size_t)row * DMODEL;

    float v[4];
    float sum = 0.f, sq = 0.f;
    #pragma unroll
    for (int i = 0; i < 4; i++) {
        int c = tid + i * 256;
        float x = pa[c] + pb[c];
        v[i] = x;
        sum += x;
        sq += x * x;
    }
    #pragma unroll
    for (int o = 16; o > 0; o >>= 1) {
        sum += __shfl_xor_sync(0xffffffffu, sum, o);
        sq  += __shfl_xor_sync(0xffffffffu, sq,  o);
    }
    __shared__ float ssum[8], ssq[8];
    if ((tid & 31) == 0) { ssum[tid >> 5] = sum; ssq[tid >> 5] = sq; }
    __syncthreads();
    if (tid < 32) {
        float s2 = (tid < 8) ? ssum[tid] : 0.f;
        float q2 = (tid < 8) ? ssq[tid] : 0.f;
        #pragma unroll
        for (int o = 4; o > 0; o >>= 1) {
            s2 += __shfl_xor_sync(0xffffffffu, s2, o);
            q2 += __shfl_xor_sync(0xffffffffu, q2, o);
        }
        if (tid == 0) { ssum[0] = s2; ssq[0] = q2; }
    }
    __syncthreads();
    const float mu   = ssum[0] * (1.f / DMODEL);
    const float var  = ssq[0] * (1.f / DMODEL) - mu * mu;
    const float rstd = rsqrtf(var + 1e-5f);

    float* po = out + (size_t)row * DMODEL;
    float* pr = out_r ? out_r + (size_t)row * DMODEL : nullptr;
    #pragma unroll
    for (int i = 0; i < 4; i++) {
        int c = tid + i * 256;
        float y = (v[i] - mu) * rstd * g[c] + be[c];
        po[c] = y;
        if (pr) pr[c] = rnd_tf32(y);
    }
}

// ---------------------------------------------------------------------------
// Launch
// ---------------------------------------------------------------------------
extern "C" void kernel_launch(void* const* d_in, const int* in_sizes, int n_in,
                              void* d_out, int out_size)
{
    (void)in_sizes; (void)n_in; (void)out_size;
    const float* x    = (const float*)d_in[0];
    const int*   mask = (const int*)  d_in[1];
    const float* w_q  = (const float*)d_in[2];
    const float* b_q  = (const float*)d_in[3];
    const float* w_k  = (const float*)d_in[4];
    const float* b_k  = (const float*)d_in[5];
    const float* w_v  = (const float*)d_in[6];
    const float* b_v  = (const float*)d_in[7];
    const float* w_o  = (const float*)d_in[8];
    const float* b_o  = (const float*)d_in[9];
    const float* w1   = (const float*)d_in[10];
    const float* b1   = (const float*)d_in[11];
    const float* w2   = (const float*)d_in[12];
    const float* b2   = (const float*)d_in[13];
    const float* g1   = (const float*)d_in[14];
    const float* be1  = (const float*)d_in[15];
    const float* g2   = (const float*)d_in[16];
    const float* be2  = (const float*)d_in[17];

    float *q, *k, *v, *ctx, *t1, *h, *hr, *ff;
    float *xr, *wqr, *wkr, *wvr, *wor, *w1r, *w2r;
    cudaGetSymbolAddress((void**)&q,   g_q);
    cudaGetSymbolAddress((void**)&k,   g_k);
    cudaGetSymbolAddress((void**)&v,   g_v);
    cudaGetSymbolAddress((void**)&ctx, g_ctx);
    cudaGetSymbolAddress((void**)&t1,  g_t1);
    cudaGetSymbolAddress((void**)&h,   g_h);
    cudaGetSymbolAddress((void**)&hr,  g_hr);
    cudaGetSymbolAddress((void**)&ff,  g_ff);
    cudaGetSymbolAddress((void**)&xr,  g_xr);
    cudaGetSymbolAddress((void**)&wqr, g_wqr);
    cudaGetSymbolAddress((void**)&wkr, g_wkr);
    cudaGetSymbolAddress((void**)&wvr, g_wvr);
    cudaGetSymbolAddress((void**)&wor, g_wor);
    cudaGetSymbolAddress((void**)&w1r, g_w1r);
    cudaGetSymbolAddress((void**)&w2r, g_w2r);

    cudaFuncSetAttribute(gemm_tf32, cudaFuncAttributeMaxDynamicSharedMemorySize,
                         GEMM_SMEM_BYTES);
    cudaFuncSetAttribute(attn3, cudaFuncAttributeMaxDynamicSharedMemorySize,
                         ATTN_SMEM_BYTES);

    // ---- pre-round GEMM inputs to tf32 (rna) ----
    {
        const int TB = 256;
        int n;
        n = MROWS * DMODEL / 4;  round_tf32_kernel<<<(n + TB - 1) / TB, TB>>>(x,   xr,  n);
        n = DMODEL * DMODEL / 4; round_tf32_kernel<<<(n + TB - 1) / TB, TB>>>(w_q, wqr, n);
        n = DMODEL * DMODEL / 4; round_tf32_kernel<<<(n + TB - 1) / TB, TB>>>(w_k, wkr, n);
        n = DMODEL * DMODEL / 4; round_tf32_kernel<<<(n + TB - 1) / TB, TB>>>(w_v, wvr, n);
        n = DMODEL * DMODEL / 4; round_tf32_kernel<<<(n + TB - 1) / TB, TB>>>(w_o, wor, n);
        n = DMODEL * DFF / 4;    round_tf32_kernel<<<(n + TB - 1) / TB, TB>>>(w1,  w1r, n);
        n = DFF * DMODEL / 4;    round_tf32_kernel<<<(n + TB - 1) / TB, TB>>>(w2,  w2r, n);
    }

    dim3 blk(128);
    dim3 blk256(256);
    dim3 gProj(DMODEL / 128, MROWS / 128);   // (8, 64)
    dim3 gFF1(DFF / 128, MROWS / 128);       // (32, 64)
    dim3 gAtt(SEQ / 128, NHEADS, BATCH);     // (16, 16, 4)

    // QKV projections: outputs rounded to tf32 (consumed by attn mma)
    gemm_tf32<<<gProj, blk, GEMM_SMEM_BYTES>>>(MROWS, DMODEL, DMODEL, xr, wqr, b_q, q, 0, 1);
    gemm_tf32<<<gProj, blk, GEMM_SMEM_BYTES>>>(MROWS, DMODEL, DMODEL, xr, wkr, b_k, k, 0, 1);
    gemm_tf32<<<gProj, blk, GEMM_SMEM_BYTES>>>(MROWS, DMODEL, DMODEL, xr, wvr, b_v, v, 0, 1);

    attn3<<<gAtt, blk256, ATTN_SMEM_BYTES>>>(q, k, v, mask, ctx);  // ctx rounded

    gemm_tf32<<<gProj, blk, GEMM_SMEM_BYTES>>>(MROWS, DMODEL, DMODEL, ctx, wor, b_o, t1, 0, 0);
    add_ln_kernel<<<MROWS, 256>>>(x, t1, g1, be1, h, hr);

    gemm_tf32<<<gFF1, blk, GEMM_SMEM_BYTES>>>(MROWS, DFF, DMODEL, hr, w1r, b1, ff, 1, 1);
    gemm_tf32<<<gProj, blk, GEMM_SMEM_BYTES>>>(MROWS, DMODEL, DFF, ff, w2r, b2, t1, 0, 0);
    add_ln_kernel<<<MROWS, 256>>>(h, t1, g2, be2, (float*)d_out, nullptr);
}

// round 14
// speedup vs baseline: 2.2846x; 1.4606x over previous
#include <cuda_runtime.h>
#include <cuda_fp16.h>
#include <math.h>
#include <stdint.h>

// ---------------------------------------------------------------------------
// Problem constants
// ---------------------------------------------------------------------------
#define BATCH 4
#define SEQ   2048
#define DMODEL 1024
#define NHEADS 16
#define DK    64
#define DFF   4096
#define MROWS (BATCH * SEQ)   // 8192

// ---------------------------------------------------------------------------
// Scratch (no cudaMalloc allowed)
// ---------------------------------------------------------------------------
__device__ float  g_q  [MROWS * DMODEL];
__device__ float  g_k  [MROWS * DMODEL];
__device__ float  g_v  [MROWS * DMODEL];
__device__ float  g_t1 [MROWS * DMODEL];
__device__ float  g_h  [MROWS * DMODEL];
__device__ __half g_hh [MROWS * DMODEL];
__device__ __half g_ctxh[MROWS * DMODEL];
__device__ __half g_ffh[MROWS * DFF];
__device__ __half g_xh [MROWS * DMODEL];
__device__ __half g_wqh[DMODEL * DMODEL];   // transposed [N,K] fp16
__device__ __half g_wkh[DMODEL * DMODEL];
__device__ __half g_wvh[DMODEL * DMODEL];
__device__ __half g_woh[DMODEL * DMODEL];
__device__ __half g_w1h[DFF * DMODEL];      // [4096,1024]
__device__ __half g_w2h[DMODEL * DFF];      // [1024,4096]

// ---------------------------------------------------------------------------
// Helpers
// ---------------------------------------------------------------------------
__device__ __forceinline__ unsigned cvt_tf32(float x) {
    unsigned r;
    asm("cvt.rna.tf32.f32 %0, %1;" : "=r"(r) : "f"(x));
    return r;
}
__device__ __forceinline__ float rnd_tf32(float x) {
    return __uint_as_float(cvt_tf32(x));
}

__device__ __forceinline__ void mma_tf32(float* c, const unsigned* a, const unsigned* b) {
    asm volatile(
        "mma.sync.aligned.m16n8k8.row.col.f32.tf32.tf32.f32 "
        "{%0,%1,%2,%3}, {%4,%5,%6,%7}, {%8,%9}, {%0,%1,%2,%3};"
        : "+f"(c[0]), "+f"(c[1]), "+f"(c[2]), "+f"(c[3])
        : "r"(a[0]), "r"(a[1]), "r"(a[2]), "r"(a[3]), "r"(b[0]), "r"(b[1]));
}

__device__ __forceinline__ void mma_f16(float* c, const unsigned* a, const unsigned* b) {
    asm volatile(
        "mma.sync.aligned.m16n8k16.row.col.f32.f16.f16.f32 "
        "{%0,%1,%2,%3}, {%4,%5,%6,%7}, {%8,%9}, {%0,%1,%2,%3};"
        : "+f"(c[0]), "+f"(c[1]), "+f"(c[2]), "+f"(c[3])
        : "r"(a[0]), "r"(a[1]), "r"(a[2]), "r"(a[3]), "r"(b[0]), "r"(b[1]));
}

__device__ __forceinline__ void cp_async16(void* smem_dst, const void* gmem_src) {
    unsigned saddr = (unsigned)__cvta_generic_to_shared(smem_dst);
    asm volatile("cp.async.cg.shared.global [%0], [%1], 16;"
                 :: "r"(saddr), "l"(gmem_src));
}
#define CP_COMMIT() asm volatile("cp.async.commit_group;")
#define CP_WAIT(n)  asm volatile("cp.async.wait_group %0;" :: "n"(n))

// ---------------------------------------------------------------------------
// Prep: f32 -> fp16 elementwise
// ---------------------------------------------------------------------------
__global__ __launch_bounds__(256) void f2h_kernel(
    const float* __restrict__ src, __half* __restrict__ dst, int n4)
{
    int i = blockIdx.x * 256 + threadIdx.x;
    if (i < n4) {
        float4 v = ((const float4*)src)[i];
        __half2 lo = __floats2half2_rn(v.x, v.y);
        __half2 hi = __floats2half2_rn(v.z, v.w);
        ((__half2*)dst)[i * 2 + 0] = lo;
        ((__half2*)dst)[i * 2 + 1] = hi;
    }
}

// ---------------------------------------------------------------------------
// Prep: transpose + fp16: dst[C,R] = fp16(src[R,C]^T). Block (32,8).
// ---------------------------------------------------------------------------
__global__ __launch_bounds__(256) void transpose_h_kernel(
    const float* __restrict__ src, __half* __restrict__ dst, int R, int C)
{
    __shared__ float tile[32][33];
    const int c0 = blockIdx.x * 32, r0 = blockIdx.y * 32;
    const int tx = threadIdx.x, ty = threadIdx.y;
    #pragma unroll
    for (int i = 0; i < 32; i += 8)
        tile[ty + i][tx] = src[(size_t)(r0 + ty + i) * C + c0 + tx];
    __syncthreads();
    #pragma unroll
    for (int i = 0; i < 32; i += 8)
        dst[(size_t)(c0 + ty + i) * R + r0 + tx] = __float2half(tile[tx][ty + i]);
}

// ---------------------------------------------------------------------------
// FP16 tensor-core GEMM (mma.sync m16n8k16), 3-stage cp.async ring.
// C[M,N] = A[M,K] @ Bt[N,K]^T + bias   (A, Bt fp16 K-major; acc fp32)
// BM=BN=128, BK=64 (fp16), 128 threads = 4 warps (2x2), warp tile 64x64.
// Outputs: optional f32 C (opt tf32-rounded) and/or fp16 Ch. Optional ReLU.
// ---------------------------------------------------------------------------
#define HS_STRIDE 36                         // uints per row (72 fp16, 144 B)
#define H_TILE_UINTS (128 * HS_STRIDE)       // 4608 per operand
#define H_STAGE_UINTS (2 * H_TILE_UINTS)     // 9216
#define GEMM_SMEM_BYTES (3 * H_STAGE_UINTS * 4)   // 110592

__global__ __launch_bounds__(128, 2) void gemm_f16(
    int M, int N, int K,
    const __half* __restrict__ A, const __half* __restrict__ Bt,
    const float* __restrict__ bias,
    float* __restrict__ C, __half* __restrict__ Ch, int relu, int rnd)
{
    extern __shared__ unsigned smu[];

    const int tid  = threadIdx.x;
    const int lane = tid & 31;
    const int warp = tid >> 5;
    const int wm = (warp >> 1) * 64;   // 0,64
    const int wn = (warp & 1) * 64;    // 0,64
    const int g = lane >> 2;
    const int t = lane & 3;
    const int cRow = blockIdx.y, cCol = blockIdx.x;

    const __half* Ag = A  + (size_t)(cRow * 128) * K;
    const __half* Bg = Bt + (size_t)(cCol * 128) * K;

    float acc[4][8][4];
    #pragma unroll
    for (int i = 0; i < 4; i++)
        #pragma unroll
        for (int j = 0; j < 8; j++)
            #pragma unroll
            for (int e = 0; e < 4; e++) acc[i][j][e] = 0.f;

    const int NT = K >> 6;   // K/64 stages

    auto load_stage = [&](int s, int k0) {
        char* ab = (char*)smu + s * H_STAGE_UINTS * 4;
        char* bb = ab + H_TILE_UINTS * 4;
        #pragma unroll
        for (int i = 0; i < 8; i++) {            // A: 128 rows x 8 chunks(16B)
            int idx = tid + i * 128;
            int row = idx >> 3, cc = idx & 7;
            cp_async16(ab + row * 144 + cc * 16,
                       Ag + (size_t)row * K + k0 + cc * 8);
        }
        #pragma unroll
        for (int i = 0; i < 8; i++) {            // B: 128 rows x 8 chunks
            int idx = tid + i * 128;
            int row = idx >> 3, cc = idx & 7;
            cp_async16(bb + row * 144 + cc * 16,
                       Bg + (size_t)row * K + k0 + cc * 8);
        }
        CP_COMMIT();
    };

    load_stage(0, 0);
    load_stage(1, 64);

    int buf = 0;
    for (int it = 0; it < NT; it++) {
        if (it < NT - 1) { CP_WAIT(1); } else { CP_WAIT(0); }
        __syncthreads();   // stage `it` visible; stage it-1 fully consumed

        if (it + 2 < NT) {
            int wbuf = buf + 2; if (wbuf >= 3) wbuf -= 3;
            load_stage(wbuf, (it + 2) << 6);
        }

        const unsigned* As = smu + buf * H_STAGE_UINTS;
        const unsigned* Bs = As + H_TILE_UINTS;

        #pragma unroll
        for (int k16 = 0; k16 < 4; k16++) {
            const int kbu = k16 * 8;      // uint offset within row
            unsigned af[4][4], bf[8][2];
            #pragma unroll
            for (int tm = 0; tm < 4; tm++) {
                int r0 = (wm + tm * 16 + g) * HS_STRIDE;
                af[tm][0] = As[r0 + kbu + t];
                af[tm][1] = As[r0 + 8 * HS_STRIDE + kbu + t];
                af[tm][2] = As[r0 + kbu + 4 + t];
                af[tm][3] = As[r0 + 8 * HS_STRIDE + kbu + 4 + t];
            }
            #pragma unroll
            for (int tn = 0; tn < 8; tn++) {
                int n0 = (wn + tn * 8 + g) * HS_STRIDE;
                bf[tn][0] = Bs[n0 + kbu + t];
                bf[tn][1] = Bs[n0 + kbu + 4 + t];
            }
            #pragma unroll
            for (int tm = 0; tm < 4; tm++)
                #pragma unroll
                for (int tn = 0; tn < 8; tn++)
                    mma_f16(acc[tm][tn], af[tm], bf[tn]);
        }

        if (++buf == 3) buf = 0;
    }

    // ---- epilogue ----
    #pragma unroll
    for (int tm = 0; tm < 4; tm++) {
        #pragma unroll
        for (int tn = 0; tn < 8; tn++) {
            int row = cRow * 128 + wm + tm * 16 + g;
            int col = cCol * 128 + wn + tn * 8 + 2 * t;
            float2 bb = *(const float2*)(bias + col);
            float2 v0 = make_float2(acc[tm][tn][0] + bb.x, acc[tm][tn][1] + bb.y);
            float2 v1 = make_float2(acc[tm][tn][2] + bb.x, acc[tm][tn][3] + bb.y);
            if (relu) {
                v0.x = fmaxf(v0.x, 0.f); v0.y = fmaxf(v0.y, 0.f);
                v1.x = fmaxf(v1.x, 0.f); v1.y = fmaxf(v1.y, 0.f);
            }
            if (C) {
                float2 w0 = v0, w1 = v1;
                if (rnd) {
                    w0.x = rnd_tf32(w0.x); w0.y = rnd_tf32(w0.y);
                    w1.x = rnd_tf32(w1.x); w1.y = rnd_tf32(w1.y);
                }
                *(float2*)(C + (size_t)row * N + col) = w0;
                *(float2*)(C + (size_t)(row + 8) * N + col) = w1;
            }
            if (Ch) {
                *(__half2*)(Ch + (size_t)row * N + col) = __floats2half2_rn(v0.x, v0.y);
                *(__half2*)(Ch + (size_t)(row + 8) * N + col) = __floats2half2_rn(v1.x, v1.y);
            }
        }
    }
}

// ---------------------------------------------------------------------------
// Flash attention on tensor cores (tf32 mma.sync m16n8k8).
// Q/K/V are f32 holding exact tf32 values (rounded by QKV GEMM epilogue).
// Output ctx written as fp16 for the O-projection GEMM.
// ---------------------------------------------------------------------------
#define QS_STRIDE 68
#define KS_STRIDE 68
#define VS_STRIDE 72
#define ATTN_SMEM_BYTES (64 * KS_STRIDE * 4 + 64 * VS_STRIDE * 4 + 256)

__global__ __launch_bounds__(256, 2) void attn3(
    const float* __restrict__ Q, const float* __restrict__ K,
    const float* __restrict__ V, const int* __restrict__ mask,
    __half* __restrict__ O)
{
    extern __shared__ char smc[];
    float*    Qstage = (float*)smc;
    unsigned* Ks     = (unsigned*)smc;
    unsigned* Vs     = (unsigned*)(smc + 64 * KS_STRIDE * 4);
    float*    maskf  = (float*)(smc + 64 * KS_STRIDE * 4 + 64 * VS_STRIDE * 4);

    const int qt = blockIdx.x, h = blockIdx.y, b = blockIdx.z;
    const int tid  = threadIdx.x;
    const int lane = tid & 31;
    const int warp = tid >> 5;
    const int g = lane >> 2;
    const int t = lane & 3;
    const size_t hoff = (size_t)h * DK;
    const size_t qrow0 = (size_t)b * SEQ + qt * 128;

    #pragma unroll
    for (int it = 0; it < 8; it++) {
        int idx = tid + it * 256;
        int r = idx >> 4;
        int c4 = (idx & 15) << 2;
        float4 v = *(const float4*)(Q + (qrow0 + r) * DMODEL + hoff + c4);
        v.x *= 0.125f; v.y *= 0.125f; v.z *= 0.125f; v.w *= 0.125f;
        *(float4*)&Qstage[r * QS_STRIDE + c4] = v;
    }
    __syncthreads();

    unsigned qf[8][4];
    {
        const int r0 = warp * 16;
        #pragma unroll
        for (int kk = 0; kk < 8; kk++) {
            qf[kk][0] = cvt_tf32(Qstage[(r0 + g)     * QS_STRIDE + kk * 8 + t]);
            qf[kk][1] = cvt_tf32(Qstage[(r0 + 8 + g) * QS_STRIDE + kk * 8 + t]);
            qf[kk][2] = cvt_tf32(Qstage[(r0 + g)     * QS_STRIDE + kk * 8 + 4 + t]);
            qf[kk][3] = cvt_tf32(Qstage[(r0 + 8 + g) * QS_STRIDE + kk * 8 + 4 + t]);
        }
    }
    __syncthreads();

    float m0 = -INFINITY, m1 = -INFINITY, l0 = 0.f, l1 = 0.f;
    float oacc[8][4];
    #pragma unroll
    for (int j = 0; j < 8; j++)
        #pragma unroll
        for (int e = 0; e < 4; e++) oacc[j][e] = 0.f;

    for (int kt = 0; kt < 32; kt++) {
        const size_t kvbase = ((size_t)b * SEQ + kt * 64) * DMODEL + hoff;

        #pragma unroll
        for (int it = 0; it < 4; it++) {
            int idx = tid + it * 256;
            int r = idx >> 4;
            int c4 = (idx & 15) << 2;
            *(uint4*)&Ks[r * KS_STRIDE + c4] =
                *(const uint4*)(K + kvbase + (size_t)r * DMODEL + c4);
            *(uint4*)&Vs[r * VS_STRIDE + c4] =
                *(const uint4*)(V + kvbase + (size_t)r * DMODEL + c4);
        }
        if (tid < 64)
            maskf[tid] = (mask[(size_t)b * SEQ + kt * 64 + tid] == 0) ? -INFINITY : 0.f;
        __syncthreads();

        float sacc[8][4];
        #pragma unroll
        for (int j = 0; j < 8; j++)
            #pragma unroll
            for (int e = 0; e < 4; e++) sacc[j][e] = 0.f;

        #pragma unroll
        for (int kk = 0; kk < 8; kk++) {
            #pragma unroll
            for (int nj = 0; nj < 8; nj++) {
                unsigned bf[2];
                bf[0] = Ks[(nj * 8 + g) * KS_STRIDE + kk * 8 + t];
                bf[1] = Ks[(nj * 8 + g) * KS_STRIDE + kk * 8 + 4 + t];
                mma_tf32(sacc[nj], qf[kk], bf);
            }
        }

        #pragma unroll
        for (int nj = 0; nj < 8; nj++) {
            float mk0 = maskf[nj * 8 + 2 * t];
            float mk1 = maskf[nj * 8 + 2 * t + 1];
            sacc[nj][0] += mk0; sacc[nj][1] += mk1;
            sacc[nj][2] += mk0; sacc[nj][3] += mk1;
        }

        {
            float mx0 = -INFINITY, mx1 = -INFINITY;
            #pragma unroll
            for (int nj = 0; nj < 8; nj++) {
                mx0 = fmaxf(mx0, fmaxf(sacc[nj][0], sacc[nj][1]));
                mx1 = fmaxf(mx1, fmaxf(sacc[nj][2], sacc[nj][3]));
            }
            mx0 = fmaxf(mx0, __shfl_xor_sync(0xffffffffu, mx0, 1));
            mx0 = fmaxf(mx0, __shfl_xor_sync(0xffffffffu, mx0, 2));
            mx1 = fmaxf(mx1, __shfl_xor_sync(0xffffffffu, mx1, 1));
            mx1 = fmaxf(mx1, __shfl_xor_sync(0xffffffffu, mx1, 2));
            float mn0 = fmaxf(m0, mx0), mn1 = fmaxf(m1, mx1);
            float corr0 = __expf(m0 - mn0), corr1 = __expf(m1 - mn1);

            float rs0 = 0.f, rs1 = 0.f;
            #pragma unroll
            for (int nj = 0; nj < 8; nj++) {
                sacc[nj][0] = __expf(sacc[nj][0] - mn0);
                sacc[nj][1] = __expf(sacc[nj][1] - mn0);
                sacc[nj][2] = __expf(sacc[nj][2] - mn1);
                sacc[nj][3] = __expf(sacc[nj][3] - mn1);
                rs0 += sacc[nj][0] + sacc[nj][1];
                rs1 += sacc[nj][2] + sacc[nj][3];
            }
            rs0 += __shfl_xor_sync(0xffffffffu, rs0, 1);
            rs0 += __shfl_xor_sync(0xffffffffu, rs0, 2);
            rs1 += __shfl_xor_sync(0xffffffffu, rs1, 1);
            rs1 += __shfl_xor_sync(0xffffffffu, rs1, 2);
            l0 = l0 * corr0 + rs0;  m0 = mn0;
            l1 = l1 * corr1 + rs1;  m1 = mn1;
            #pragma unroll
            for (int j = 0; j < 8; j++) {
                oacc[j][0] *= corr0; oacc[j][1] *= corr0;
                oacc[j][2] *= corr1; oacc[j][3] *= corr1;
            }
        }

        {
            const int src_lo = (lane & ~3) | (t >> 1);
            const int src_hi = src_lo + 2;
            const bool odd = (t & 1);
            #pragma unroll
            for (int j = 0; j < 8; j++) {
                float c0a = __shfl_sync(0xffffffffu, sacc[j][0], src_lo);
                float c1a = __shfl_sync(0xffffffffu, sacc[j][1], src_lo);
                float c0b = __shfl_sync(0xffffffffu, sacc[j][0], src_hi);
                float c1b = __shfl_sync(0xffffffffu, sacc[j][1], src_hi);
                float c2a = __shfl_sync(0xffffffffu, sacc[j][2], src_lo);
                float c3a = __shfl_sync(0xffffffffu, sacc[j][3], src_lo);
                float c2b = __shfl_sync(0xffffffffu, sacc[j][2], src_hi);
                float c3b = __shfl_sync(0xffffffffu, sacc[j][3], src_hi);
                unsigned af[4];
                af[0] = __float_as_uint(odd ? c1a : c0a);
                af[1] = __float_as_uint(odd ? c3a : c2a);
                af[2] = __float_as_uint(odd ? c1b : c0b);
                af[3] = __float_as_uint(odd ? c3b : c2b);
                #pragma unroll
                for (int jj = 0; jj < 8; jj++) {
                    unsigned bf[2];
                    bf[0] = Vs[(j * 8 + t)     * VS_STRIDE + jj * 8 + g];
                    bf[1] = Vs[(j * 8 + t + 4) * VS_STRIDE + jj * 8 + g];
                    mma_tf32(oacc[jj], af, bf);
                }
            }
        }
        __syncthreads();
    }

    {
        const float inv0 = 1.f / l0, inv1 = 1.f / l1;
        const size_t r0 = qrow0 + warp * 16 + g;
        #pragma unroll
        for (int jj = 0; jj < 8; jj++) {
            int col = jj * 8 + 2 * t;
            *(__half2*)(O + r0 * DMODEL + hoff + col) =
                __floats2half2_rn(oacc[jj][0] * inv0, oacc[jj][1] * inv0);
            *(__half2*)(O + (r0 + 8) * DMODEL + hoff + col) =
                __floats2half2_rn(oacc[jj][2] * inv1, oacc[jj][3] * inv1);
        }
    }
}

// ---------------------------------------------------------------------------
// out[row] = LayerNorm(a[row] + b[row]) * gamma + beta (+ optional fp16 copy)
// ---------------------------------------------------------------------------
__global__ __launch_bounds__(256) void add_ln_kernel(
    const float* __restrict__ a, const float* __restrict__ bsrc,
    const float* __restrict__ g, const float* __restrict__ be,
    float* __restrict__ out, __half* __restrict__ out_h)
{
    const int row = blockIdx.x;
    const int tid = threadIdx.x;
    const float* pa = a + (size_t)row * DMODEL;
    const float* pb = bsrc + (size_t)row * DMODEL;

    float v[4];
    float sum = 0.f, sq = 0.f;
    #pragma unroll
    for (int i = 0; i < 4; i++) {
        int c = tid + i * 256;
        float x = pa[c] + pb[c];
        v[i] = x;
        sum += x;
        sq += x * x;
    }
    #pragma unroll
    for (int o = 16; o > 0; o >>= 1) {
        sum += __shfl_xor_sync(0xffffffffu, sum, o);
        sq  += __shfl_xor_sync(0xffffffffu, sq,  o);
    }
    __shared__ float ssum[8], ssq[8];
    if ((tid & 31) == 0) { ssum[tid >> 5] = sum; ssq[tid >> 5] = sq; }
    __syncthreads();
    if (tid < 32) {
        float s2 = (tid < 8) ? ssum[tid] : 0.f;
        float q2 = (tid < 8) ? ssq[tid] : 0.f;
        #pragma unroll
        for (int o = 4; o > 0; o >>= 1) {
            s2 += __shfl_xor_sync(0xffffffffu, s2, o);
            q2 += __shfl_xor_sync(0xffffffffu, q2, o);
        }
        if (tid == 0) { ssum[0] = s2; ssq[0] = q2; }
    }
    __syncthreads();
    const float mu   = ssum[0] * (1.f / DMODEL);
    const float var  = ssq[0] * (1.f / DMODEL) - mu * mu;
    const float rstd = rsqrtf(var + 1e-5f);

    float* po = out + (size_t)row * DMODEL;
    __half* ph = out_h ? out_h + (size_t)row * DMODEL : nullptr;
    #pragma unroll
    for (int i = 0; i < 4; i++) {
        int c = tid + i * 256;
        float y = (v[i] - mu) * rstd * g[c] + be[c];
        po[c] = y;
        if (ph) ph[c] = __float2half(y);
    }
}

// ---------------------------------------------------------------------------
// Launch
// ---------------------------------------------------------------------------
extern "C" void kernel_launch(void* const* d_in, const int* in_sizes, int n_in,
                              void* d_out, int out_size)
{
    (void)in_sizes; (void)n_in; (void)out_size;
    const float* x    = (const float*)d_in[0];
    const int*   mask = (const int*)  d_in[1];
    const float* w_q  = (const float*)d_in[2];
    const float* b_q  = (const float*)d_in[3];
    const float* w_k  = (const float*)d_in[4];
    const float* b_k  = (const float*)d_in[5];
    const float* w_v  = (const float*)d_in[6];
    const float* b_v  = (const float*)d_in[7];
    const float* w_o  = (const float*)d_in[8];
    const float* b_o  = (const float*)d_in[9];
    const float* w1   = (const float*)d_in[10];
    const float* b1   = (const float*)d_in[11];
    const float* w2   = (const float*)d_in[12];
    const float* b2   = (const float*)d_in[13];
    const float* g1   = (const float*)d_in[14];
    const float* be1  = (const float*)d_in[15];
    const float* g2   = (const float*)d_in[16];
    const float* be2  = (const float*)d_in[17];

    float *q, *k, *v, *t1, *h;
    __half *hh, *ctxh, *ffh, *xh, *wqh, *wkh, *wvh, *woh, *w1h, *w2h;
    cudaGetSymbolAddress((void**)&q,    g_q);
    cudaGetSymbolAddress((void**)&k,    g_k);
    cudaGetSymbolAddress((void**)&v,    g_v);
    cudaGetSymbolAddress((void**)&t1,   g_t1);
    cudaGetSymbolAddress((void**)&h,    g_h);
    cudaGetSymbolAddress((void**)&hh,   g_hh);
    cudaGetSymbolAddress((void**)&ctxh, g_ctxh);
    cudaGetSymbolAddress((void**)&ffh,  g_ffh);
    cudaGetSymbolAddress((void**)&xh,   g_xh);
    cudaGetSymbolAddress((void**)&wqh,  g_wqh);
    cudaGetSymbolAddress((void**)&wkh,  g_wkh);
    cudaGetSymbolAddress((void**)&wvh,  g_wvh);
    cudaGetSymbolAddress((void**)&woh,  g_woh);
    cudaGetSymbolAddress((void**)&w1h,  g_w1h);
    cudaGetSymbolAddress((void**)&w2h,  g_w2h);

    cudaFuncSetAttribute(gemm_f16, cudaFuncAttributeMaxDynamicSharedMemorySize,
                         GEMM_SMEM_BYTES);
    cudaFuncSetAttribute(attn3, cudaFuncAttributeMaxDynamicSharedMemorySize,
                         ATTN_SMEM_BYTES);

    // ---- prep: x -> fp16; weights transpose+fp16 to [N,K] ----
    {
        const int TB = 256;
        int n = MROWS * DMODEL / 4;
        f2h_kernel<<<(n + TB - 1) / TB, TB>>>(x, xh, n);
        dim3 tb(32, 8);
        transpose_h_kernel<<<dim3(DMODEL / 32, DMODEL / 32), tb>>>(w_q, wqh, DMODEL, DMODEL);
        transpose_h_kernel<<<dim3(DMODEL / 32, DMODEL / 32), tb>>>(w_k, wkh, DMODEL, DMODEL);
        transpose_h_kernel<<<dim3(DMODEL / 32, DMODEL / 32), tb>>>(w_v, wvh, DMODEL, DMODEL);
        transpose_h_kernel<<<dim3(DMODEL / 32, DMODEL / 32), tb>>>(w_o, woh, DMODEL, DMODEL);
        transpose_h_kernel<<<dim3(DFF / 32, DMODEL / 32), tb>>>(w1, w1h, DMODEL, DFF);
        transpose_h_kernel<<<dim3(DMODEL / 32, DFF / 32), tb>>>(w2, w2h, DFF, DMODEL);
    }

    dim3 blk128(128);
    dim3 gProj(DMODEL / 128, MROWS / 128);   // (8, 64)
    dim3 gFF1(DFF / 128, MROWS / 128);       // (32, 64)
    dim3 gAtt(SEQ / 128, NHEADS, BATCH);     // (16, 16, 4)

    // QKV: f32 outputs rounded to tf32 (consumed by attn tf32 mma)
    gemm_f16<<<gProj, blk128, GEMM_SMEM_BYTES>>>(MROWS, DMODEL, DMODEL, xh, wqh, b_q, q, nullptr, 0, 1);
    gemm_f16<<<gProj, blk128, GEMM_SMEM_BYTES>>>(MROWS, DMODEL, DMODEL, xh, wkh, b_k, k, nullptr, 0, 1);
    gemm_f16<<<gProj, blk128, GEMM_SMEM_BYTES>>>(MROWS, DMODEL, DMODEL, xh, wvh, b_v, v, nullptr, 0, 1);

    attn3<<<gAtt, 256, ATTN_SMEM_BYTES>>>(q, k, v, mask, ctxh);   // ctx in fp16

    gemm_f16<<<gProj, blk128, GEMM_SMEM_BYTES>>>(MROWS, DMODEL, DMODEL, ctxh, woh, b_o, t1, nullptr, 0, 0);
    add_ln_kernel<<<MROWS, 256>>>(x, t1, g1, be1, h, hh);

    gemm_f16<<<gFF1, blk128, GEMM_SMEM_BYTES>>>(MROWS, DFF, DMODEL, hh, w1h, b1, nullptr, ffh, 1, 0);
    gemm_f16<<<gProj, blk128, GEMM_SMEM_BYTES>>>(MROWS, DMODEL, DFF, ffh, w2h, b2, t1, nullptr, 0, 0);
    add_ln_kernel<<<MROWS, 256>>>(h, t1, g2, be2, (float*)d_out, nullptr);
}

// round 15
// speedup vs baseline: 2.9254x; 1.2805x over previous
#include <cuda_runtime.h>
#include <cuda_fp16.h>
#include <math.h>
#include <stdint.h>

// ---------------------------------------------------------------------------
// Problem constants
// ---------------------------------------------------------------------------
#define BATCH 4
#define SEQ   2048
#define DMODEL 1024
#define NHEADS 16
#define DK    64
#define DFF   4096
#define MROWS (BATCH * SEQ)   // 8192

// ---------------------------------------------------------------------------
// Scratch (no cudaMalloc allowed)
// ---------------------------------------------------------------------------
__device__ float  g_q  [MROWS * DMODEL];
__device__ float  g_k  [MROWS * DMODEL];
__device__ float  g_v  [MROWS * DMODEL];
__device__ float  g_t1 [MROWS * DMODEL];
__device__ float  g_h  [MROWS * DMODEL];
__device__ __half g_hh [MROWS * DMODEL];
__device__ __half g_ctxh[MROWS * DMODEL];
__device__ __half g_ffh[MROWS * DFF];
__device__ __half g_xh [MROWS * DMODEL];
__device__ __half g_wqh[DMODEL * DMODEL];   // transposed [N,K] fp16
__device__ __half g_wkh[DMODEL * DMODEL];
__device__ __half g_wvh[DMODEL * DMODEL];
__device__ __half g_woh[DMODEL * DMODEL];
__device__ __half g_w1h[DFF * DMODEL];      // [4096,1024]
__device__ __half g_w2h[DMODEL * DFF];      // [1024,4096]

// ---------------------------------------------------------------------------
// Helpers
// ---------------------------------------------------------------------------
__device__ __forceinline__ unsigned cvt_tf32(float x) {
    unsigned r;
    asm("cvt.rna.tf32.f32 %0, %1;" : "=r"(r) : "f"(x));
    return r;
}
__device__ __forceinline__ float rnd_tf32(float x) {
    return __uint_as_float(cvt_tf32(x));
}

__device__ __forceinline__ void mma_f16(float* c, const unsigned* a, const unsigned* b) {
    asm volatile(
        "mma.sync.aligned.m16n8k16.row.col.f32.f16.f16.f32 "
        "{%0,%1,%2,%3}, {%4,%5,%6,%7}, {%8,%9}, {%0,%1,%2,%3};"
        : "+f"(c[0]), "+f"(c[1]), "+f"(c[2]), "+f"(c[3])
        : "r"(a[0]), "r"(a[1]), "r"(a[2]), "r"(a[3]), "r"(b[0]), "r"(b[1]));
}

__device__ __forceinline__ void ldsm_x4(unsigned* r, uint32_t addr) {
    asm volatile("ldmatrix.sync.aligned.m8n8.x4.shared.b16 {%0,%1,%2,%3}, [%4];"
                 : "=r"(r[0]), "=r"(r[1]), "=r"(r[2]), "=r"(r[3]) : "r"(addr));
}
__device__ __forceinline__ void ldsm_x4_t(unsigned* r, uint32_t addr) {
    asm volatile("ldmatrix.sync.aligned.m8n8.x4.trans.shared.b16 {%0,%1,%2,%3}, [%4];"
                 : "=r"(r[0]), "=r"(r[1]), "=r"(r[2]), "=r"(r[3]) : "r"(addr));
}

__device__ __forceinline__ unsigned packh2(float a, float b) {
    __half2 h = __floats2half2_rn(a, b);
    return *reinterpret_cast<unsigned*>(&h);
}

__device__ __forceinline__ void cp_async16(void* smem_dst, const void* gmem_src) {
    unsigned saddr = (unsigned)__cvta_generic_to_shared(smem_dst);
    asm volatile("cp.async.cg.shared.global [%0], [%1], 16;"
                 :: "r"(saddr), "l"(gmem_src));
}
#define CP_COMMIT() asm volatile("cp.async.commit_group;")
#define CP_WAIT(n)  asm volatile("cp.async.wait_group %0;" :: "n"(n))

__device__ __forceinline__ uint32_t smem_u32(const void* p) {
    uint32_t a;
    asm("{ .reg .u64 t; cvta.to.shared.u64 t, %1; cvt.u32.u64 %0, t; }"
        : "=r"(a) : "l"(p));
    return a;
}

// ---------------------------------------------------------------------------
// Prep: f32 -> fp16 elementwise
// ---------------------------------------------------------------------------
__global__ __launch_bounds__(256) void f2h_kernel(
    const float* __restrict__ src, __half* __restrict__ dst, int n4)
{
    int i = blockIdx.x * 256 + threadIdx.x;
    if (i < n4) {
        float4 v = ((const float4*)src)[i];
        ((__half2*)dst)[i * 2 + 0] = __floats2half2_rn(v.x, v.y);
        ((__half2*)dst)[i * 2 + 1] = __floats2half2_rn(v.z, v.w);
    }
}

// ---------------------------------------------------------------------------
// Prep: transpose + fp16: dst[C,R] = fp16(src[R,C]^T). Block (32,8).
// ---------------------------------------------------------------------------
__global__ __launch_bounds__(256) void transpose_h_kernel(
    const float* __restrict__ src, __half* __restrict__ dst, int R, int C)
{
    __shared__ float tile[32][33];
    const int c0 = blockIdx.x * 32, r0 = blockIdx.y * 32;
    const int tx = threadIdx.x, ty = threadIdx.y;
    #pragma unroll
    for (int i = 0; i < 32; i += 8)
        tile[ty + i][tx] = src[(size_t)(r0 + ty + i) * C + c0 + tx];
    __syncthreads();
    #pragma unroll
    for (int i = 0; i < 32; i += 8)
        dst[(size_t)(c0 + ty + i) * R + r0 + tx] = __float2half(tile[tx][ty + i]);
}

// ---------------------------------------------------------------------------
// FP16 tensor-core GEMM (mma.sync m16n8k16), 3-stage cp.async ring.
// C[M,N] = A[M,K] @ Bt[N,K]^T + bias   (A, Bt fp16 K-major; acc fp32)
// BM=BN=128, BK=64 (fp16), 128 threads = 4 warps (2x2), warp tile 64x64.
// ---------------------------------------------------------------------------
#define HS_STRIDE 36                         // uints per row (72 fp16, 144 B)
#define H_TILE_UINTS (128 * HS_STRIDE)
#define H_STAGE_UINTS (2 * H_TILE_UINTS)
#define GEMM_SMEM_BYTES (3 * H_STAGE_UINTS * 4)   // 110592

__global__ __launch_bounds__(128, 2) void gemm_f16(
    int M, int N, int K,
    const __half* __restrict__ A, const __half* __restrict__ Bt,
    const float* __restrict__ bias,
    float* __restrict__ C, __half* __restrict__ Ch, int relu, int rnd)
{
    extern __shared__ unsigned smu[];

    const int tid  = threadIdx.x;
    const int lane = tid & 31;
    const int warp = tid >> 5;
    const int wm = (warp >> 1) * 64;
    const int wn = (warp & 1) * 64;
    const int g = lane >> 2;
    const int t = lane & 3;
    const int cRow = blockIdx.y, cCol = blockIdx.x;

    const __half* Ag = A  + (size_t)(cRow * 128) * K;
    const __half* Bg = Bt + (size_t)(cCol * 128) * K;

    float acc[4][8][4];
    #pragma unroll
    for (int i = 0; i < 4; i++)
        #pragma unroll
        for (int j = 0; j < 8; j++)
            #pragma unroll
            for (int e = 0; e < 4; e++) acc[i][j][e] = 0.f;

    const int NT = K >> 6;

    auto load_stage = [&](int s, int k0) {
        char* ab = (char*)smu + s * H_STAGE_UINTS * 4;
        char* bb = ab + H_TILE_UINTS * 4;
        #pragma unroll
        for (int i = 0; i < 8; i++) {
            int idx = tid + i * 128;
            int row = idx >> 3, cc = idx & 7;
            cp_async16(ab + row * 144 + cc * 16,
                       Ag + (size_t)row * K + k0 + cc * 8);
        }
        #pragma unroll
        for (int i = 0; i < 8; i++) {
            int idx = tid + i * 128;
            int row = idx >> 3, cc = idx & 7;
            cp_async16(bb + row * 144 + cc * 16,
                       Bg + (size_t)row * K + k0 + cc * 8);
        }
        CP_COMMIT();
    };

    load_stage(0, 0);
    load_stage(1, 64);

    int buf = 0;
    for (int it = 0; it < NT; it++) {
        if (it < NT - 1) { CP_WAIT(1); } else { CP_WAIT(0); }
        __syncthreads();

        if (it + 2 < NT) {
            int wbuf = buf + 2; if (wbuf >= 3) wbuf -= 3;
            load_stage(wbuf, (it + 2) << 6);
        }

        const unsigned* As = smu + buf * H_STAGE_UINTS;
        const unsigned* Bs = As + H_TILE_UINTS;

        #pragma unroll
        for (int k16 = 0; k16 < 4; k16++) {
            const int kbu = k16 * 8;
            unsigned af[4][4], bf[8][2];
            #pragma unroll
            for (int tm = 0; tm < 4; tm++) {
                int r0 = (wm + tm * 16 + g) * HS_STRIDE;
                af[tm][0] = As[r0 + kbu + t];
                af[tm][1] = As[r0 + 8 * HS_STRIDE + kbu + t];
                af[tm][2] = As[r0 + kbu + 4 + t];
                af[tm][3] = As[r0 + 8 * HS_STRIDE + kbu + 4 + t];
            }
            #pragma unroll
            for (int tn = 0; tn < 8; tn++) {
                int n0 = (wn + tn * 8 + g) * HS_STRIDE;
                bf[tn][0] = Bs[n0 + kbu + t];
                bf[tn][1] = Bs[n0 + kbu + 4 + t];
            }
            #pragma unroll
            for (int tm = 0; tm < 4; tm++)
                #pragma unroll
                for (int tn = 0; tn < 8; tn++)
                    mma_f16(acc[tm][tn], af[tm], bf[tn]);
        }

        if (++buf == 3) buf = 0;
    }

    #pragma unroll
    for (int tm = 0; tm < 4; tm++) {
        #pragma unroll
        for (int tn = 0; tn < 8; tn++) {
            int row = cRow * 128 + wm + tm * 16 + g;
            int col = cCol * 128 + wn + tn * 8 + 2 * t;
            float2 bb = *(const float2*)(bias + col);
            float2 v0 = make_float2(acc[tm][tn][0] + bb.x, acc[tm][tn][1] + bb.y);
            float2 v1 = make_float2(acc[tm][tn][2] + bb.x, acc[tm][tn][3] + bb.y);
            if (relu) {
                v0.x = fmaxf(v0.x, 0.f); v0.y = fmaxf(v0.y, 0.f);
                v1.x = fmaxf(v1.x, 0.f); v1.y = fmaxf(v1.y, 0.f);
            }
            if (C) {
                float2 w0 = v0, w1 = v1;
                if (rnd) {
                    w0.x = rnd_tf32(w0.x); w0.y = rnd_tf32(w0.y);
                    w1.x = rnd_tf32(w1.x); w1.y = rnd_tf32(w1.y);
                }
                *(float2*)(C + (size_t)row * N + col) = w0;
                *(float2*)(C + (size_t)(row + 8) * N + col) = w1;
            }
            if (Ch) {
                *(__half2*)(Ch + (size_t)row * N + col) = __floats2half2_rn(v0.x, v0.y);
                *(__half2*)(Ch + (size_t)(row + 8) * N + col) = __floats2half2_rn(v1.x, v1.y);
            }
        }
    }
}

// ---------------------------------------------------------------------------
// Flash attention on fp16 tensor cores (mma.sync m16n8k16).
// Block = (batch, head, 128-row Q tile); 256 threads = 8 warps.
// K,V tiles stored natural [key][dim] fp16 (144B row pitch); fragments via
// ldmatrix.x4 (K: plain, V: .trans). P accum layout == next A-frag layout,
// so P needs only cvt-packs, no shuffles. Softmax in fp32. Output fp16.
// ---------------------------------------------------------------------------
#define QS_STRIDE 68
#define KVH_PITCH 72     // halves per row (144 B)
#define ATTN_SMEM_BYTES (128 * QS_STRIDE * 4)   // 34816 (Q staging is the max)

__global__ __launch_bounds__(256, 2) void attn4(
    const float* __restrict__ Q, const float* __restrict__ K,
    const float* __restrict__ V, const int* __restrict__ mask,
    __half* __restrict__ O)
{
    extern __shared__ char smc[];
    float*  Qstage = (float*)smc;                          // staging only
    __half* Ksh    = (__half*)smc;                         // 64*72 fp16
    __half* Vsh    = (__half*)(smc + 64 * KVH_PITCH * 2);  // 64*72 fp16
    float*  maskf  = (float*)(smc + 2 * 64 * KVH_PITCH * 2);

    const int qt = blockIdx.x, h = blockIdx.y, b = blockIdx.z;
    const int tid  = threadIdx.x;
    const int lane = tid & 31;
    const int warp = tid >> 5;
    const int g = lane >> 2;
    const int t = lane & 3;
    const size_t hoff = (size_t)h * DK;
    const size_t qrow0 = (size_t)b * SEQ + qt * 128;

    // ---- Stage Q (scaled, f32), then pack per-warp fp16 A-fragments ----
    #pragma unroll
    for (int it = 0; it < 8; it++) {
        int idx = tid + it * 256;
        int r = idx >> 4;
        int c4 = (idx & 15) << 2;
        float4 v = *(const float4*)(Q + (qrow0 + r) * DMODEL + hoff + c4);
        v.x *= 0.125f; v.y *= 0.125f; v.z *= 0.125f; v.w *= 0.125f;
        *(float4*)&Qstage[r * QS_STRIDE + c4] = v;
    }
    __syncthreads();

    unsigned qf[4][4];
    {
        const int r0 = warp * 16;
        #pragma unroll
        for (int kk = 0; kk < 4; kk++) {
            const float* q0 = &Qstage[(r0 + g) * QS_STRIDE + kk * 16];
            const float* q1 = &Qstage[(r0 + 8 + g) * QS_STRIDE + kk * 16];
            float2 a = *(const float2*)(q0 + 2 * t);
            float2 bq = *(const float2*)(q1 + 2 * t);
            float2 c = *(const float2*)(q0 + 2 * t + 8);
            float2 d = *(const float2*)(q1 + 2 * t + 8);
            qf[kk][0] = packh2(a.x, a.y);
            qf[kk][1] = packh2(bq.x, bq.y);
            qf[kk][2] = packh2(c.x, c.y);
            qf[kk][3] = packh2(d.x, d.y);
        }
    }
    __syncthreads();   // Qstage dead; smem becomes Ksh/Vsh

    // ldmatrix per-lane base addresses
    const uint32_t ks_base = smem_u32(Ksh);
    const uint32_t vs_base = smem_u32(Vsh);
    const int l7 = lane & 7;
    // K (plain): matrix m = lane>>3: nj = 2*njp + (m>>1), khalf = m&1
    const uint32_t kaddr0 = ks_base
        + 144 * (16 * ((lane >> 4) & 1) + l7)     // wrong expr placeholder fixed below
        ;
    // (computed properly below; keep lane pieces)
    const int km = lane >> 3;                      // 0..3
    const uint32_t k_lane = ks_base + 144 * (8 * (km >> 1) + l7) + 16 * (km & 1);
    // V (.trans): jj = 2*jjp + (lane>>4), khalf = (lane>>3)&1, row = 16j+8kh+l7
    const uint32_t v_lane = vs_base + 144 * (8 * ((lane >> 3) & 1) + l7)
                          + 16 * (lane >> 4);
    (void)kaddr0;

    float m0 = -INFINITY, m1 = -INFINITY, l0 = 0.f, l1 = 0.f;
    float oacc[8][4];
    #pragma unroll
    for (int j = 0; j < 8; j++)
        #pragma unroll
        for (int e = 0; e < 4; e++) oacc[j][e] = 0.f;

    for (int kt = 0; kt < 32; kt++) {
        const size_t kvbase = ((size_t)b * SEQ + kt * 64) * DMODEL + hoff;

        // ---- Load K,V tiles, convert to fp16 ----
        #pragma unroll
        for (int it = 0; it < 4; it++) {
            int idx = tid + it * 256;
            int r = idx >> 4;
            int c4 = (idx & 15) << 2;
            float4 kv = *(const float4*)(K + kvbase + (size_t)r * DMODEL + c4);
            uint2 kp;
            kp.x = packh2(kv.x, kv.y);
            kp.y = packh2(kv.z, kv.w);
            *(uint2*)&Ksh[r * KVH_PITCH + c4] = kp;
            float4 vv = *(const float4*)(V + kvbase + (size_t)r * DMODEL + c4);
            uint2 vp;
            vp.x = packh2(vv.x, vv.y);
            vp.y = packh2(vv.z, vv.w);
            *(uint2*)&Vsh[r * KVH_PITCH + c4] = vp;
        }
        if (tid < 64)
            maskf[tid] = (mask[(size_t)b * SEQ + kt * 64 + tid] == 0) ? -INFINITY : 0.f;
        __syncthreads();

        // ---- S = Q @ K^T : 16 ldmatrix.x4 + 32 mma ----
        float sacc[8][4];
        #pragma unroll
        for (int j = 0; j < 8; j++)
            #pragma unroll
            for (int e = 0; e < 4; e++) sacc[j][e] = 0.f;

        #pragma unroll
        for (int k16 = 0; k16 < 4; k16++) {
            #pragma unroll
            for (int njp = 0; njp < 4; njp++) {
                unsigned bf[4];
                ldsm_x4(bf, k_lane + 2304u * njp + 32u * k16);
                mma_f16(sacc[2 * njp],     qf[k16], &bf[0]);
                mma_f16(sacc[2 * njp + 1], qf[k16], &bf[2]);
            }
        }

        // ---- Mask ----
        #pragma unroll
        for (int nj = 0; nj < 8; nj++) {
            float mk0 = maskf[nj * 8 + 2 * t];
            float mk1 = maskf[nj * 8 + 2 * t + 1];
            sacc[nj][0] += mk0; sacc[nj][1] += mk1;
            sacc[nj][2] += mk0; sacc[nj][3] += mk1;
        }

        // ---- Online softmax (rows g and g+8) ----
        {
            float mx0 = -INFINITY, mx1 = -INFINITY;
            #pragma unroll
            for (int nj = 0; nj < 8; nj++) {
                mx0 = fmaxf(mx0, fmaxf(sacc[nj][0], sacc[nj][1]));
                mx1 = fmaxf(mx1, fmaxf(sacc[nj][2], sacc[nj][3]));
            }
            mx0 = fmaxf(mx0, __shfl_xor_sync(0xffffffffu, mx0, 1));
            mx0 = fmaxf(mx0, __shfl_xor_sync(0xffffffffu, mx0, 2));
            mx1 = fmaxf(mx1, __shfl_xor_sync(0xffffffffu, mx1, 1));
            mx1 = fmaxf(mx1, __shfl_xor_sync(0xffffffffu, mx1, 2));
            float mn0 = fmaxf(m0, mx0), mn1 = fmaxf(m1, mx1);
            float corr0 = __expf(m0 - mn0), corr1 = __expf(m1 - mn1);

            float rs0 = 0.f, rs1 = 0.f;
            #pragma unroll
            for (int nj = 0; nj < 8; nj++) {
                sacc[nj][0] = __expf(sacc[nj][0] - mn0);
                sacc[nj][1] = __expf(sacc[nj][1] - mn0);
                sacc[nj][2] = __expf(sacc[nj][2] - mn1);
                sacc[nj][3] = __expf(sacc[nj][3] - mn1);
                rs0 += sacc[nj][0] + sacc[nj][1];
                rs1 += sacc[nj][2] + sacc[nj][3];
            }
            rs0 += __shfl_xor_sync(0xffffffffu, rs0, 1);
            rs0 += __shfl_xor_sync(0xffffffffu, rs0, 2);
            rs1 += __shfl_xor_sync(0xffffffffu, rs1, 1);
            rs1 += __shfl_xor_sync(0xffffffffu, rs1, 2);
            l0 = l0 * corr0 + rs0;  m0 = mn0;
            l1 = l1 * corr1 + rs1;  m1 = mn1;
            #pragma unroll
            for (int j = 0; j < 8; j++) {
                oacc[j][0] *= corr0; oacc[j][1] *= corr0;
                oacc[j][2] *= corr1; oacc[j][3] *= corr1;
            }
        }

        // ---- O += P @ V : P packs straight from sacc; V via ldmatrix.trans ----
        #pragma unroll
        for (int j = 0; j < 4; j++) {
            unsigned af[4];
            af[0] = packh2(sacc[2 * j][0],     sacc[2 * j][1]);
            af[1] = packh2(sacc[2 * j][2],     sacc[2 * j][3]);
            af[2] = packh2(sacc[2 * j + 1][0], sacc[2 * j + 1][1]);
            af[3] = packh2(sacc[2 * j + 1][2], sacc[2 * j + 1][3]);
            #pragma unroll
            for (int jjp = 0; jjp < 4; jjp++) {
                unsigned bf[4];
                ldsm_x4_t(bf, v_lane + 2304u * j + 32u * jjp);
                mma_f16(oacc[2 * jjp],     af, &bf[0]);
                mma_f16(oacc[2 * jjp + 1], af, &bf[2]);
            }
        }
        __syncthreads();   // tile consumed
    }

    // ---- Output (fp16) ----
    {
        const float inv0 = 1.f / l0, inv1 = 1.f / l1;
        const size_t r0 = qrow0 + warp * 16 + g;
        #pragma unroll
        for (int jj = 0; jj < 8; jj++) {
            int col = jj * 8 + 2 * t;
            *(__half2*)(O + r0 * DMODEL + hoff + col) =
                __floats2half2_rn(oacc[jj][0] * inv0, oacc[jj][1] * inv0);
            *(__half2*)(O + (r0 + 8) * DMODEL + hoff + col) =
                __floats2half2_rn(oacc[jj][2] * inv1, oacc[jj][3] * inv1);
        }
    }
}

// ---------------------------------------------------------------------------
// out[row] = LayerNorm(a[row] + b[row]) * gamma + beta (+ optional fp16 copy)
// ---------------------------------------------------------------------------
__global__ __launch_bounds__(256) void add_ln_kernel(
    const float* __restrict__ a, const float* __restrict__ bsrc,
    const float* __restrict__ g, const float* __restrict__ be,
    float* __restrict__ out, __half* __restrict__ out_h)
{
    const int row = blockIdx.x;
    const int tid = threadIdx.x;
    const float* pa = a + (size_t)row * DMODEL;
    const float* pb = bsrc + (size_t)row * DMODEL;

    float v[4];
    float sum = 0.f, sq = 0.f;
    #pragma unroll
    for (int i = 0; i < 4; i++) {
        int c = tid + i * 256;
        float x = pa[c] + pb[c];
        v[i] = x;
        sum += x;
        sq += x * x;
    }
    #pragma unroll
    for (int o = 16; o > 0; o >>= 1) {
        sum += __shfl_xor_sync(0xffffffffu, sum, o);
        sq  += __shfl_xor_sync(0xffffffffu, sq,  o);
    }
    __shared__ float ssum[8], ssq[8];
    if ((tid & 31) == 0) { ssum[tid >> 5] = sum; ssq[tid >> 5] = sq; }
    __syncthreads();
    if (tid < 32) {
        float s2 = (tid < 8) ? ssum[tid] : 0.f;
        float q2 = (tid < 8) ? ssq[tid] : 0.f;
        #pragma unroll
        for (int o = 4; o > 0; o >>= 1) {
            s2 += __shfl_xor_sync(0xffffffffu, s2, o);
            q2 += __shfl_xor_sync(0xffffffffu, q2, o);
        }
        if (tid == 0) { ssum[0] = s2; ssq[0] = q2; }
    }
    __syncthreads();
    const float mu   = ssum[0] * (1.f / DMODEL);
    const float var  = ssq[0] * (1.f / DMODEL) - mu * mu;
    const float rstd = rsqrtf(var + 1e-5f);

    float* po = out + (size_t)row * DMODEL;
    __half* ph = out_h ? out_h + (size_t)row * DMODEL : nullptr;
    #pragma unroll
    for (int i = 0; i < 4; i++) {
        int c = tid + i * 256;
        float y = (v[i] - mu) * rstd * g[c] + be[c];
        po[c] = y;
        if (ph) ph[c] = __float2half(y);
    }
}

// ---------------------------------------------------------------------------
// Launch
// ---------------------------------------------------------------------------
extern "C" void kernel_launch(void* const* d_in, const int* in_sizes, int n_in,
                              void* d_out, int out_size)
{
    (void)in_sizes; (void)n_in; (void)out_size;
    const float* x    = (const float*)d_in[0];
    const int*   mask = (const int*)  d_in[1];
    const float* w_q  = (const float*)d_in[2];
    const float* b_q  = (const float*)d_in[3];
    const float* w_k  = (const float*)d_in[4];
    const float* b_k  = (const float*)d_in[5];
    const float* w_v  = (const float*)d_in[6];
    const float* b_v  = (const float*)d_in[7];
    const float* w_o  = (const float*)d_in[8];
    const float* b_o  = (const float*)d_in[9];
    const float* w1   = (const float*)d_in[10];
    const float* b1   = (const float*)d_in[11];
    const float* w2   = (const float*)d_in[12];
    const float* b2   = (const float*)d_in[13];
    const float* g1   = (const float*)d_in[14];
    const float* be1  = (const float*)d_in[15];
    const float* g2   = (const float*)d_in[16];
    const float* be2  = (const float*)d_in[17];

    float *q, *k, *v, *t1, *h;
    __half *hh, *ctxh, *ffh, *xh, *wqh, *wkh, *wvh, *woh, *w1h, *w2h;
    cudaGetSymbolAddress((void**)&q,    g_q);
    cudaGetSymbolAddress((void**)&k,    g_k);
    cudaGetSymbolAddress((void**)&v,    g_v);
    cudaGetSymbolAddress((void**)&t1,   g_t1);
    cudaGetSymbolAddress((void**)&h,    g_h);
    cudaGetSymbolAddress((void**)&hh,   g_hh);
    cudaGetSymbolAddress((void**)&ctxh, g_ctxh);
    cudaGetSymbolAddress((void**)&ffh,  g_ffh);
    cudaGetSymbolAddress((void**)&xh,   g_xh);
    cudaGetSymbolAddress((void**)&wqh,  g_wqh);
    cudaGetSymbolAddress((void**)&wkh,  g_wkh);
    cudaGetSymbolAddress((void**)&wvh,  g_wvh);
    cudaGetSymbolAddress((void**)&woh,  g_woh);
    cudaGetSymbolAddress((void**)&w1h,  g_w1h);
    cudaGetSymbolAddress((void**)&w2h,  g_w2h);

    cudaFuncSetAttribute(gemm_f16, cudaFuncAttributeMaxDynamicSharedMemorySize,
                         GEMM_SMEM_BYTES);
    cudaFuncSetAttribute(attn4, cudaFuncAttributeMaxDynamicSharedMemorySize,
                         ATTN_SMEM_BYTES);

    // ---- prep ----
    {
        const int TB = 256;
        int n = MROWS * DMODEL / 4;
        f2h_kernel<<<(n + TB - 1) / TB, TB>>>(x, xh, n);
        dim3 tb(32, 8);
        transpose_h_kernel<<<dim3(DMODEL / 32, DMODEL / 32), tb>>>(w_q, wqh, DMODEL, DMODEL);
        transpose_h_kernel<<<dim3(DMODEL / 32, DMODEL / 32), tb>>>(w_k, wkh, DMODEL, DMODEL);
        transpose_h_kernel<<<dim3(DMODEL / 32, DMODEL / 32), tb>>>(w_v, wvh, DMODEL, DMODEL);
        transpose_h_kernel<<<dim3(DMODEL / 32, DMODEL / 32), tb>>>(w_o, woh, DMODEL, DMODEL);
        transpose_h_kernel<<<dim3(DFF / 32, DMODEL / 32), tb>>>(w1, w1h, DMODEL, DFF);
        transpose_h_kernel<<<dim3(DMODEL / 32, DFF / 32), tb>>>(w2, w2h, DFF, DMODEL);
    }

    dim3 blk128(128);
    dim3 gProj(DMODEL / 128, MROWS / 128);   // (8, 64)
    dim3 gFF1(DFF / 128, MROWS / 128);       // (32, 64)
    dim3 gAtt(SEQ / 128, NHEADS, BATCH);     // (16, 16, 4)

    gemm_f16<<<gProj, blk128, GEMM_SMEM_BYTES>>>(MROWS, DMODEL, DMODEL, xh, wqh, b_q, q, nullptr, 0, 0);
    gemm_f16<<<gProj, blk128, GEMM_SMEM_BYTES>>>(MROWS, DMODEL, DMODEL, xh, wkh, b_k, k, nullptr, 0, 0);
    gemm_f16<<<gProj, blk128, GEMM_SMEM_BYTES>>>(MROWS, DMODEL, DMODEL, xh, wvh, b_v, v, nullptr, 0, 0);

    attn4<<<gAtt, 256, ATTN_SMEM_BYTES>>>(q, k, v, mask, ctxh);   // ctx fp16

    gemm_f16<<<gProj, blk128, GEMM_SMEM_BYTES>>>(MROWS, DMODEL, DMODEL, ctxh, woh, b_o, t1, nullptr, 0, 0);
    add_ln_kernel<<<MROWS, 256>>>(x, t1, g1, be1, h, hh);

    gemm_f16<<<gFF1, blk128, GEMM_SMEM_BYTES>>>(MROWS, DFF, DMODEL, hh, w1h, b1, nullptr, ffh, 1, 0);
    gemm_f16<<<gProj, blk128, GEMM_SMEM_BYTES>>>(MROWS, DMODEL, DFF, ffh, w2h, b2, t1, nullptr, 0, 0);
    add_ln_kernel<<<MROWS, 256>>>(h, t1, g2, be2, (float*)d_out, nullptr);
}

// round 16
// speedup vs baseline: 3.1811x; 1.0874x over previous
#include <cuda_runtime.h>
#include <cuda_fp16.h>
#include <math.h>
#include <stdint.h>

// ---------------------------------------------------------------------------
// Problem constants
// ---------------------------------------------------------------------------
#define BATCH 4
#define SEQ   2048
#define DMODEL 1024
#define NHEADS 16
#define DK    64
#define DFF   4096
#define MROWS (BATCH * SEQ)   // 8192
#define NQKV  (3 * DMODEL)    // 3072

// ---------------------------------------------------------------------------
// Scratch (no cudaMalloc allowed)
// ---------------------------------------------------------------------------
__device__ float  g_t1 [MROWS * DMODEL];
__device__ float  g_h  [MROWS * DMODEL];
__device__ __half g_hh [MROWS * DMODEL];
__device__ __half g_ctxh[MROWS * DMODEL];
__device__ __half g_ffh[MROWS * DFF];
__device__ __half g_xh [MROWS * DMODEL];
__device__ __half g_qkvh[MROWS * NQKV];       // fused QKV output
__device__ __half g_wqkvh[NQKV * DMODEL];     // [3072,1024] transposed fp16
__device__ __half g_woh[DMODEL * DMODEL];
__device__ __half g_w1h[DFF * DMODEL];
__device__ __half g_w2h[DMODEL * DFF];
__device__ float  g_bqkv[NQKV];

// ---------------------------------------------------------------------------
// Helpers
// ---------------------------------------------------------------------------
__device__ __forceinline__ void mma_f16(float* c, const unsigned* a, const unsigned* b) {
    asm volatile(
        "mma.sync.aligned.m16n8k16.row.col.f32.f16.f16.f32 "
        "{%0,%1,%2,%3}, {%4,%5,%6,%7}, {%8,%9}, {%0,%1,%2,%3};"
        : "+f"(c[0]), "+f"(c[1]), "+f"(c[2]), "+f"(c[3])
        : "r"(a[0]), "r"(a[1]), "r"(a[2]), "r"(a[3]), "r"(b[0]), "r"(b[1]));
}

__device__ __forceinline__ void ldsm_x4(unsigned* r, uint32_t addr) {
    asm volatile("ldmatrix.sync.aligned.m8n8.x4.shared.b16 {%0,%1,%2,%3}, [%4];"
                 : "=r"(r[0]), "=r"(r[1]), "=r"(r[2]), "=r"(r[3]) : "r"(addr));
}
__device__ __forceinline__ void ldsm_x4_t(unsigned* r, uint32_t addr) {
    asm volatile("ldmatrix.sync.aligned.m8n8.x4.trans.shared.b16 {%0,%1,%2,%3}, [%4];"
                 : "=r"(r[0]), "=r"(r[1]), "=r"(r[2]), "=r"(r[3]) : "r"(addr));
}

__device__ __forceinline__ unsigned packh2(float a, float b) {
    __half2 h = __floats2half2_rn(a, b);
    return *reinterpret_cast<unsigned*>(&h);
}

__device__ __forceinline__ void cp_async16(void* smem_dst, const void* gmem_src) {
    unsigned saddr = (unsigned)__cvta_generic_to_shared(smem_dst);
    asm volatile("cp.async.cg.shared.global [%0], [%1], 16;"
                 :: "r"(saddr), "l"(gmem_src));
}
#define CP_COMMIT() asm volatile("cp.async.commit_group;")
#define CP_WAIT(n)  asm volatile("cp.async.wait_group %0;" :: "n"(n))

__device__ __forceinline__ uint32_t smem_u32(const void* p) {
    uint32_t a;
    asm("{ .reg .u64 t; cvta.to.shared.u64 t, %1; cvt.u32.u64 %0, t; }"
        : "=r"(a) : "l"(p));
    return a;
}

// ---------------------------------------------------------------------------
// Prep kernels
// ---------------------------------------------------------------------------
__global__ __launch_bounds__(256) void f2h_kernel(
    const float* __restrict__ src, __half* __restrict__ dst, int n4)
{
    int i = blockIdx.x * 256 + threadIdx.x;
    if (i < n4) {
        float4 v = ((const float4*)src)[i];
        ((__half2*)dst)[i * 2 + 0] = __floats2half2_rn(v.x, v.y);
        ((__half2*)dst)[i * 2 + 1] = __floats2half2_rn(v.z, v.w);
    }
}

__global__ __launch_bounds__(256) void transpose_h_kernel(
    const float* __restrict__ src, __half* __restrict__ dst, int R, int C)
{
    __shared__ float tile[32][33];
    const int c0 = blockIdx.x * 32, r0 = blockIdx.y * 32;
    const int tx = threadIdx.x, ty = threadIdx.y;
    #pragma unroll
    for (int i = 0; i < 32; i += 8)
        tile[ty + i][tx] = src[(size_t)(r0 + ty + i) * C + c0 + tx];
    __syncthreads();
    #pragma unroll
    for (int i = 0; i < 32; i += 8)
        dst[(size_t)(c0 + ty + i) * R + r0 + tx] = __float2half(tile[tx][ty + i]);
}

__global__ __launch_bounds__(256) void concat3_kernel(
    const float* __restrict__ a, const float* __restrict__ b,
    const float* __restrict__ c, float* __restrict__ dst, int n)
{
    int i = blockIdx.x * 256 + threadIdx.x;
    if (i < n) {
        dst[i] = a[i];
        dst[n + i] = b[i];
        dst[2 * n + i] = c[i];
    }
}

// ---------------------------------------------------------------------------
// FP16 tensor-core GEMM (mma.sync m16n8k16), 3-stage cp.async, ldmatrix frags.
// C[M,N] = A[M,K] @ Bt[N,K]^T + bias   (A, Bt fp16 K-major; acc fp32)
// BM=BN=128, BK=64, 128 threads = 4 warps (2x2), warp tile 64x64.
// ---------------------------------------------------------------------------
#define H_PITCH 144                              // bytes per 64-half row
#define H_TILE_BYTES (128 * H_PITCH)             // 18432
#define H_STAGE_BYTES (2 * H_TILE_BYTES)         // 36864
#define GEMM_SMEM_BYTES (3 * H_STAGE_BYTES)      // 110592

__global__ __launch_bounds__(128, 2) void gemm_f16(
    int M, int N, int K,
    const __half* __restrict__ A, const __half* __restrict__ Bt,
    const float* __restrict__ bias,
    float* __restrict__ C, __half* __restrict__ Ch, int relu)
{
    extern __shared__ char smc_g[];
    const uint32_t smem_base = smem_u32(smc_g);

    const int tid  = threadIdx.x;
    const int lane = tid & 31;
    const int warp = tid >> 5;
    const int wm = (warp >> 1) * 64;
    const int wn = (warp & 1) * 64;
    const int g = lane >> 2;
    const int t = lane & 3;
    const int cRow = blockIdx.y, cCol = blockIdx.x;

    const __half* Ag = A  + (size_t)(cRow * 128) * K;
    const __half* Bg = Bt + (size_t)(cCol * 128) * K;

    // ldmatrix lane offsets
    const int l7 = lane & 7, lm = lane >> 3;
    const uint32_t a_off = (uint32_t)(wm + 8 * (lm & 1) + l7) * H_PITCH + (lm >> 1) * 16;
    const uint32_t b_off = (uint32_t)(wn + 8 * (lm >> 1) + l7) * H_PITCH + (lm & 1) * 16;

    float acc[4][8][4];
    #pragma unroll
    for (int i = 0; i < 4; i++)
        #pragma unroll
        for (int j = 0; j < 8; j++)
            #pragma unroll
            for (int e = 0; e < 4; e++) acc[i][j][e] = 0.f;

    const int NT = K >> 6;

    auto load_stage = [&](int s, int k0) {
        char* ab = smc_g + s * H_STAGE_BYTES;
        char* bb = ab + H_TILE_BYTES;
        #pragma unroll
        for (int i = 0; i < 8; i++) {
            int idx = tid + i * 128;
            int row = idx >> 3, cc = idx & 7;
            cp_async16(ab + row * H_PITCH + cc * 16,
                       Ag + (size_t)row * K + k0 + cc * 8);
        }
        #pragma unroll
        for (int i = 0; i < 8; i++) {
            int idx = tid + i * 128;
            int row = idx >> 3, cc = idx & 7;
            cp_async16(bb + row * H_PITCH + cc * 16,
                       Bg + (size_t)row * K + k0 + cc * 8);
        }
        CP_COMMIT();
    };

    load_stage(0, 0);
    load_stage(1, 64);

    int buf = 0;
    for (int it = 0; it < NT; it++) {
        if (it < NT - 1) { CP_WAIT(1); } else { CP_WAIT(0); }
        __syncthreads();

        if (it + 2 < NT) {
            int wbuf = buf + 2; if (wbuf >= 3) wbuf -= 3;
            load_stage(wbuf, (it + 2) << 6);
        }

        const uint32_t abase = smem_base + buf * H_STAGE_BYTES;
        const uint32_t bbase = abase + H_TILE_BYTES;

        #pragma unroll
        for (int k16 = 0; k16 < 4; k16++) {
            unsigned af[4][4], bf[8][2];
            #pragma unroll
            for (int tm = 0; tm < 4; tm++)
                ldsm_x4(af[tm], abase + a_off + (uint32_t)tm * 16 * H_PITCH + k16 * 32);
            #pragma unroll
            for (int tnp = 0; tnp < 4; tnp++) {
                unsigned bq[4];
                ldsm_x4(bq, bbase + b_off + (uint32_t)tnp * 16 * H_PITCH + k16 * 32);
                bf[2 * tnp][0] = bq[0]; bf[2 * tnp][1] = bq[1];
                bf[2 * tnp + 1][0] = bq[2]; bf[2 * tnp + 1][1] = bq[3];
            }
            #pragma unroll
            for (int tm = 0; tm < 4; tm++)
                #pragma unroll
                for (int tn = 0; tn < 8; tn++)
                    mma_f16(acc[tm][tn], af[tm], bf[tn]);
        }

        if (++buf == 3) buf = 0;
    }

    #pragma unroll
    for (int tm = 0; tm < 4; tm++) {
        #pragma unroll
        for (int tn = 0; tn < 8; tn++) {
            int row = cRow * 128 + wm + tm * 16 + g;
            int col = cCol * 128 + wn + tn * 8 + 2 * t;
            float2 bb = *(const float2*)(bias + col);
            float2 v0 = make_float2(acc[tm][tn][0] + bb.x, acc[tm][tn][1] + bb.y);
            float2 v1 = make_float2(acc[tm][tn][2] + bb.x, acc[tm][tn][3] + bb.y);
            if (relu) {
                v0.x = fmaxf(v0.x, 0.f); v0.y = fmaxf(v0.y, 0.f);
                v1.x = fmaxf(v1.x, 0.f); v1.y = fmaxf(v1.y, 0.f);
            }
            if (C) {
                *(float2*)(C + (size_t)row * N + col) = v0;
                *(float2*)(C + (size_t)(row + 8) * N + col) = v1;
            }
            if (Ch) {
                *(__half2*)(Ch + (size_t)row * N + col) = __floats2half2_rn(v0.x, v0.y);
                *(__half2*)(Ch + (size_t)(row + 8) * N + col) = __floats2half2_rn(v1.x, v1.y);
            }
        }
    }
}

// ---------------------------------------------------------------------------
// Flash attention (fp16 m16n8k16). Input = fused QKV fp16 [MROWS, 3072]
// (Q at +0, K at +1024, V at +2048 within each row).
// K/V tiles via cp.async; Q/K frags via ldmatrix, V via ldmatrix.trans.
// Softmax fp32; output ctx fp16.
// ---------------------------------------------------------------------------
#define KV_PITCH 144
#define ATTN_SMEM_BYTES (2 * 64 * KV_PITCH + 512)   // Ksh+Vsh+mask (Q stage fits)

__global__ __launch_bounds__(256, 2) void attn5(
    const __half* __restrict__ QKV, const int* __restrict__ mask,
    __half* __restrict__ O)
{
    extern __shared__ char smc[];
    __half* Ksh = (__half*)smc;                        // 64 x 144B
    __half* Vsh = (__half*)(smc + 64 * KV_PITCH);      // 64 x 144B
    float*  maskf = (float*)(smc + 2 * 64 * KV_PITCH); // 64 floats

    const int qt = blockIdx.x, h = blockIdx.y, b = blockIdx.z;
    const int tid  = threadIdx.x;
    const int lane = tid & 31;
    const int warp = tid >> 5;
    const int g = lane >> 2;
    const int t = lane & 3;
    const int l7 = lane & 7, lm = lane >> 3;
    const size_t hoff = (size_t)h * DK;
    const size_t qrow0 = (size_t)b * SEQ + qt * 128;

    const uint32_t smem_base = smem_u32(smc);

    // ---- Stage Q fp16 (scaled by 0.125), extract A-frags via ldmatrix ----
    // Q staging reuses Ksh/Vsh area (128 rows x 144B = 18432 <= smem)
    {
        const __half2 s8 = __float2half2_rn(0.125f);
        #pragma unroll
        for (int it = 0; it < 4; it++) {
            int idx = tid + it * 256;
            int r = idx >> 3;
            int c8 = (idx & 7) * 8;
            uint4 u = *(const uint4*)(QKV + (qrow0 + r) * NQKV + hoff + c8);
            __half2* hp = (__half2*)&u;
            hp[0] = __hmul2(hp[0], s8);
            hp[1] = __hmul2(hp[1], s8);
            hp[2] = __hmul2(hp[2], s8);
            hp[3] = __hmul2(hp[3], s8);
            *(uint4*)(smc + r * KV_PITCH + c8 * 2) = u;
        }
    }
    __syncthreads();

    unsigned qf[4][4];
    {
        const uint32_t q_off = (uint32_t)(warp * 16 + 8 * (lm & 1) + l7) * KV_PITCH
                             + (lm >> 1) * 16;
        #pragma unroll
        for (int kk = 0; kk < 4; kk++)
            ldsm_x4(qf[kk], smem_base + q_off + kk * 32);
    }
    __syncthreads();   // Q staging dead

    // lane bases for K (plain) and V (trans) ldmatrix
    const uint32_t k_lane = smem_base + (uint32_t)(8 * (lm >> 1) + l7) * KV_PITCH
                          + (lm & 1) * 16;
    const uint32_t v_lane = smem_base + 64 * KV_PITCH
                          + (uint32_t)(8 * ((lane >> 3) & 1) + l7) * KV_PITCH
                          + 16 * (lane >> 4);

    float m0 = -INFINITY, m1 = -INFINITY, l0 = 0.f, l1 = 0.f;
    float oacc[8][4];
    #pragma unroll
    for (int j = 0; j < 8; j++)
        #pragma unroll
        for (int e = 0; e < 4; e++) oacc[j][e] = 0.f;

    const __half* Kg = QKV + DMODEL;       // K offset within fused row
    const __half* Vg = QKV + 2 * DMODEL;

    for (int kt = 0; kt < 32; kt++) {
        const size_t kvrow0 = (size_t)b * SEQ + kt * 64;

        // ---- Load K,V tiles via cp.async (fp16, 16B chunks) ----
        #pragma unroll
        for (int it = 0; it < 2; it++) {
            int idx = tid + it * 256;
            int r = idx >> 3, c = idx & 7;
            cp_async16(smc + r * KV_PITCH + c * 16,
                       Kg + (kvrow0 + r) * NQKV + hoff + c * 8);
            cp_async16(smc + 64 * KV_PITCH + r * KV_PITCH + c * 16,
                       Vg + (kvrow0 + r) * NQKV + hoff + c * 8);
        }
        CP_COMMIT();
        if (tid < 64)
            maskf[tid] = (mask[(size_t)b * SEQ + kt * 64 + tid] == 0) ? -INFINITY : 0.f;
        CP_WAIT(0);
        __syncthreads();

        // ---- S = Q @ K^T ----
        float sacc[8][4];
        #pragma unroll
        for (int j = 0; j < 8; j++)
            #pragma unroll
            for (int e = 0; e < 4; e++) sacc[j][e] = 0.f;

        #pragma unroll
        for (int k16 = 0; k16 < 4; k16++) {
            #pragma unroll
            for (int njp = 0; njp < 4; njp++) {
                unsigned bf[4];
                ldsm_x4(bf, k_lane + (uint32_t)njp * 16 * KV_PITCH + 32u * k16);
                mma_f16(sacc[2 * njp],     qf[k16], &bf[0]);
                mma_f16(sacc[2 * njp + 1], qf[k16], &bf[2]);
            }
        }

        // ---- Mask ----
        #pragma unroll
        for (int nj = 0; nj < 8; nj++) {
            float mk0 = maskf[nj * 8 + 2 * t];
            float mk1 = maskf[nj * 8 + 2 * t + 1];
            sacc[nj][0] += mk0; sacc[nj][1] += mk1;
            sacc[nj][2] += mk0; sacc[nj][3] += mk1;
        }

        // ---- Online softmax ----
        {
            float mx0 = -INFINITY, mx1 = -INFINITY;
            #pragma unroll
            for (int nj = 0; nj < 8; nj++) {
                mx0 = fmaxf(mx0, fmaxf(sacc[nj][0], sacc[nj][1]));
                mx1 = fmaxf(mx1, fmaxf(sacc[nj][2], sacc[nj][3]));
            }
            mx0 = fmaxf(mx0, __shfl_xor_sync(0xffffffffu, mx0, 1));
            mx0 = fmaxf(mx0, __shfl_xor_sync(0xffffffffu, mx0, 2));
            mx1 = fmaxf(mx1, __shfl_xor_sync(0xffffffffu, mx1, 1));
            mx1 = fmaxf(mx1, __shfl_xor_sync(0xffffffffu, mx1, 2));
            float mn0 = fmaxf(m0, mx0), mn1 = fmaxf(m1, mx1);
            float corr0 = __expf(m0 - mn0), corr1 = __expf(m1 - mn1);

            float rs0 = 0.f, rs1 = 0.f;
            #pragma unroll
            for (int nj = 0; nj < 8; nj++) {
                sacc[nj][0] = __expf(sacc[nj][0] - mn0);
                sacc[nj][1] = __expf(sacc[nj][1] - mn0);
                sacc[nj][2] = __expf(sacc[nj][2] - mn1);
                sacc[nj][3] = __expf(sacc[nj][3] - mn1);
                rs0 += sacc[nj][0] + sacc[nj][1];
                rs1 += sacc[nj][2] + sacc[nj][3];
            }
            rs0 += __shfl_xor_sync(0xffffffffu, rs0, 1);
            rs0 += __shfl_xor_sync(0xffffffffu, rs0, 2);
            rs1 += __shfl_xor_sync(0xffffffffu, rs1, 1);
            rs1 += __shfl_xor_sync(0xffffffffu, rs1, 2);
            l0 = l0 * corr0 + rs0;  m0 = mn0;
            l1 = l1 * corr1 + rs1;  m1 = mn1;
            #pragma unroll
            for (int j = 0; j < 8; j++) {
                oacc[j][0] *= corr0; oacc[j][1] *= corr0;
                oacc[j][2] *= corr1; oacc[j][3] *= corr1;
            }
        }

        // ---- O += P @ V ----
        #pragma unroll
        for (int j = 0; j < 4; j++) {
            unsigned af[4];
            af[0] = packh2(sacc[2 * j][0],     sacc[2 * j][1]);
            af[1] = packh2(sacc[2 * j][2],     sacc[2 * j][3]);
            af[2] = packh2(sacc[2 * j + 1][0], sacc[2 * j + 1][1]);
            af[3] = packh2(sacc[2 * j + 1][2], sacc[2 * j + 1][3]);
            #pragma unroll
            for (int jjp = 0; jjp < 4; jjp++) {
                unsigned bf[4];
                ldsm_x4_t(bf, v_lane + (uint32_t)j * 16 * KV_PITCH + 32u * jjp);
                mma_f16(oacc[2 * jjp],     af, &bf[0]);
                mma_f16(oacc[2 * jjp + 1], af, &bf[2]);
            }
        }
        __syncthreads();   // tile consumed before next cp.async overwrite
    }

    // ---- Output fp16 ----
    {
        const float inv0 = 1.f / l0, inv1 = 1.f / l1;
        const size_t r0 = qrow0 + warp * 16 + g;
        #pragma unroll
        for (int jj = 0; jj < 8; jj++) {
            int col = jj * 8 + 2 * t;
            *(__half2*)(O + r0 * DMODEL + hoff + col) =
                __floats2half2_rn(oacc[jj][0] * inv0, oacc[jj][1] * inv0);
            *(__half2*)(O + (r0 + 8) * DMODEL + hoff + col) =
                __floats2half2_rn(oacc[jj][2] * inv1, oacc[jj][3] * inv1);
        }
    }
}

// ---------------------------------------------------------------------------
// out[row] = LayerNorm(a[row] + b[row]) * gamma + beta (+ optional fp16 copy)
// ---------------------------------------------------------------------------
__global__ __launch_bounds__(256) void add_ln_kernel(
    const float* __restrict__ a, const float* __restrict__ bsrc,
    const float* __restrict__ g, const float* __restrict__ be,
    float* __restrict__ out, __half* __restrict__ out_h)
{
    const int row = blockIdx.x;
    const int tid = threadIdx.x;
    const float* pa = a + (size_t)row * DMODEL;
    const float* pb = bsrc + (size_t)row * DMODEL;

    float v[4];
    float sum = 0.f, sq = 0.f;
    #pragma unroll
    for (int i = 0; i < 4; i++) {
        int c = tid + i * 256;
        float x = pa[c] + pb[c];
        v[i] = x;
        sum += x;
        sq += x * x;
    }
    #pragma unroll
    for (int o = 16; o > 0; o >>= 1) {
        sum += __shfl_xor_sync(0xffffffffu, sum, o);
        sq  += __shfl_xor_sync(0xffffffffu, sq,  o);
    }
    __shared__ float ssum[8], ssq[8];
    if ((tid & 31) == 0) { ssum[tid >> 5] = sum; ssq[tid >> 5] = sq; }
    __syncthreads();
    if (tid < 32) {
        float s2 = (tid < 8) ? ssum[tid] : 0.f;
        float q2 = (tid < 8) ? ssq[tid] : 0.f;
        #pragma unroll
        for (int o = 4; o > 0; o >>= 1) {
            s2 += __shfl_xor_sync(0xffffffffu, s2, o);
            q2 += __shfl_xor_sync(0xffffffffu, q2, o);
        }
        if (tid == 0) { ssum[0] = s2; ssq[0] = q2; }
    }
    __syncthreads();
    const float mu   = ssum[0] * (1.f / DMODEL);
    const float var  = ssq[0] * (1.f / DMODEL) - mu * mu;
    const float rstd = rsqrtf(var + 1e-5f);

    float* po = out + (size_t)row * DMODEL;
    __half* ph = out_h ? out_h + (size_t)row * DMODEL : nullptr;
    #pragma unroll
    for (int i = 0; i < 4; i++) {
        int c = tid + i * 256;
        float y = (v[i] - mu) * rstd * g[c] + be[c];
        po[c] = y;
        if (ph) ph[c] = __float2half(y);
    }
}

// ---------------------------------------------------------------------------
// Launch
// ---------------------------------------------------------------------------
extern "C" void kernel_launch(void* const* d_in, const int* in_sizes, int n_in,
                              void* d_out, int out_size)
{
    (void)in_sizes; (void)n_in; (void)out_size;
    const float* x    = (const float*)d_in[0];
    const int*   mask = (const int*)  d_in[1];
    const float* w_q  = (const float*)d_in[2];
    const float* b_q  = (const float*)d_in[3];
    const float* w_k  = (const float*)d_in[4];
    const float* b_k  = (const float*)d_in[5];
    const float* w_v  = (const float*)d_in[6];
    const float* b_v  = (const float*)d_in[7];
    const float* w_o  = (const float*)d_in[8];
    const float* b_o  = (const float*)d_in[9];
    const float* w1   = (const float*)d_in[10];
    const float* b1   = (const float*)d_in[11];
    const float* w2   = (const float*)d_in[12];
    const float* b2   = (const float*)d_in[13];
    const float* g1   = (const float*)d_in[14];
    const float* be1  = (const float*)d_in[15];
    const float* g2   = (const float*)d_in[16];
    const float* be2  = (const float*)d_in[17];

    float *t1, *h, *bqkv;
    __half *hh, *ctxh, *ffh, *xh, *qkvh, *wqkvh, *woh, *w1h, *w2h;
    cudaGetSymbolAddress((void**)&t1,    g_t1);
    cudaGetSymbolAddress((void**)&h,     g_h);
    cudaGetSymbolAddress((void**)&hh,    g_hh);
    cudaGetSymbolAddress((void**)&ctxh,  g_ctxh);
    cudaGetSymbolAddress((void**)&ffh,   g_ffh);
    cudaGetSymbolAddress((void**)&xh,    g_xh);
    cudaGetSymbolAddress((void**)&qkvh,  g_qkvh);
    cudaGetSymbolAddress((void**)&wqkvh, g_wqkvh);
    cudaGetSymbolAddress((void**)&woh,   g_woh);
    cudaGetSymbolAddress((void**)&w1h,   g_w1h);
    cudaGetSymbolAddress((void**)&w2h,   g_w2h);
    cudaGetSymbolAddress((void**)&bqkv,  g_bqkv);

    cudaFuncSetAttribute(gemm_f16, cudaFuncAttributeMaxDynamicSharedMemorySize,
                         GEMM_SMEM_BYTES);
    cudaFuncSetAttribute(attn5, cudaFuncAttributeMaxDynamicSharedMemorySize,
                         ATTN_SMEM_BYTES);

    // ---- prep ----
    {
        const int TB = 256;
        int n = MROWS * DMODEL / 4;
        f2h_kernel<<<(n + TB - 1) / TB, TB>>>(x, xh, n);
        dim3 tb(32, 8);
        // wqkvh: Q rows [0,1024), K rows [1024,2048), V rows [2048,3072)
        transpose_h_kernel<<<dim3(DMODEL / 32, DMODEL / 32), tb>>>(w_q, wqkvh, DMODEL, DMODEL);
        transpose_h_kernel<<<dim3(DMODEL / 32, DMODEL / 32), tb>>>(w_k, wqkvh + DMODEL * DMODEL, DMODEL, DMODEL);
        transpose_h_kernel<<<dim3(DMODEL / 32, DMODEL / 32), tb>>>(w_v, wqkvh + 2 * DMODEL * DMODEL, DMODEL, DMODEL);
        transpose_h_kernel<<<dim3(DMODEL / 32, DMODEL / 32), tb>>>(w_o, woh, DMODEL, DMODEL);
        transpose_h_kernel<<<dim3(DFF / 32, DMODEL / 32), tb>>>(w1, w1h, DMODEL, DFF);
        transpose_h_kernel<<<dim3(DMODEL / 32, DFF / 32), tb>>>(w2, w2h, DFF, DMODEL);
        concat3_kernel<<<(DMODEL + TB - 1) / TB, TB>>>(b_q, b_k, b_v, bqkv, DMODEL);
    }

    dim3 blk128(128);
    dim3 gQKV(NQKV / 128, MROWS / 128);      // (24, 64)
    dim3 gProj(DMODEL / 128, MROWS / 128);   // (8, 64)
    dim3 gFF1(DFF / 128, MROWS / 128);       // (32, 64)
    dim3 gAtt(SEQ / 128, NHEADS, BATCH);     // (16, 16, 4)

    // fused QKV projection -> fp16 [MROWS, 3072]
    gemm_f16<<<gQKV, blk128, GEMM_SMEM_BYTES>>>(MROWS, NQKV, DMODEL, xh, wqkvh, bqkv, nullptr, qkvh, 0);

    attn5<<<gAtt, 256, ATTN_SMEM_BYTES>>>(qkvh, mask, ctxh);

    gemm_f16<<<gProj, blk128, GEMM_SMEM_BYTES>>>(MROWS, DMODEL, DMODEL, ctxh, woh, b_o, t1, nullptr, 0);
    add_ln_kernel<<<MROWS, 256>>>(x, t1, g1, be1, h, hh);

    gemm_f16<<<gFF1, blk128, GEMM_SMEM_BYTES>>>(MROWS, DFF, DMODEL, hh, w1h, b1, nullptr, ffh, 1);
    gemm_f16<<<gProj, blk128, GEMM_SMEM_BYTES>>>(MROWS, DMODEL, DFF, ffh, w2h, b2, t1, nullptr, 0);
    add_ln_kernel<<<MROWS, 256>>>(h, t1, g2, be2, (float*)d_out, nullptr);
}

// round 17
// speedup vs baseline: 3.2381x; 1.0179x over previous
#include <cuda_runtime.h>
#include <cuda_fp16.h>
#include <math.h>
#include <stdint.h>

// ---------------------------------------------------------------------------
// Problem constants
// ---------------------------------------------------------------------------
#define BATCH 4
#define SEQ   2048
#define DMODEL 1024
#define NHEADS 16
#define DK    64
#define DFF   4096
#define MROWS (BATCH * SEQ)   // 8192
#define NQKV  (3 * DMODEL)    // 3072

// ---------------------------------------------------------------------------
// Scratch (no cudaMalloc allowed)
// ---------------------------------------------------------------------------
__device__ float  g_t1 [MROWS * DMODEL];
__device__ float  g_h  [MROWS * DMODEL];
__device__ __half g_hh [MROWS * DMODEL];
__device__ __half g_ctxh[MROWS * DMODEL];
__device__ __half g_ffh[MROWS * DFF];
__device__ __half g_xh [MROWS * DMODEL];
__device__ __half g_qkvh[MROWS * NQKV];       // fused QKV output
__device__ __half g_wqkvh[NQKV * DMODEL];     // [3072,1024] transposed fp16
__device__ __half g_woh[DMODEL * DMODEL];
__device__ __half g_w1h[DFF * DMODEL];
__device__ __half g_w2h[DMODEL * DFF];
__device__ float  g_bqkv[NQKV];

// ---------------------------------------------------------------------------
// Helpers
// ---------------------------------------------------------------------------
__device__ __forceinline__ void mma_f16(float* c, const unsigned* a, const unsigned* b) {
    asm volatile(
        "mma.sync.aligned.m16n8k16.row.col.f32.f16.f16.f32 "
        "{%0,%1,%2,%3}, {%4,%5,%6,%7}, {%8,%9}, {%0,%1,%2,%3};"
        : "+f"(c[0]), "+f"(c[1]), "+f"(c[2]), "+f"(c[3])
        : "r"(a[0]), "r"(a[1]), "r"(a[2]), "r"(a[3]), "r"(b[0]), "r"(b[1]));
}

__device__ __forceinline__ void ldsm_x4(unsigned* r, uint32_t addr) {
    asm volatile("ldmatrix.sync.aligned.m8n8.x4.shared.b16 {%0,%1,%2,%3}, [%4];"
                 : "=r"(r[0]), "=r"(r[1]), "=r"(r[2]), "=r"(r[3]) : "r"(addr));
}
__device__ __forceinline__ void ldsm_x4_t(unsigned* r, uint32_t addr) {
    asm volatile("ldmatrix.sync.aligned.m8n8.x4.trans.shared.b16 {%0,%1,%2,%3}, [%4];"
                 : "=r"(r[0]), "=r"(r[1]), "=r"(r[2]), "=r"(r[3]) : "r"(addr));
}

__device__ __forceinline__ unsigned packh2(float a, float b) {
    __half2 h = __floats2half2_rn(a, b);
    return *reinterpret_cast<unsigned*>(&h);
}

__device__ __forceinline__ void cp_async16(void* smem_dst, const void* gmem_src) {
    unsigned saddr = (unsigned)__cvta_generic_to_shared(smem_dst);
    asm volatile("cp.async.cg.shared.global [%0], [%1], 16;"
                 :: "r"(saddr), "l"(gmem_src));
}
#define CP_COMMIT() asm volatile("cp.async.commit_group;")
#define CP_WAIT(n)  asm volatile("cp.async.wait_group %0;" :: "n"(n))

__device__ __forceinline__ uint32_t smem_u32(const void* p) {
    uint32_t a;
    asm("{ .reg .u64 t; cvta.to.shared.u64 t, %1; cvt.u32.u64 %0, t; }"
        : "=r"(a) : "l"(p));
    return a;
}

// ---------------------------------------------------------------------------
// Prep kernels
// ---------------------------------------------------------------------------
__global__ __launch_bounds__(256) void f2h_kernel(
    const float* __restrict__ src, __half* __restrict__ dst, int n4)
{
    int i = blockIdx.x * 256 + threadIdx.x;
    if (i < n4) {
        float4 v = ((const float4*)src)[i];
        ((__half2*)dst)[i * 2 + 0] = __floats2half2_rn(v.x, v.y);
        ((__half2*)dst)[i * 2 + 1] = __floats2half2_rn(v.z, v.w);
    }
}

__global__ __launch_bounds__(256) void transpose_h_kernel(
    const float* __restrict__ src, __half* __restrict__ dst, int R, int C)
{
    __shared__ float tile[32][33];
    const int c0 = blockIdx.x * 32, r0 = blockIdx.y * 32;
    const int tx = threadIdx.x, ty = threadIdx.y;
    #pragma unroll
    for (int i = 0; i < 32; i += 8)
        tile[ty + i][tx] = src[(size_t)(r0 + ty + i) * C + c0 + tx];
    __syncthreads();
    #pragma unroll
    for (int i = 0; i < 32; i += 8)
        dst[(size_t)(c0 + ty + i) * R + r0 + tx] = __float2half(tile[tx][ty + i]);
}

__global__ __launch_bounds__(256) void concat3_kernel(
    const float* __restrict__ a, const float* __restrict__ b,
    const float* __restrict__ c, float* __restrict__ dst, int n)
{
    int i = blockIdx.x * 256 + threadIdx.x;
    if (i < n) {
        dst[i] = a[i];
        dst[n + i] = b[i];
        dst[2 * n + i] = c[i];
    }
}

// ---------------------------------------------------------------------------
// FP16 tensor-core GEMM (mma.sync m16n8k16), 3-stage cp.async, ldmatrix frags.
// C[M,N] = A[M,K] @ Bt[N,K]^T + bias   (A, Bt fp16 K-major; acc fp32)
// BM=BN=128, BK=64, 128 threads = 4 warps (2x2), warp tile 64x64.
// ---------------------------------------------------------------------------
#define H_PITCH 144                              // bytes per 64-half row
#define H_TILE_BYTES (128 * H_PITCH)             // 18432
#define H_STAGE_BYTES (2 * H_TILE_BYTES)         // 36864
#define GEMM_SMEM_BYTES (3 * H_STAGE_BYTES)      // 110592

__global__ __launch_bounds__(128, 2) void gemm_f16(
    int M, int N, int K,
    const __half* __restrict__ A, const __half* __restrict__ Bt,
    const float* __restrict__ bias,
    float* __restrict__ C, __half* __restrict__ Ch, int relu)
{
    extern __shared__ char smc_g[];
    const uint32_t smem_base = smem_u32(smc_g);

    const int tid  = threadIdx.x;
    const int lane = tid & 31;
    const int warp = tid >> 5;
    const int wm = (warp >> 1) * 64;
    const int wn = (warp & 1) * 64;
    const int g = lane >> 2;
    const int t = lane & 3;
    const int cRow = blockIdx.y, cCol = blockIdx.x;

    const __half* Ag = A  + (size_t)(cRow * 128) * K;
    const __half* Bg = Bt + (size_t)(cCol * 128) * K;

    const int l7 = lane & 7, lm = lane >> 3;
    const uint32_t a_off = (uint32_t)(wm + 8 * (lm & 1) + l7) * H_PITCH + (lm >> 1) * 16;
    const uint32_t b_off = (uint32_t)(wn + 8 * (lm >> 1) + l7) * H_PITCH + (lm & 1) * 16;

    float acc[4][8][4];
    #pragma unroll
    for (int i = 0; i < 4; i++)
        #pragma unroll
        for (int j = 0; j < 8; j++)
            #pragma unroll
            for (int e = 0; e < 4; e++) acc[i][j][e] = 0.f;

    const int NT = K >> 6;

    auto load_stage = [&](int s, int k0) {
        char* ab = smc_g + s * H_STAGE_BYTES;
        char* bb = ab + H_TILE_BYTES;
        #pragma unroll
        for (int i = 0; i < 8; i++) {
            int idx = tid + i * 128;
            int row = idx >> 3, cc = idx & 7;
            cp_async16(ab + row * H_PITCH + cc * 16,
                       Ag + (size_t)row * K + k0 + cc * 8);
        }
        #pragma unroll
        for (int i = 0; i < 8; i++) {
            int idx = tid + i * 128;
            int row = idx >> 3, cc = idx & 7;
            cp_async16(bb + row * H_PITCH + cc * 16,
                       Bg + (size_t)row * K + k0 + cc * 8);
        }
        CP_COMMIT();
    };

    load_stage(0, 0);
    load_stage(1, 64);

    int buf = 0;
    for (int it = 0; it < NT; it++) {
        if (it < NT - 1) { CP_WAIT(1); } else { CP_WAIT(0); }
        __syncthreads();

        if (it + 2 < NT) {
            int wbuf = buf + 2; if (wbuf >= 3) wbuf -= 3;
            load_stage(wbuf, (it + 2) << 6);
        }

        const uint32_t abase = smem_base + buf * H_STAGE_BYTES;
        const uint32_t bbase = abase + H_TILE_BYTES;

        #pragma unroll
        for (int k16 = 0; k16 < 4; k16++) {
            unsigned af[4][4], bf[8][2];
            #pragma unroll
            for (int tm = 0; tm < 4; tm++)
                ldsm_x4(af[tm], abase + a_off + (uint32_t)tm * 16 * H_PITCH + k16 * 32);
            #pragma unroll
            for (int tnp = 0; tnp < 4; tnp++) {
                unsigned bq[4];
                ldsm_x4(bq, bbase + b_off + (uint32_t)tnp * 16 * H_PITCH + k16 * 32);
                bf[2 * tnp][0] = bq[0]; bf[2 * tnp][1] = bq[1];
                bf[2 * tnp + 1][0] = bq[2]; bf[2 * tnp + 1][1] = bq[3];
            }
            #pragma unroll
            for (int tm = 0; tm < 4; tm++)
                #pragma unroll
                for (int tn = 0; tn < 8; tn++)
                    mma_f16(acc[tm][tn], af[tm], bf[tn]);
        }

        if (++buf == 3) buf = 0;
    }

    #pragma unroll
    for (int tm = 0; tm < 4; tm++) {
        #pragma unroll
        for (int tn = 0; tn < 8; tn++) {
            int row = cRow * 128 + wm + tm * 16 + g;
            int col = cCol * 128 + wn + tn * 8 + 2 * t;
            float2 bb = *(const float2*)(bias + col);
            float2 v0 = make_float2(acc[tm][tn][0] + bb.x, acc[tm][tn][1] + bb.y);
            float2 v1 = make_float2(acc[tm][tn][2] + bb.x, acc[tm][tn][3] + bb.y);
            if (relu) {
                v0.x = fmaxf(v0.x, 0.f); v0.y = fmaxf(v0.y, 0.f);
                v1.x = fmaxf(v1.x, 0.f); v1.y = fmaxf(v1.y, 0.f);
            }
            if (C) {
                *(float2*)(C + (size_t)row * N + col) = v0;
                *(float2*)(C + (size_t)(row + 8) * N + col) = v1;
            }
            if (Ch) {
                *(__half2*)(Ch + (size_t)row * N + col) = __floats2half2_rn(v0.x, v0.y);
                *(__half2*)(Ch + (size_t)(row + 8) * N + col) = __floats2half2_rn(v1.x, v1.y);
            }
        }
    }
}

// ---------------------------------------------------------------------------
// Flash attention (fp16 m16n8k16), double-buffered K/V cp.async pipeline.
// Input = fused QKV fp16 [MROWS, 3072] (Q +0, K +1024, V +2048 per row).
// Per iteration: wait(tile kt) -> sync -> prefetch kt+1 -> compute kt.
// ---------------------------------------------------------------------------
#define KV_PITCH 144
#define KV_BUF_BYTES (2 * 64 * KV_PITCH)                 // K+V per buffer: 18432
#define ATTN_SMEM_BYTES (2 * KV_BUF_BYTES + 512)         // 37376

__global__ __launch_bounds__(256, 2) void attn5(
    const __half* __restrict__ QKV, const int* __restrict__ mask,
    __half* __restrict__ O)
{
    extern __shared__ char smc[];
    float* maskf = (float*)(smc + 2 * KV_BUF_BYTES);     // [2][64]

    const int qt = blockIdx.x, h = blockIdx.y, b = blockIdx.z;
    const int tid  = threadIdx.x;
    const int lane = tid & 31;
    const int warp = tid >> 5;
    const int g = lane >> 2;
    const int t = lane & 3;
    const int l7 = lane & 7, lm = lane >> 3;
    const size_t hoff = (size_t)h * DK;
    const size_t qrow0 = (size_t)b * SEQ + qt * 128;

    const uint32_t smem_base = smem_u32(smc);

    // ---- Stage Q fp16 (scaled 0.125) into buffer area; extract frags ----
    {
        const __half2 s8 = __float2half2_rn(0.125f);
        #pragma unroll
        for (int it = 0; it < 4; it++) {
            int idx = tid + it * 256;
            int r = idx >> 3;
            int c8 = (idx & 7) * 8;
            uint4 u = *(const uint4*)(QKV + (qrow0 + r) * NQKV + hoff + c8);
            __half2* hp = (__half2*)&u;
            hp[0] = __hmul2(hp[0], s8);
            hp[1] = __hmul2(hp[1], s8);
            hp[2] = __hmul2(hp[2], s8);
            hp[3] = __hmul2(hp[3], s8);
            *(uint4*)(smc + r * KV_PITCH + c8 * 2) = u;
        }
    }
    __syncthreads();

    unsigned qf[4][4];
    {
        const uint32_t q_off = (uint32_t)(warp * 16 + 8 * (lm & 1) + l7) * KV_PITCH
                             + (lm >> 1) * 16;
        #pragma unroll
        for (int kk = 0; kk < 4; kk++)
            ldsm_x4(qf[kk], smem_base + q_off + kk * 32);
    }
    __syncthreads();   // Q staging dead; buffers free

    // lane offsets (within a buffer) for K (plain) and V (trans) ldmatrix
    const uint32_t k_off = (uint32_t)(8 * (lm >> 1) + l7) * KV_PITCH + (lm & 1) * 16;
    const uint32_t v_off = 64 * KV_PITCH
                         + (uint32_t)(8 * ((lane >> 3) & 1) + l7) * KV_PITCH
                         + 16 * (lane >> 4);

    const __half* Kg = QKV + DMODEL;
    const __half* Vg = QKV + 2 * DMODEL;

    auto load_kv = [&](int s, int kt) {
        const size_t kvrow0 = (size_t)b * SEQ + kt * 64;
        char* kb = smc + s * KV_BUF_BYTES;
        char* vb = kb + 64 * KV_PITCH;
        #pragma unroll
        for (int it = 0; it < 2; it++) {
            int idx = tid + it * 256;
            int r = idx >> 3, c = idx & 7;
            cp_async16(kb + r * KV_PITCH + c * 16,
                       Kg + (kvrow0 + r) * NQKV + hoff + c * 8);
            cp_async16(vb + r * KV_PITCH + c * 16,
                       Vg + (kvrow0 + r) * NQKV + hoff + c * 8);
        }
        CP_COMMIT();
        if (tid < 64)
            maskf[s * 64 + tid] =
                (mask[(size_t)b * SEQ + kt * 64 + tid] == 0) ? -INFINITY : 0.f;
    };

    float m0 = -INFINITY, m1 = -INFINITY, l0 = 0.f, l1 = 0.f;
    float oacc[8][4];
    #pragma unroll
    for (int j = 0; j < 8; j++)
        #pragma unroll
        for (int e = 0; e < 4; e++) oacc[j][e] = 0.f;

    load_kv(0, 0);   // prologue

    for (int kt = 0; kt < 32; kt++) {
        const int s = kt & 1;
        if (kt + 1 < 32) { CP_WAIT(1); } else { CP_WAIT(0); }
        __syncthreads();   // tile kt visible; everyone left buffer s^1

        if (kt + 1 < 32) load_kv(s ^ 1, kt + 1);   // overlaps compute below

        const uint32_t bufb = smem_base + s * KV_BUF_BYTES;
        const float* mf = maskf + s * 64;

        // ---- S = Q @ K^T ----
        float sacc[8][4];
        #pragma unroll
        for (int j = 0; j < 8; j++)
            #pragma unroll
            for (int e = 0; e < 4; e++) sacc[j][e] = 0.f;

        #pragma unroll
        for (int k16 = 0; k16 < 4; k16++) {
            #pragma unroll
            for (int njp = 0; njp < 4; njp++) {
                unsigned bf[4];
                ldsm_x4(bf, bufb + k_off + (uint32_t)njp * 16 * KV_PITCH + 32u * k16);
                mma_f16(sacc[2 * njp],     qf[k16], &bf[0]);
                mma_f16(sacc[2 * njp + 1], qf[k16], &bf[2]);
            }
        }

        // ---- Mask ----
        #pragma unroll
        for (int nj = 0; nj < 8; nj++) {
            float mk0 = mf[nj * 8 + 2 * t];
            float mk1 = mf[nj * 8 + 2 * t + 1];
            sacc[nj][0] += mk0; sacc[nj][1] += mk1;
            sacc[nj][2] += mk0; sacc[nj][3] += mk1;
        }

        // ---- Online softmax ----
        {
            float mx0 = -INFINITY, mx1 = -INFINITY;
            #pragma unroll
            for (int nj = 0; nj < 8; nj++) {
                mx0 = fmaxf(mx0, fmaxf(sacc[nj][0], sacc[nj][1]));
                mx1 = fmaxf(mx1, fmaxf(sacc[nj][2], sacc[nj][3]));
            }
            mx0 = fmaxf(mx0, __shfl_xor_sync(0xffffffffu, mx0, 1));
            mx0 = fmaxf(mx0, __shfl_xor_sync(0xffffffffu, mx0, 2));
            mx1 = fmaxf(mx1, __shfl_xor_sync(0xffffffffu, mx1, 1));
            mx1 = fmaxf(mx1, __shfl_xor_sync(0xffffffffu, mx1, 2));
            float mn0 = fmaxf(m0, mx0), mn1 = fmaxf(m1, mx1);
            float corr0 = __expf(m0 - mn0), corr1 = __expf(m1 - mn1);

            float rs0 = 0.f, rs1 = 0.f;
            #pragma unroll
            for (int nj = 0; nj < 8; nj++) {
                sacc[nj][0] = __expf(sacc[nj][0] - mn0);
                sacc[nj][1] = __expf(sacc[nj][1] - mn0);
                sacc[nj][2] = __expf(sacc[nj][2] - mn1);
                sacc[nj][3] = __expf(sacc[nj][3] - mn1);
                rs0 += sacc[nj][0] + sacc[nj][1];
                rs1 += sacc[nj][2] + sacc[nj][3];
            }
            rs0 += __shfl_xor_sync(0xffffffffu, rs0, 1);
            rs0 += __shfl_xor_sync(0xffffffffu, rs0, 2);
            rs1 += __shfl_xor_sync(0xffffffffu, rs1, 1);
            rs1 += __shfl_xor_sync(0xffffffffu, rs1, 2);
            l0 = l0 * corr0 + rs0;  m0 = mn0;
            l1 = l1 * corr1 + rs1;  m1 = mn1;
            #pragma unroll
            for (int j = 0; j < 8; j++) {
                oacc[j][0] *= corr0; oacc[j][1] *= corr0;
                oacc[j][2] *= corr1; oacc[j][3] *= corr1;
            }
        }

        // ---- O += P @ V ----
        #pragma unroll
        for (int j = 0; j < 4; j++) {
            unsigned af[4];
            af[0] = packh2(sacc[2 * j][0],     sacc[2 * j][1]);
            af[1] = packh2(sacc[2 * j][2],     sacc[2 * j][3]);
            af[2] = packh2(sacc[2 * j + 1][0], sacc[2 * j + 1][1]);
            af[3] = packh2(sacc[2 * j + 1][2], sacc[2 * j + 1][3]);
            #pragma unroll
            for (int jjp = 0; jjp < 4; jjp++) {
                unsigned bf[4];
                ldsm_x4_t(bf, bufb + v_off + (uint32_t)j * 16 * KV_PITCH + 32u * jjp);
                mma_f16(oacc[2 * jjp],     af, &bf[0]);
                mma_f16(oacc[2 * jjp + 1], af, &bf[2]);
            }
        }
        // no trailing barrier: next iteration's top sync provides WAR protection
    }

    // ---- Output fp16 ----
    {
        const float inv0 = 1.f / l0, inv1 = 1.f / l1;
        const size_t r0 = qrow0 + warp * 16 + g;
        #pragma unroll
        for (int jj = 0; jj < 8; jj++) {
            int col = jj * 8 + 2 * t;
            *(__half2*)(O + r0 * DMODEL + hoff + col) =
                __floats2half2_rn(oacc[jj][0] * inv0, oacc[jj][1] * inv0);
            *(__half2*)(O + (r0 + 8) * DMODEL + hoff + col) =
                __floats2half2_rn(oacc[jj][2] * inv1, oacc[jj][3] * inv1);
        }
    }
}

// ---------------------------------------------------------------------------
// out[row] = LayerNorm(a[row] + b[row]) * gamma + beta (+ optional fp16 copy)
// ---------------------------------------------------------------------------
__global__ __launch_bounds__(256) void add_ln_kernel(
    const float* __restrict__ a, const float* __restrict__ bsrc,
    const float* __restrict__ g, const float* __restrict__ be,
    float* __restrict__ out, __half* __restrict__ out_h)
{
    const int row = blockIdx.x;
    const int tid = threadIdx.x;
    const float* pa = a + (size_t)row * DMODEL;
    const float* pb = bsrc + (size_t)row * DMODEL;

    float v[4];
    float sum = 0.f, sq = 0.f;
    #pragma unroll
    for (int i = 0; i < 4; i++) {
        int c = tid + i * 256;
        float x = pa[c] + pb[c];
        v[i] = x;
        sum += x;
        sq += x * x;
    }
    #pragma unroll
    for (int o = 16; o > 0; o >>= 1) {
        sum += __shfl_xor_sync(0xffffffffu, sum, o);
        sq  += __shfl_xor_sync(0xffffffffu, sq,  o);
    }
    __shared__ float ssum[8], ssq[8];
    if ((tid & 31) == 0) { ssum[tid >> 5] = sum; ssq[tid >> 5] = sq; }
    __syncthreads();
    if (tid < 32) {
        float s2 = (tid < 8) ? ssum[tid] : 0.f;
        float q2 = (tid < 8) ? ssq[tid] : 0.f;
        #pragma unroll
        for (int o = 4; o > 0; o >>= 1) {
            s2 += __shfl_xor_sync(0xffffffffu, s2, o);
            q2 += __shfl_xor_sync(0xffffffffu, q2, o);
        }
        if (tid == 0) { ssum[0] = s2; ssq[0] = q2; }
    }
    __syncthreads();
    const float mu   = ssum[0] * (1.f / DMODEL);
    const float var  = ssq[0] * (1.f / DMODEL) - mu * mu;
    const float rstd = rsqrtf(var + 1e-5f);

    float* po = out + (size_t)row * DMODEL;
    __half* ph = out_h ? out_h + (size_t)row * DMODEL : nullptr;
    #pragma unroll
    for (int i = 0; i < 4; i++) {
        int c = tid + i * 256;
        float y = (v[i] - mu) * rstd * g[c] + be[c];
        po[c] = y;
        if (ph) ph[c] = __float2half(y);
    }
}

// ---------------------------------------------------------------------------
// Launch
// ---------------------------------------------------------------------------
extern "C" void kernel_launch(void* const* d_in, const int* in_sizes, int n_in,
                              void* d_out, int out_size)
{
    (void)in_sizes; (void)n_in; (void)out_size;
    const float* x    = (const float*)d_in[0];
    const int*   mask = (const int*)  d_in[1];
    const float* w_q  = (const float*)d_in[2];
    const float* b_q  = (const float*)d_in[3];
    const float* w_k  = (const float*)d_in[4];
    const float* b_k  = (const float*)d_in[5];
    const float* w_v  = (const float*)d_in[6];
    const float* b_v  = (const float*)d_in[7];
    const float* w_o  = (const float*)d_in[8];
    const float* b_o  = (const float*)d_in[9];
    const float* w1   = (const float*)d_in[10];
    const float* b1   = (const float*)d_in[11];
    const float* w2   = (const float*)d_in[12];
    const float* b2   = (const float*)d_in[13];
    const float* g1   = (const float*)d_in[14];
    const float* be1  = (const float*)d_in[15];
    const float* g2   = (const float*)d_in[16];
    const float* be2  = (const float*)d_in[17];

    float *t1, *h, *bqkv;
    __half *hh, *ctxh, *ffh, *xh, *qkvh, *wqkvh, *woh, *w1h, *w2h;
    cudaGetSymbolAddress((void**)&t1,    g_t1);
    cudaGetSymbolAddress((void**)&h,     g_h);
    cudaGetSymbolAddress((void**)&hh,    g_hh);
    cudaGetSymbolAddress((void**)&ctxh,  g_ctxh);
    cudaGetSymbolAddress((void**)&ffh,   g_ffh);
    cudaGetSymbolAddress((void**)&xh,    g_xh);
    cudaGetSymbolAddress((void**)&qkvh,  g_qkvh);
    cudaGetSymbolAddress((void**)&wqkvh, g_wqkvh);
    cudaGetSymbolAddress((void**)&woh,   g_woh);
    cudaGetSymbolAddress((void**)&w1h,   g_w1h);
    cudaGetSymbolAddress((void**)&w2h,   g_w2h);
    cudaGetSymbolAddress((void**)&bqkv,  g_bqkv);

    cudaFuncSetAttribute(gemm_f16, cudaFuncAttributeMaxDynamicSharedMemorySize,
                         GEMM_SMEM_BYTES);
    cudaFuncSetAttribute(attn5, cudaFuncAttributeMaxDynamicSharedMemorySize,
                         ATTN_SMEM_BYTES);

    // ---- prep ----
    {
        const int TB = 256;
        int n = MROWS * DMODEL / 4;
        f2h_kernel<<<(n + TB - 1) / TB, TB>>>(x, xh, n);
        dim3 tb(32, 8);
        transpose_h_kernel<<<dim3(DMODEL / 32, DMODEL / 32), tb>>>(w_q, wqkvh, DMODEL, DMODEL);
        transpose_h_kernel<<<dim3(DMODEL / 32, DMODEL / 32), tb>>>(w_k, wqkvh + DMODEL * DMODEL, DMODEL, DMODEL);
        transpose_h_kernel<<<dim3(DMODEL / 32, DMODEL / 32), tb>>>(w_v, wqkvh + 2 * DMODEL * DMODEL, DMODEL, DMODEL);
        transpose_h_kernel<<<dim3(DMODEL / 32, DMODEL / 32), tb>>>(w_o, woh, DMODEL, DMODEL);
        transpose_h_kernel<<<dim3(DFF / 32, DMODEL / 32), tb>>>(w1, w1h, DMODEL, DFF);
        transpose_h_kernel<<<dim3(DMODEL / 32, DFF / 32), tb>>>(w2, w2h, DFF, DMODEL);
        concat3_kernel<<<(DMODEL + TB - 1) / TB, TB>>>(b_q, b_k, b_v, bqkv, DMODEL);
    }

    dim3 blk128(128);
    dim3 gQKV(NQKV / 128, MROWS / 128);      // (24, 64)
    dim3 gProj(DMODEL / 128, MROWS / 128);   // (8, 64)
    dim3 gFF1(DFF / 128, MROWS / 128);       // (32, 64)
    dim3 gAtt(SEQ / 128, NHEADS, BATCH);     // (16, 16, 4)

    gemm_f16<<<gQKV, blk128, GEMM_SMEM_BYTES>>>(MROWS, NQKV, DMODEL, xh, wqkvh, bqkv, nullptr, qkvh, 0);

    attn5<<<gAtt, 256, ATTN_SMEM_BYTES>>>(qkvh, mask, ctxh);

    gemm_f16<<<gProj, blk128, GEMM_SMEM_BYTES>>>(MROWS, DMODEL, DMODEL, ctxh, woh, b_o, t1, nullptr, 0);
    add_ln_kernel<<<MROWS, 256>>>(x, t1, g1, be1, h, hh);

    gemm_f16<<<gFF1, blk128, GEMM_SMEM_BYTES>>>(MROWS, DFF, DMODEL, hh, w1h, b1, nullptr, ffh, 1);
    gemm_f16<<<gProj, blk128, GEMM_SMEM_BYTES>>>(MROWS, DMODEL, DFF, ffh, w2h, b2, t1, nullptr, 0);
    add_ln_kernel<<<MROWS, 256>>>(h, t1, g2, be2, (float*)d_out, nullptr);
}